// round 1
// baseline (speedup 1.0000x reference)
#include <cuda_runtime.h>
#include <math.h>

// ---------------- problem constants ----------------
#define Bn 4
#define Tn 512
#define Vn 576
#define Ln 256
#define Hn 1024
#define NHn 16
#define HDn 64
#define In 4096
#define En 8
#define KTXT 80
#define KIMG 90

// ---------------- device scratch (no allocations allowed) ----------------
__device__ float g_ln_buf[Bn*Tn*Hn];
__device__ float g_qkv  [Bn*Tn*3*Hn];
__device__ float g_attn [Bn*Tn*Hn];
__device__ float g_q1   [Bn*Tn*Hn];
__device__ float g_q2   [Bn*Tn*Hn];
__device__ float g_qc   [Bn*Tn*Hn];
__device__ float g_kv   [Bn*Vn*2*Hn];
__device__ float g_scores[Bn*NHn*Tn*Vn];        // covers self (T*T) and cross (T*V)
__device__ float g_probs_txt[Bn*Tn*En];
__device__ float g_probs_img[Bn*Vn*En];
__device__ float g_ctx_img[Bn*Hn];
__device__ float g_ctx_txt[Bn*Hn];
__device__ float g_cp_img[Bn*En];
__device__ float g_cp_txt[Bn*En];
__device__ int   g_sel_txt[Bn*En*KTXT];
__device__ int   g_sel_img[Bn*En*KIMG];
__device__ int   g_pos_txt[Bn*En*Tn];
__device__ int   g_pos_img[Bn*En*Vn];
__device__ float g_hbuf [Bn*En*KIMG*In];
__device__ float g_down [Bn*En*KIMG*Hn];

// ---------------- helpers ----------------
__device__ __forceinline__ float gelu_tanh(float x){
    float x3 = x*x*x;
    return 0.5f*x*(1.0f+tanhf(0.7978845608028654f*(x+0.044715f*x3)));
}

// ---------------- generic 64x64 tiled GEMM: C = alpha*A*B(^T) [+bias] [gelu] [+res]
// A: [M,K] row-major (optionally row-gathered), B: [N,K] (TRANSB) or [K,N]
// batch = gridDim.z; z -> (b = z/nh, h = z%nh); per-(b,h) pointer offsets.
template<bool TRANSB, bool BIAS, bool RES, bool GELU, bool GATHER>
__global__ void __launch_bounds__(256)
gemm64(const float* __restrict__ A, const float* __restrict__ Bm,
       const float* __restrict__ bias, const float* __restrict__ res,
       float* __restrict__ C,
       int M, int N, int K, int lda, int ldb, int ldc,
       long long aOffB, long long aOffH, long long bOffB, long long bOffH,
       long long cOffB, long long cOffH, long long biasOffH,
       int nh, float alpha,
       const int* __restrict__ gidx, int gStride, int rowsPerB)
{
    __shared__ float As[16][65];
    __shared__ float Bs[16][65];
    int z = blockIdx.z;
    int b = z / nh, h = z - b*nh;
    const float* Ab = GATHER ? A : (A + (long long)b*aOffB + (long long)h*aOffH);
    const float* Bb = Bm + (long long)b*bOffB + (long long)h*bOffH;
    float* Cb = C + (long long)b*cOffB + (long long)h*cOffH;
    const float* biasb = BIAS ? (bias + (long long)h*biasOffH) : nullptr;
    const float* resb  = RES  ? (res  + (long long)b*cOffB + (long long)h*cOffH) : nullptr;

    int row0 = blockIdx.y*64, col0 = blockIdx.x*64;
    int tx = threadIdx.x, ty = threadIdx.y;
    int tid = ty*16 + tx;

    float acc[4][4] = {};

    for (int k0 = 0; k0 < K; k0 += 16) {
        // load A tile (64 rows x 16 k)
        #pragma unroll
        for (int i = 0; i < 4; i++) {
            int l = tid + i*256;
            int m = l >> 4, kk = l & 15;
            int grow = row0 + m;
            int kidx = k0 + kk;
            float v = 0.f;
            if (grow < M && kidx < K) {
                if (GATHER) {
                    long long arow = (long long)b*rowsPerB + gidx[(long long)z*gStride + grow];
                    v = A[arow*lda + kidx];
                } else {
                    v = Ab[(long long)grow*lda + kidx];
                }
            }
            As[kk][m] = v;
        }
        // load B tile (64 cols x 16 k)
        if (TRANSB) {
            #pragma unroll
            for (int i = 0; i < 4; i++) {
                int l = tid + i*256;
                int n = l >> 4, kk = l & 15;
                int gcol = col0 + n, kidx = k0 + kk;
                float v = 0.f;
                if (gcol < N && kidx < K) v = Bb[(long long)gcol*ldb + kidx];
                Bs[kk][n] = v;
            }
        } else {
            #pragma unroll
            for (int i = 0; i < 4; i++) {
                int l = tid + i*256;
                int kk = l >> 6, n = l & 63;
                int gcol = col0 + n, kidx = k0 + kk;
                float v = 0.f;
                if (gcol < N && kidx < K) v = Bb[(long long)kidx*ldb + gcol];
                Bs[kk][n] = v;
            }
        }
        __syncthreads();
        #pragma unroll
        for (int kk = 0; kk < 16; kk++) {
            float a0 = As[kk][ty], a1 = As[kk][ty+16], a2 = As[kk][ty+32], a3 = As[kk][ty+48];
            float b0 = Bs[kk][tx], b1 = Bs[kk][tx+16], b2 = Bs[kk][tx+32], b3 = Bs[kk][tx+48];
            acc[0][0] += a0*b0; acc[0][1] += a0*b1; acc[0][2] += a0*b2; acc[0][3] += a0*b3;
            acc[1][0] += a1*b0; acc[1][1] += a1*b1; acc[1][2] += a1*b2; acc[1][3] += a1*b3;
            acc[2][0] += a2*b0; acc[2][1] += a2*b1; acc[2][2] += a2*b2; acc[2][3] += a2*b3;
            acc[3][0] += a3*b0; acc[3][1] += a3*b1; acc[3][2] += a3*b2; acc[3][3] += a3*b3;
        }
        __syncthreads();
    }
    #pragma unroll
    for (int i = 0; i < 4; i++) {
        int row = row0 + ty + 16*i;
        if (row >= M) continue;
        #pragma unroll
        for (int j = 0; j < 4; j++) {
            int col = col0 + tx + 16*j;
            if (col >= N) continue;
            float v = acc[i][j]*alpha;
            if (BIAS) v += biasb[col];
            if (GELU) v = gelu_tanh(v);
            if (RES)  v += resb[(long long)row*ldc + col];
            Cb[(long long)row*ldc + col] = v;
        }
    }
}

// ---------------- LayerNorm (rows of H=1024), 256 threads ----------------
__global__ void ln_kernel(const float* __restrict__ x, const float* __restrict__ g,
                          const float* __restrict__ bta, float* __restrict__ y)
{
    long long row = blockIdx.x;
    int tid = threadIdx.x;
    const float4* xr = (const float4*)(x + row*Hn);
    float4 xv = xr[tid];
    float s = xv.x+xv.y+xv.z+xv.w;
    float q = xv.x*xv.x+xv.y*xv.y+xv.z*xv.z+xv.w*xv.w;
    for (int o=16;o;o>>=1){ s += __shfl_down_sync(0xffffffffu,s,o); q += __shfl_down_sync(0xffffffffu,q,o); }
    __shared__ float ss[8], qq[8];
    __shared__ float mv[2];
    int lane = tid&31, wd = tid>>5;
    if (lane==0){ ss[wd]=s; qq[wd]=q; }
    __syncthreads();
    if (tid==0){
        float a=0,c=0;
        #pragma unroll
        for(int i=0;i<8;i++){a+=ss[i]; c+=qq[i];}
        float mean = a*(1.f/Hn);
        float var  = c*(1.f/Hn) - mean*mean;
        mv[0]=mean; mv[1]=rsqrtf(var+1e-5f);
    }
    __syncthreads();
    float mean=mv[0], inv=mv[1];
    float4 gv = ((const float4*)g)[tid];
    float4 bv = ((const float4*)bta)[tid];
    float4 o;
    o.x=(xv.x-mean)*inv*gv.x+bv.x;
    o.y=(xv.y-mean)*inv*gv.y+bv.y;
    o.z=(xv.z-mean)*inv*gv.z+bv.z;
    o.w=(xv.w-mean)*inv*gv.w+bv.w;
    ((float4*)(y + row*Hn))[tid] = o;
}

// ---------------- row softmax (in-place), 128 threads ----------------
__global__ void softmax_kernel(float* __restrict__ p, int cols)
{
    long long row = blockIdx.x;
    float* r = p + row*cols;
    int tid = threadIdx.x;
    float mx = -1e30f;
    for (int i=tid;i<cols;i+=128) mx = fmaxf(mx, r[i]);
    for (int o=16;o;o>>=1) mx = fmaxf(mx, __shfl_xor_sync(0xffffffffu,mx,o));
    __shared__ float sm[4], sq[4];
    if ((tid&31)==0) sm[tid>>5]=mx;
    __syncthreads();
    mx = fmaxf(fmaxf(sm[0],sm[1]),fmaxf(sm[2],sm[3]));
    float sum = 0.f;
    for (int i=tid;i<cols;i+=128){ float e=__expf(r[i]-mx); r[i]=e; sum+=e; }
    for (int o=16;o;o>>=1) sum += __shfl_xor_sync(0xffffffffu,sum,o);
    if ((tid&31)==0) sq[tid>>5]=sum;
    __syncthreads();
    sum = sq[0]+sq[1]+sq[2]+sq[3];
    float inv = 1.f/sum;
    for (int i=tid;i<cols;i+=128) r[i]*=inv;
}

// ---------------- mean over rows dim: out[b,h] = mean_v x[b,v,h] ----------------
__global__ void mean_rows(const float* __restrict__ x, float* __restrict__ out, int rows)
{
    int b = blockIdx.x, tid = threadIdx.x;
    const float4* xb = (const float4*)(x + (long long)b*rows*Hn);
    float4 acc = {0,0,0,0};
    for (int v=0; v<rows; v++){
        float4 t = xb[v*(Hn/4) + tid];
        acc.x+=t.x; acc.y+=t.y; acc.z+=t.z; acc.w+=t.w;
    }
    float inv = 1.f/rows;
    float4 o = {acc.x*inv, acc.y*inv, acc.z*inv, acc.w*inv};
    ((float4*)(out + (long long)b*Hn))[tid] = o;
}

// ---------------- ctxpart[b,e] = ctx[b] . W[e, H:2H] + bias[e] ----------------
__global__ void ctxpart_kernel(const float* __restrict__ ctx, const float* __restrict__ W,
                               const float* __restrict__ bias, float* __restrict__ out)
{
    int z = blockIdx.x; int b = z >> 3, e = z & 7;
    int tid = threadIdx.x;
    const float4* c4 = (const float4*)(ctx + (long long)b*Hn);
    const float4* w4 = (const float4*)(W + (long long)e*2*Hn + Hn);
    float4 c = c4[tid], w = w4[tid];
    float s = c.x*w.x + c.y*w.y + c.z*w.z + c.w*w.w;
    for (int o=16;o;o>>=1) s += __shfl_down_sync(0xffffffffu,s,o);
    __shared__ float sh[8];
    if ((tid&31)==0) sh[tid>>5]=s;
    __syncthreads();
    if (tid==0){ float t=0; for(int i=0;i<8;i++) t+=sh[i]; out[z] = t + bias[e]; }
}

// ---------------- gating: probs[token,e] = softmax_e( x . W[e,:H] + cp[b,e] ) ----------------
__global__ void gate_kernel(const float* __restrict__ x, const float* __restrict__ W,
                            const float* __restrict__ cp, float* __restrict__ probs, int S)
{
    int token = blockIdx.x; int b = token / S;
    int tid = threadIdx.x;
    __shared__ float xs[Hn];
    ((float4*)xs)[tid] = ((const float4*)(x + (long long)token*Hn))[tid];
    __syncthreads();
    int w = tid >> 5, lane = tid & 31;
    const float* We = W + (long long)w*2*Hn;
    float s = 0.f;
    for (int hh = lane; hh < Hn; hh += 32) s += xs[hh]*We[hh];
    for (int o=16;o;o>>=1) s += __shfl_down_sync(0xffffffffu,s,o);
    __shared__ float lg[En];
    if (lane==0) lg[w] = s + cp[b*En + w];
    __syncthreads();
    if (tid==0){
        float mx = lg[0];
        #pragma unroll
        for (int e=1;e<En;e++) mx = fmaxf(mx, lg[e]);
        float ev[En]; float sum = 0.f;
        #pragma unroll
        for (int e=0;e<En;e++){ ev[e]=expf(lg[e]-mx); sum+=ev[e]; }
        float inv = 1.f/sum;
        #pragma unroll
        for (int e=0;e<En;e++) probs[(long long)token*En+e]=ev[e]*inv;
    }
}

// ---------------- per-(b,e) top-k via bitonic sort (value desc, index asc ties) ----------------
__global__ void topk_kernel(const float* __restrict__ probs, int S, int k, int kmax,
                            int* __restrict__ sel, int* __restrict__ pos)
{
    int z = blockIdx.x; int b = z / En, e = z - b*En;
    int tid = threadIdx.x; // 256
    __shared__ float sv[1024];
    __shared__ int   si[1024];
    for (int i=tid;i<1024;i+=256){
        sv[i] = (i < S) ? probs[((long long)b*S + i)*En + e] : -1e30f;
        si[i] = i;
    }
    __syncthreads();
    for (int ksz=2; ksz<=1024; ksz<<=1){
        for (int j=ksz>>1; j>0; j>>=1){
            for (int i=tid; i<1024; i+=256){
                int ixj = i ^ j;
                if (ixj > i){
                    float v1=sv[i], v2=sv[ixj];
                    int i1=si[i], i2=si[ixj];
                    bool before = (v1 > v2) || (v1 == v2 && i1 < i2);
                    bool asc = ((i & ksz) == 0);
                    if (asc ? !before : before){
                        sv[i]=v2; sv[ixj]=v1; si[i]=i2; si[ixj]=i1;
                    }
                }
            }
            __syncthreads();
        }
    }
    for (int i=tid;i<S;i+=256) pos[(long long)z*S + i] = 0;
    __syncthreads();
    for (int j=tid;j<k;j+=256){
        int s = si[j];
        sel[(long long)z*kmax + j] = s;
        pos[(long long)z*S + s] = j + 1;
    }
}

// ---------------- combine: out = resid + (sum over chosen experts of down rows)/count ----------------
__global__ void combine_kernel(const float* __restrict__ down, const int* __restrict__ pos,
                               const float* __restrict__ resid, float* __restrict__ out,
                               int S, int kmax)
{
    int bs = blockIdx.x; int b = bs / S; int s = bs - b*S;
    int tid = threadIdx.x;
    int p[En]; int cnt = 0;
    #pragma unroll
    for (int e=0;e<En;e++){ p[e] = pos[((long long)(b*En+e))*S + s]; cnt += (p[e]>0); }
    float inv = 1.f / (cnt > 0 ? cnt : 1);
    float4 acc = {0,0,0,0};
    #pragma unroll
    for (int e=0;e<En;e++){
        if (p[e] > 0){
            const float4* dr = (const float4*)(down + ((long long)(b*En+e)*kmax + (p[e]-1))*Hn);
            float4 d = dr[tid];
            acc.x+=d.x; acc.y+=d.y; acc.z+=d.z; acc.w+=d.w;
        }
    }
    float4 r = ((const float4*)(resid + (long long)bs*Hn))[tid];
    float4 o = {r.x+acc.x*inv, r.y+acc.y*inv, r.z+acc.z*inv, r.w+acc.w*inv};
    ((float4*)(out + (long long)bs*Hn))[tid] = o;
}

// ---------------- host ----------------
extern "C" void kernel_launch(void* const* d_in, const int* in_sizes, int n_in,
                              void* d_out, int out_size)
{
    const float* query    = (const float*)d_in[0];
    const float* image    = (const float*)d_in[1];
    const float* textctx  = (const float*)d_in[2];
    const float* sa_w_in  = (const float*)d_in[3];
    const float* sa_b_in  = (const float*)d_in[4];
    const float* sa_w_out = (const float*)d_in[5];
    const float* sa_b_out = (const float*)d_in[6];
    const float* ca_w_in  = (const float*)d_in[7];
    const float* ca_b_in  = (const float*)d_in[8];
    const float* ca_w_out = (const float*)d_in[9];
    const float* ca_b_out = (const float*)d_in[10];
    const float* gate_img_w = (const float*)d_in[11];
    const float* gate_img_b = (const float*)d_in[12];
    const float* gate_txt_w = (const float*)d_in[13];
    const float* gate_txt_b = (const float*)d_in[14];
    const float* e_w1 = (const float*)d_in[15];
    const float* e_b1 = (const float*)d_in[16];
    const float* e_w2 = (const float*)d_in[17];
    const float* e_b2 = (const float*)d_in[18];
    const float* lnq_g = (const float*)d_in[19];
    const float* lnq_b = (const float*)d_in[20];
    const float* lnc_g = (const float*)d_in[21];
    const float* lnc_b = (const float*)d_in[22];
    const float* lnf_g = (const float*)d_in[23];
    const float* lnf_b = (const float*)d_in[24];

    float *pLn,*pQkv,*pAttn,*pQ1,*pQ2,*pQc,*pKv,*pSc,*pPt,*pPi,*pCtxI,*pCtxT,*pCpI,*pCpT,*pH,*pDown;
    int *pSelT,*pSelI,*pPosT,*pPosI;
    cudaGetSymbolAddress((void**)&pLn,  g_ln_buf);
    cudaGetSymbolAddress((void**)&pQkv, g_qkv);
    cudaGetSymbolAddress((void**)&pAttn,g_attn);
    cudaGetSymbolAddress((void**)&pQ1,  g_q1);
    cudaGetSymbolAddress((void**)&pQ2,  g_q2);
    cudaGetSymbolAddress((void**)&pQc,  g_qc);
    cudaGetSymbolAddress((void**)&pKv,  g_kv);
    cudaGetSymbolAddress((void**)&pSc,  g_scores);
    cudaGetSymbolAddress((void**)&pPt,  g_probs_txt);
    cudaGetSymbolAddress((void**)&pPi,  g_probs_img);
    cudaGetSymbolAddress((void**)&pCtxI,g_ctx_img);
    cudaGetSymbolAddress((void**)&pCtxT,g_ctx_txt);
    cudaGetSymbolAddress((void**)&pCpI, g_cp_img);
    cudaGetSymbolAddress((void**)&pCpT, g_cp_txt);
    cudaGetSymbolAddress((void**)&pH,   g_hbuf);
    cudaGetSymbolAddress((void**)&pDown,g_down);
    cudaGetSymbolAddress((void**)&pSelT,g_sel_txt);
    cudaGetSymbolAddress((void**)&pSelI,g_sel_img);
    cudaGetSymbolAddress((void**)&pPosT,g_pos_txt);
    cudaGetSymbolAddress((void**)&pPosI,g_pos_img);

    dim3 blk(16,16);
    const int BT = Bn*Tn, BV = Bn*Vn;
    float* outQ = (float*)d_out;
    float* outI = outQ + (long long)BT*Hn;

    // 1) self-attention
    ln_kernel<<<BT,256>>>(query, lnq_g, lnq_b, pLn);
    gemm64<true,true,false,false,false><<<dim3(48,32,1),blk>>>(pLn, sa_w_in, sa_b_in, nullptr, pQkv,
        BT, 3*Hn, Hn, Hn, Hn, 3*Hn, 0,0,0,0,0,0, 0, 1, 1.f, nullptr,0,0);
    gemm64<true,false,false,false,false><<<dim3(8,8,Bn*NHn),blk>>>(pQkv, pQkv+Hn, nullptr, nullptr, pSc,
        Tn, Tn, HDn, 3*Hn, 3*Hn, Tn,
        (long long)Tn*3*Hn, HDn, (long long)Tn*3*Hn, HDn,
        (long long)NHn*Tn*Tn, (long long)Tn*Tn, 0, NHn, 0.125f, nullptr,0,0);
    softmax_kernel<<<Bn*NHn*Tn,128>>>(pSc, Tn);
    gemm64<false,false,false,false,false><<<dim3(1,8,Bn*NHn),blk>>>(pSc, pQkv+2*Hn, nullptr, nullptr, pAttn,
        Tn, HDn, Tn, Tn, 3*Hn, Hn,
        (long long)NHn*Tn*Tn, (long long)Tn*Tn, (long long)Tn*3*Hn, HDn,
        (long long)Tn*Hn, HDn, 0, NHn, 1.f, nullptr,0,0);
    gemm64<true,true,true,false,false><<<dim3(16,32,1),blk>>>(pAttn, sa_w_out, sa_b_out, query, pQ1,
        BT, Hn, Hn, Hn, Hn, Hn, 0,0,0,0,0,0, 0, 1, 1.f, nullptr,0,0);

    // 2) cross-attention to image tokens
    ln_kernel<<<BT,256>>>(pQ1, lnc_g, lnc_b, pLn);
    gemm64<true,true,false,false,false><<<dim3(16,32,1),blk>>>(pLn, ca_w_in, ca_b_in, nullptr, pQc,
        BT, Hn, Hn, Hn, Hn, Hn, 0,0,0,0,0,0, 0, 1, 1.f, nullptr,0,0);
    gemm64<true,true,false,false,false><<<dim3(32,36,1),blk>>>(image, ca_w_in + (long long)Hn*Hn, ca_b_in + Hn, nullptr, pKv,
        BV, 2*Hn, Hn, Hn, Hn, 2*Hn, 0,0,0,0,0,0, 0, 1, 1.f, nullptr,0,0);
    gemm64<true,false,false,false,false><<<dim3(9,8,Bn*NHn),blk>>>(pQc, pKv, nullptr, nullptr, pSc,
        Tn, Vn, HDn, Hn, 2*Hn, Vn,
        (long long)Tn*Hn, HDn, (long long)Vn*2*Hn, HDn,
        (long long)NHn*Tn*Vn, (long long)Tn*Vn, 0, NHn, 0.125f, nullptr,0,0);
    softmax_kernel<<<Bn*NHn*Tn,128>>>(pSc, Vn);
    gemm64<false,false,false,false,false><<<dim3(1,8,Bn*NHn),blk>>>(pSc, pKv+Hn, nullptr, nullptr, pAttn,
        Tn, HDn, Vn, Vn, 2*Hn, Hn,
        (long long)NHn*Tn*Vn, (long long)Tn*Vn, (long long)Vn*2*Hn, HDn,
        (long long)Tn*Hn, HDn, 0, NHn, 1.f, nullptr,0,0);
    gemm64<true,true,true,false,false><<<dim3(16,32,1),blk>>>(pAttn, ca_w_out, ca_b_out, pQ1, pQ2,
        BT, Hn, Hn, Hn, Hn, Hn, 0,0,0,0,0,0, 0, 1, 1.f, nullptr,0,0);

    // 3) gating
    mean_rows<<<Bn,256>>>(image, pCtxI, Vn);
    mean_rows<<<Bn,256>>>(textctx, pCtxT, Ln);
    ctxpart_kernel<<<Bn*En,256>>>(pCtxT, gate_img_w, gate_img_b, pCpI);
    ctxpart_kernel<<<Bn*En,256>>>(pCtxI, gate_txt_w, gate_txt_b, pCpT);
    gate_kernel<<<BV,256>>>(image, gate_img_w, pCpI, pPi, Vn);
    gate_kernel<<<BT,256>>>(pQ2, gate_txt_w, pCpT, pPt, Tn);
    topk_kernel<<<Bn*En,256>>>(pPt, Tn, KTXT, KTXT, pSelT, pPosT);
    topk_kernel<<<Bn*En,256>>>(pPi, Vn, KIMG, KIMG, pSelI, pPosI);

    // 4) text MoE (on LN(q2)), residual q2 -> outQ
    ln_kernel<<<BT,256>>>(pQ2, lnf_g, lnf_b, pLn);
    gemm64<true,true,false,true,true><<<dim3(64,2,Bn*En),blk>>>(pLn, e_w1, e_b1, nullptr, pH,
        KTXT, In, Hn, Hn, Hn, In,
        0,0, 0, (long long)In*Hn,
        (long long)En*KTXT*In, (long long)KTXT*In, (long long)In, En, 1.f, pSelT, KTXT, Tn);
    gemm64<true,true,false,false,false><<<dim3(16,2,Bn*En),blk>>>(pH, e_w2, e_b2, nullptr, pDown,
        KTXT, Hn, In, In, In, Hn,
        (long long)En*KTXT*In, (long long)KTXT*In, 0, (long long)Hn*In,
        (long long)En*KTXT*Hn, (long long)KTXT*Hn, (long long)Hn, En, 1.f, nullptr,0,0);
    combine_kernel<<<BT,256>>>(pDown, pPosT, pQ2, outQ, Tn, KTXT);

    // 5) image MoE (on raw image tokens), residual image -> outI
    gemm64<true,true,false,true,true><<<dim3(64,2,Bn*En),blk>>>(image, e_w1, e_b1, nullptr, pH,
        KIMG, In, Hn, Hn, Hn, In,
        0,0, 0, (long long)In*Hn,
        (long long)En*KIMG*In, (long long)KIMG*In, (long long)In, En, 1.f, pSelI, KIMG, Vn);
    gemm64<true,true,false,false,false><<<dim3(16,2,Bn*En),blk>>>(pH, e_w2, e_b2, nullptr, pDown,
        KIMG, Hn, In, In, In, Hn,
        (long long)En*KIMG*In, (long long)KIMG*In, 0, (long long)Hn*In,
        (long long)En*KIMG*Hn, (long long)KIMG*Hn, (long long)Hn, En, 1.f, nullptr,0,0);
    combine_kernel<<<BV,256>>>(pDown, pPosI, image, outI, Vn, KIMG);
}

// round 5
// speedup vs baseline: 2.9439x; 2.9439x over previous
#include <cuda_runtime.h>
#include <cuda_bf16.h>
#include <cstdint>
#include <math.h>

// ---------------- problem constants ----------------
#define Bn 4
#define Tn 512
#define Vn 576
#define Ln 256
#define Hn 1024
#define NHn 16
#define HDn 64
#define In 4096
#define En 8
#define KTXT 80
#define KIMG 90

// ---------------- device scratch ----------------
__device__ float g_ln_buf[Bn*Tn*Hn];
__device__ float g_qkv  [Bn*Tn*3*Hn];
__device__ float g_attn [Bn*Tn*Hn];
__device__ float g_q1   [Bn*Tn*Hn];
__device__ float g_q2   [Bn*Tn*Hn];
__device__ float g_qc   [Bn*Tn*Hn];
__device__ float g_kv   [Bn*Vn*2*Hn];
__device__ float g_scores[Bn*NHn*Tn*Vn];
__device__ float g_probs_txt[Bn*Tn*En];
__device__ float g_probs_img[Bn*Vn*En];
__device__ float g_ctx_img[Bn*Hn];
__device__ float g_ctx_txt[Bn*Hn];
__device__ float g_cp_img[Bn*En];
__device__ float g_cp_txt[Bn*En];
__device__ int   g_sel_txt[Bn*En*KTXT];
__device__ int   g_sel_img[Bn*En*KIMG];
__device__ int   g_pos_txt[Bn*En*Tn];
__device__ int   g_pos_img[Bn*En*Vn];
__device__ float g_hbuf [Bn*En*KIMG*In];
__device__ float g_down [Bn*En*KIMG*Hn];

// ---------------- helpers ----------------
__device__ __forceinline__ uint32_t smem_u32(const void* p){
    uint32_t a;
    asm("{ .reg .u64 t; cvta.to.shared.u64 t, %1; cvt.u32.u64 %0, t; }" : "=r"(a) : "l"(p));
    return a;
}
__device__ __forceinline__ float gelu_tanh(float x){
    float x3 = x*x*x;
    return 0.5f*x*(1.0f+tanhf(0.7978845608028654f*(x+0.044715f*x3)));
}
__device__ __forceinline__ void ldm_x4(uint32_t& r0,uint32_t& r1,uint32_t& r2,uint32_t& r3, uint32_t addr){
    asm volatile("ldmatrix.sync.aligned.m8n8.x4.shared.b16 {%0,%1,%2,%3}, [%4];"
      : "=r"(r0),"=r"(r1),"=r"(r2),"=r"(r3) : "r"(addr));
}
__device__ __forceinline__ void ldm_x2(uint32_t& r0,uint32_t& r1, uint32_t addr){
    asm volatile("ldmatrix.sync.aligned.m8n8.x2.shared.b16 {%0,%1}, [%2];"
      : "=r"(r0),"=r"(r1) : "r"(addr));
}
__device__ __forceinline__ void mma_bf16(float* c, const uint32_t* a, const uint32_t* b){
    asm volatile("mma.sync.aligned.m16n8k16.row.col.f32.bf16.bf16.f32 "
      "{%0,%1,%2,%3}, {%4,%5,%6,%7}, {%8,%9}, {%0,%1,%2,%3};"
      : "+f"(c[0]),"+f"(c[1]),"+f"(c[2]),"+f"(c[3])
      : "r"(a[0]),"r"(a[1]),"r"(a[2]),"r"(a[3]), "r"(b[0]),"r"(b[1]));
}

// =========================================================================
// HMMA bf16x3 GEMM: C[M,N] = A[M,K] @ B[N,K]^T (+bias)(gelu)(+res)
// Tile 128x128x32, 256 threads (8 warps, 2x4), padded smem (stride 40 bf16).
// 3-pass split accumulation: Ahi*Bhi + Ahi*Blo + Alo*Bhi (fp32 acc).
// =========================================================================
#define LDS 40   // smem row stride in bf16 (80 bytes: 16B-aligned, conflict-free)

template<bool BIAS, bool RES, bool GELU, bool GATHER>
__global__ void __launch_bounds__(256, 2)
mma_gemm(const float* __restrict__ A, const float* __restrict__ Bm,
         const float* __restrict__ bias, const float* __restrict__ res,
         float* __restrict__ C,
         int M, int K, int lda, int ldb, int ldc,
         long long aOffB, long long aOffH, long long bOffB, long long bOffH,
         long long cOffB, long long cOffH, long long biasOffH,
         int nh, const int* __restrict__ gidx, int gStride, int rowsPerB)
{
    __shared__ __align__(16) __nv_bfloat16 sAhi[128*LDS];
    __shared__ __align__(16) __nv_bfloat16 sAlo[128*LDS];
    __shared__ __align__(16) __nv_bfloat16 sBhi[128*LDS];
    __shared__ __align__(16) __nv_bfloat16 sBlo[128*LDS];

    int tid = threadIdx.x;
    int wid = tid >> 5, lane = tid & 31;
    int wm = wid & 1, wn = wid >> 1;
    int z = blockIdx.z;
    int b = z / nh, h = z - b*nh;
    const float* Ab = GATHER ? A : (A + (long long)b*aOffB + (long long)h*aOffH);
    const float* Bb = Bm + (long long)b*bOffB + (long long)h*bOffH;
    float* Cb = C + (long long)b*cOffB + (long long)h*cOffH;
    const float* biasb = BIAS ? (bias + (long long)h*biasOffH) : nullptr;
    const float* resb  = RES  ? (res  + (long long)b*cOffB + (long long)h*cOffH) : nullptr;
    int row0 = blockIdx.y * 128, col0 = blockIdx.x * 128;

    uint32_t aHiB = smem_u32(sAhi), aLoB = smem_u32(sAlo);
    uint32_t bHiB = smem_u32(sBhi), bLoB = smem_u32(sBlo);

    float acc[4][4][4] = {};

    for (int k0 = 0; k0 < K; k0 += 32) {
        // ---- load + split A tile (128 x 32) ----
        #pragma unroll
        for (int i = 0; i < 4; i++) {
            int idx = tid + i*256;
            int r = idx >> 3, kb = (idx & 7) << 2;
            float4 v = make_float4(0.f,0.f,0.f,0.f);
            int grow = row0 + r;
            if (grow < M) {
                if (GATHER) {
                    long long arow = (long long)b*rowsPerB + gidx[(long long)z*gStride + grow];
                    v = *(const float4*)(A + arow*lda + k0 + kb);
                } else {
                    v = *(const float4*)(Ab + (long long)grow*lda + k0 + kb);
                }
            }
            __nv_bfloat162 h01 = __floats2bfloat162_rn(v.x, v.y);
            __nv_bfloat162 h23 = __floats2bfloat162_rn(v.z, v.w);
            __nv_bfloat162 l01 = __floats2bfloat162_rn(v.x - __bfloat162float(h01.x), v.y - __bfloat162float(h01.y));
            __nv_bfloat162 l23 = __floats2bfloat162_rn(v.z - __bfloat162float(h23.x), v.w - __bfloat162float(h23.y));
            uint2 hv, lv;
            hv.x = *(uint32_t*)&h01; hv.y = *(uint32_t*)&h23;
            lv.x = *(uint32_t*)&l01; lv.y = *(uint32_t*)&l23;
            *(uint2*)&sAhi[r*LDS + kb] = hv;
            *(uint2*)&sAlo[r*LDS + kb] = lv;
        }
        // ---- load + split B tile (128 x 32) ----
        #pragma unroll
        for (int i = 0; i < 4; i++) {
            int idx = tid + i*256;
            int r = idx >> 3, kb = (idx & 7) << 2;
            float4 v = *(const float4*)(Bb + (long long)(col0 + r)*ldb + k0 + kb);
            __nv_bfloat162 h01 = __floats2bfloat162_rn(v.x, v.y);
            __nv_bfloat162 h23 = __floats2bfloat162_rn(v.z, v.w);
            __nv_bfloat162 l01 = __floats2bfloat162_rn(v.x - __bfloat162float(h01.x), v.y - __bfloat162float(h01.y));
            __nv_bfloat162 l23 = __floats2bfloat162_rn(v.z - __bfloat162float(h23.x), v.w - __bfloat162float(h23.y));
            uint2 hv, lv;
            hv.x = *(uint32_t*)&h01; hv.y = *(uint32_t*)&h23;
            lv.x = *(uint32_t*)&l01; lv.y = *(uint32_t*)&l23;
            *(uint2*)&sBhi[r*LDS + kb] = hv;
            *(uint2*)&sBlo[r*LDS + kb] = lv;
        }
        __syncthreads();
        // ---- mma over 2 k16 halves ----
        #pragma unroll
        for (int kh = 0; kh < 2; kh++) {
            uint32_t bh[4][2], bl[4][2];
            #pragma unroll
            for (int ni = 0; ni < 4; ni++) {
                uint32_t off = ((uint32_t)((wn*32 + ni*8 + (lane & 7))*LDS + kh*16 + ((lane >> 3) & 1)*8)) * 2u;
                ldm_x2(bh[ni][0], bh[ni][1], bHiB + off);
                ldm_x2(bl[ni][0], bl[ni][1], bLoB + off);
            }
            #pragma unroll
            for (int mi = 0; mi < 4; mi++) {
                uint32_t off = ((uint32_t)((wm*64 + mi*16 + (lane & 15))*LDS + kh*16 + (lane >> 4)*8)) * 2u;
                uint32_t ah[4], al[4];
                ldm_x4(ah[0], ah[1], ah[2], ah[3], aHiB + off);
                ldm_x4(al[0], al[1], al[2], al[3], aLoB + off);
                #pragma unroll
                for (int ni = 0; ni < 4; ni++) {
                    mma_bf16(acc[mi][ni], ah, bh[ni]);
                    mma_bf16(acc[mi][ni], ah, bl[ni]);
                    mma_bf16(acc[mi][ni], al, bh[ni]);
                }
            }
        }
        __syncthreads();
    }

    // ---- epilogue ----
    #pragma unroll
    for (int mi = 0; mi < 4; mi++) {
        #pragma unroll
        for (int ni = 0; ni < 4; ni++) {
            int rg = row0 + wm*64 + mi*16 + (lane >> 2);
            int cg = col0 + wn*32 + ni*8 + (lane & 3)*2;
            #pragma unroll
            for (int half = 0; half < 2; half++) {
                int row = rg + half*8;
                if (row < M) {
                    float v0 = acc[mi][ni][half*2+0];
                    float v1 = acc[mi][ni][half*2+1];
                    if (BIAS) { v0 += biasb[cg]; v1 += biasb[cg+1]; }
                    if (GELU) { v0 = gelu_tanh(v0); v1 = gelu_tanh(v1); }
                    if (RES)  { v0 += resb[(long long)row*ldc + cg]; v1 += resb[(long long)row*ldc + cg + 1]; }
                    float2 o = make_float2(v0, v1);
                    *(float2*)&Cb[(long long)row*ldc + cg] = o;
                }
            }
        }
    }
}

// ---------------- fp32 gemm64 (attention core only) ----------------
template<bool TRANSB>
__global__ void __launch_bounds__(256)
gemm64(const float* __restrict__ A, const float* __restrict__ Bm,
       float* __restrict__ C,
       int M, int N, int K, int lda, int ldb, int ldc,
       long long aOffB, long long aOffH, long long bOffB, long long bOffH,
       long long cOffB, long long cOffH,
       int nh, float alpha)
{
    __shared__ float As[16][65];
    __shared__ float Bs[16][65];
    int z = blockIdx.z;
    int b = z / nh, h = z - b*nh;
    const float* Ab = A + (long long)b*aOffB + (long long)h*aOffH;
    const float* Bb = Bm + (long long)b*bOffB + (long long)h*bOffH;
    float* Cb = C + (long long)b*cOffB + (long long)h*cOffH;

    int row0 = blockIdx.y*64, col0 = blockIdx.x*64;
    int tx = threadIdx.x, ty = threadIdx.y;
    int tid = ty*16 + tx;
    float acc[4][4] = {};

    for (int k0 = 0; k0 < K; k0 += 16) {
        #pragma unroll
        for (int i = 0; i < 4; i++) {
            int l = tid + i*256;
            int m = l >> 4, kk = l & 15;
            int grow = row0 + m, kidx = k0 + kk;
            float v = 0.f;
            if (grow < M && kidx < K) v = Ab[(long long)grow*lda + kidx];
            As[kk][m] = v;
        }
        if (TRANSB) {
            #pragma unroll
            for (int i = 0; i < 4; i++) {
                int l = tid + i*256;
                int n = l >> 4, kk = l & 15;
                int gcol = col0 + n, kidx = k0 + kk;
                float v = 0.f;
                if (gcol < N && kidx < K) v = Bb[(long long)gcol*ldb + kidx];
                Bs[kk][n] = v;
            }
        } else {
            #pragma unroll
            for (int i = 0; i < 4; i++) {
                int l = tid + i*256;
                int kk = l >> 6, n = l & 63;
                int gcol = col0 + n, kidx = k0 + kk;
                float v = 0.f;
                if (gcol < N && kidx < K) v = Bb[(long long)kidx*ldb + gcol];
                Bs[kk][n] = v;
            }
        }
        __syncthreads();
        #pragma unroll
        for (int kk = 0; kk < 16; kk++) {
            float a0 = As[kk][ty], a1 = As[kk][ty+16], a2 = As[kk][ty+32], a3 = As[kk][ty+48];
            float b0 = Bs[kk][tx], b1 = Bs[kk][tx+16], b2 = Bs[kk][tx+32], b3 = Bs[kk][tx+48];
            acc[0][0] += a0*b0; acc[0][1] += a0*b1; acc[0][2] += a0*b2; acc[0][3] += a0*b3;
            acc[1][0] += a1*b0; acc[1][1] += a1*b1; acc[1][2] += a1*b2; acc[1][3] += a1*b3;
            acc[2][0] += a2*b0; acc[2][1] += a2*b1; acc[2][2] += a2*b2; acc[2][3] += a2*b3;
            acc[3][0] += a3*b0; acc[3][1] += a3*b1; acc[3][2] += a3*b2; acc[3][3] += a3*b3;
        }
        __syncthreads();
    }
    #pragma unroll
    for (int i = 0; i < 4; i++) {
        int row = row0 + ty + 16*i;
        if (row >= M) continue;
        #pragma unroll
        for (int j = 0; j < 4; j++) {
            int col = col0 + tx + 16*j;
            if (col >= N) continue;
            Cb[(long long)row*ldc + col] = acc[i][j]*alpha;
        }
    }
}

// ---------------- LayerNorm ----------------
__global__ void ln_kernel(const float* __restrict__ x, const float* __restrict__ g,
                          const float* __restrict__ bta, float* __restrict__ y)
{
    long long row = blockIdx.x;
    int tid = threadIdx.x;
    const float4* xr = (const float4*)(x + row*Hn);
    float4 xv = xr[tid];
    float s = xv.x+xv.y+xv.z+xv.w;
    float q = xv.x*xv.x+xv.y*xv.y+xv.z*xv.z+xv.w*xv.w;
    for (int o=16;o;o>>=1){ s += __shfl_down_sync(0xffffffffu,s,o); q += __shfl_down_sync(0xffffffffu,q,o); }
    __shared__ float ss[8], qq[8];
    __shared__ float mv[2];
    int lane = tid&31, wd = tid>>5;
    if (lane==0){ ss[wd]=s; qq[wd]=q; }
    __syncthreads();
    if (tid==0){
        float a=0,c=0;
        #pragma unroll
        for(int i=0;i<8;i++){a+=ss[i]; c+=qq[i];}
        float mean = a*(1.f/Hn);
        float var  = c*(1.f/Hn) - mean*mean;
        mv[0]=mean; mv[1]=rsqrtf(var+1e-5f);
    }
    __syncthreads();
    float mean=mv[0], inv=mv[1];
    float4 gv = ((const float4*)g)[tid];
    float4 bv = ((const float4*)bta)[tid];
    float4 o;
    o.x=(xv.x-mean)*inv*gv.x+bv.x;
    o.y=(xv.y-mean)*inv*gv.y+bv.y;
    o.z=(xv.z-mean)*inv*gv.z+bv.z;
    o.w=(xv.w-mean)*inv*gv.w+bv.w;
    ((float4*)(y + row*Hn))[tid] = o;
}

// ---------------- row softmax ----------------
__global__ void softmax_kernel(float* __restrict__ p, int cols)
{
    long long row = blockIdx.x;
    float* r = p + row*cols;
    int tid = threadIdx.x;
    float mx = -1e30f;
    for (int i=tid;i<cols;i+=128) mx = fmaxf(mx, r[i]);
    for (int o=16;o;o>>=1) mx = fmaxf(mx, __shfl_xor_sync(0xffffffffu,mx,o));
    __shared__ float sm[4], sq[4];
    if ((tid&31)==0) sm[tid>>5]=mx;
    __syncthreads();
    mx = fmaxf(fmaxf(sm[0],sm[1]),fmaxf(sm[2],sm[3]));
    float sum = 0.f;
    for (int i=tid;i<cols;i+=128){ float e=__expf(r[i]-mx); r[i]=e; sum+=e; }
    for (int o=16;o;o>>=1) sum += __shfl_xor_sync(0xffffffffu,sum,o);
    if ((tid&31)==0) sq[tid>>5]=sum;
    __syncthreads();
    sum = sq[0]+sq[1]+sq[2]+sq[3];
    float inv = 1.f/sum;
    for (int i=tid;i<cols;i+=128) r[i]*=inv;
}

// ---------------- mean over rows ----------------
__global__ void mean_rows(const float* __restrict__ x, float* __restrict__ out, int rows)
{
    int b = blockIdx.x, tid = threadIdx.x;
    const float4* xb = (const float4*)(x + (long long)b*rows*Hn);
    float4 acc = {0,0,0,0};
    for (int v=0; v<rows; v++){
        float4 t = xb[v*(Hn/4) + tid];
        acc.x+=t.x; acc.y+=t.y; acc.z+=t.z; acc.w+=t.w;
    }
    float inv = 1.f/rows;
    float4 o = {acc.x*inv, acc.y*inv, acc.z*inv, acc.w*inv};
    ((float4*)(out + (long long)b*Hn))[tid] = o;
}

// ---------------- ctxpart ----------------
__global__ void ctxpart_kernel(const float* __restrict__ ctx, const float* __restrict__ W,
                               const float* __restrict__ bias, float* __restrict__ out)
{
    int z = blockIdx.x; int b = z >> 3, e = z & 7;
    int tid = threadIdx.x;
    const float4* c4 = (const float4*)(ctx + (long long)b*Hn);
    const float4* w4 = (const float4*)(W + (long long)e*2*Hn + Hn);
    float4 c = c4[tid], w = w4[tid];
    float s = c.x*w.x + c.y*w.y + c.z*w.z + c.w*w.w;
    for (int o=16;o;o>>=1) s += __shfl_down_sync(0xffffffffu,s,o);
    __shared__ float sh[8];
    if ((tid&31)==0) sh[tid>>5]=s;
    __syncthreads();
    if (tid==0){ float t=0; for(int i=0;i<8;i++) t+=sh[i]; out[z] = t + bias[e]; }
}

// ---------------- gating ----------------
__global__ void gate_kernel(const float* __restrict__ x, const float* __restrict__ W,
                            const float* __restrict__ cp, float* __restrict__ probs, int S)
{
    int token = blockIdx.x; int b = token / S;
    int tid = threadIdx.x;
    __shared__ float xs[Hn];
    ((float4*)xs)[tid] = ((const float4*)(x + (long long)token*Hn))[tid];
    __syncthreads();
    int w = tid >> 5, lane = tid & 31;
    const float* We = W + (long long)w*2*Hn;
    float s = 0.f;
    for (int hh = lane; hh < Hn; hh += 32) s += xs[hh]*We[hh];
    for (int o=16;o;o>>=1) s += __shfl_down_sync(0xffffffffu,s,o);
    __shared__ float lg[En];
    if (lane==0) lg[w] = s + cp[b*En + w];
    __syncthreads();
    if (tid==0){
        float mx = lg[0];
        #pragma unroll
        for (int e=1;e<En;e++) mx = fmaxf(mx, lg[e]);
        float ev[En]; float sum = 0.f;
        #pragma unroll
        for (int e=0;e<En;e++){ ev[e]=expf(lg[e]-mx); sum+=ev[e]; }
        float inv = 1.f/sum;
        #pragma unroll
        for (int e=0;e<En;e++) probs[(long long)token*En+e]=ev[e]*inv;
    }
}

// ---------------- top-k (bitonic; value desc, index asc) ----------------
__global__ void topk_kernel(const float* __restrict__ probs, int S, int k, int kmax,
                            int* __restrict__ sel, int* __restrict__ pos)
{
    int z = blockIdx.x; int b = z / En, e = z - b*En;
    int tid = threadIdx.x;
    __shared__ float sv[1024];
    __shared__ int   si[1024];
    for (int i=tid;i<1024;i+=256){
        sv[i] = (i < S) ? probs[((long long)b*S + i)*En + e] : -1e30f;
        si[i] = i;
    }
    __syncthreads();
    for (int ksz=2; ksz<=1024; ksz<<=1){
        for (int j=ksz>>1; j>0; j>>=1){
            for (int i=tid; i<1024; i+=256){
                int ixj = i ^ j;
                if (ixj > i){
                    float v1=sv[i], v2=sv[ixj];
                    int i1=si[i], i2=si[ixj];
                    bool before = (v1 > v2) || (v1 == v2 && i1 < i2);
                    bool asc = ((i & ksz) == 0);
                    if (asc ? !before : before){
                        sv[i]=v2; sv[ixj]=v1; si[i]=i2; si[ixj]=i1;
                    }
                }
            }
            __syncthreads();
        }
    }
    for (int i=tid;i<S;i+=256) pos[(long long)z*S + i] = 0;
    __syncthreads();
    for (int j=tid;j<k;j+=256){
        int s = si[j];
        sel[(long long)z*kmax + j] = s;
        pos[(long long)z*S + s] = j + 1;
    }
}

// ---------------- combine ----------------
__global__ void combine_kernel(const float* __restrict__ down, const int* __restrict__ pos,
                               const float* __restrict__ resid, float* __restrict__ out,
                               int S, int kmax)
{
    int bs = blockIdx.x; int b = bs / S; int s = bs - b*S;
    int tid = threadIdx.x;
    int p[En]; int cnt = 0;
    #pragma unroll
    for (int e=0;e<En;e++){ p[e] = pos[((long long)(b*En+e))*S + s]; cnt += (p[e]>0); }
    float inv = 1.f / (cnt > 0 ? cnt : 1);
    float4 acc = {0,0,0,0};
    #pragma unroll
    for (int e=0;e<En;e++){
        if (p[e] > 0){
            const float4* dr = (const float4*)(down + ((long long)(b*En+e)*kmax + (p[e]-1))*Hn);
            float4 d = dr[tid];
            acc.x+=d.x; acc.y+=d.y; acc.z+=d.z; acc.w+=d.w;
        }
    }
    float4 r = ((const float4*)(resid + (long long)bs*Hn))[tid];
    float4 o = {r.x+acc.x*inv, r.y+acc.y*inv, r.z+acc.z*inv, r.w+acc.w*inv};
    ((float4*)(out + (long long)bs*Hn))[tid] = o;
}

// ---------------- host ----------------
extern "C" void kernel_launch(void* const* d_in, const int* in_sizes, int n_in,
                              void* d_out, int out_size)
{
    const float* query    = (const float*)d_in[0];
    const float* image    = (const float*)d_in[1];
    const float* textctx  = (const float*)d_in[2];
    const float* sa_w_in  = (const float*)d_in[3];
    const float* sa_b_in  = (const float*)d_in[4];
    const float* sa_w_out = (const float*)d_in[5];
    const float* sa_b_out = (const float*)d_in[6];
    const float* ca_w_in  = (const float*)d_in[7];
    const float* ca_b_in  = (const float*)d_in[8];
    const float* ca_w_out = (const float*)d_in[9];
    const float* ca_b_out = (const float*)d_in[10];
    const float* gate_img_w = (const float*)d_in[11];
    const float* gate_img_b = (const float*)d_in[12];
    const float* gate_txt_w = (const float*)d_in[13];
    const float* gate_txt_b = (const float*)d_in[14];
    const float* e_w1 = (const float*)d_in[15];
    const float* e_b1 = (const float*)d_in[16];
    const float* e_w2 = (const float*)d_in[17];
    const float* e_b2 = (const float*)d_in[18];
    const float* lnq_g = (const float*)d_in[19];
    const float* lnq_b = (const float*)d_in[20];
    const float* lnc_g = (const float*)d_in[21];
    const float* lnc_b = (const float*)d_in[22];
    const float* lnf_g = (const float*)d_in[23];
    const float* lnf_b = (const float*)d_in[24];

    float *pLn,*pQkv,*pAttn,*pQ1,*pQ2,*pQc,*pKv,*pSc,*pPt,*pPi,*pCtxI,*pCtxT,*pCpI,*pCpT,*pH,*pDown;
    int *pSelT,*pSelI,*pPosT,*pPosI;
    cudaGetSymbolAddress((void**)&pLn,  g_ln_buf);
    cudaGetSymbolAddress((void**)&pQkv, g_qkv);
    cudaGetSymbolAddress((void**)&pAttn,g_attn);
    cudaGetSymbolAddress((void**)&pQ1,  g_q1);
    cudaGetSymbolAddress((void**)&pQ2,  g_q2);
    cudaGetSymbolAddress((void**)&pQc,  g_qc);
    cudaGetSymbolAddress((void**)&pKv,  g_kv);
    cudaGetSymbolAddress((void**)&pSc,  g_scores);
    cudaGetSymbolAddress((void**)&pPt,  g_probs_txt);
    cudaGetSymbolAddress((void**)&pPi,  g_probs_img);
    cudaGetSymbolAddress((void**)&pCtxI,g_ctx_img);
    cudaGetSymbolAddress((void**)&pCtxT,g_ctx_txt);
    cudaGetSymbolAddress((void**)&pCpI, g_cp_img);
    cudaGetSymbolAddress((void**)&pCpT, g_cp_txt);
    cudaGetSymbolAddress((void**)&pH,   g_hbuf);
    cudaGetSymbolAddress((void**)&pDown,g_down);
    cudaGetSymbolAddress((void**)&pSelT,g_sel_txt);
    cudaGetSymbolAddress((void**)&pSelI,g_sel_img);
    cudaGetSymbolAddress((void**)&pPosT,g_pos_txt);
    cudaGetSymbolAddress((void**)&pPosI,g_pos_img);

    dim3 blk(16,16);
    const int BT = Bn*Tn, BV = Bn*Vn;
    float* outQ = (float*)d_out;
    float* outI = outQ + (long long)BT*Hn;

    // 1) self-attention
    ln_kernel<<<BT,256>>>(query, lnq_g, lnq_b, pLn);
    mma_gemm<true,false,false,false><<<dim3(24,16,1),256>>>(pLn, sa_w_in, sa_b_in, nullptr, pQkv,
        BT, Hn, Hn, Hn, 3*Hn, 0,0,0,0,0,0, 0, 1, nullptr,0,0);
    gemm64<true><<<dim3(8,8,Bn*NHn),blk>>>(pQkv, pQkv+Hn, pSc,
        Tn, Tn, HDn, 3*Hn, 3*Hn, Tn,
        (long long)Tn*3*Hn, HDn, (long long)Tn*3*Hn, HDn,
        (long long)NHn*Tn*Tn, (long long)Tn*Tn, NHn, 0.125f);
    softmax_kernel<<<Bn*NHn*Tn,128>>>(pSc, Tn);
    gemm64<false><<<dim3(1,8,Bn*NHn),blk>>>(pSc, pQkv+2*Hn, pAttn,
        Tn, HDn, Tn, Tn, 3*Hn, Hn,
        (long long)NHn*Tn*Tn, (long long)Tn*Tn, (long long)Tn*3*Hn, HDn,
        (long long)Tn*Hn, HDn, NHn, 1.f);
    mma_gemm<true,true,false,false><<<dim3(8,16,1),256>>>(pAttn, sa_w_out, sa_b_out, query, pQ1,
        BT, Hn, Hn, Hn, Hn, 0,0,0,0,0,0, 0, 1, nullptr,0,0);

    // 2) cross-attention
    ln_kernel<<<BT,256>>>(pQ1, lnc_g, lnc_b, pLn);
    mma_gemm<true,false,false,false><<<dim3(8,16,1),256>>>(pLn, ca_w_in, ca_b_in, nullptr, pQc,
        BT, Hn, Hn, Hn, Hn, 0,0,0,0,0,0, 0, 1, nullptr,0,0);
    mma_gemm<true,false,false,false><<<dim3(16,18,1),256>>>(image, ca_w_in + (long long)Hn*Hn, ca_b_in + Hn, nullptr, pKv,
        BV, Hn, Hn, Hn, 2*Hn, 0,0,0,0,0,0, 0, 1, nullptr,0,0);
    gemm64<true><<<dim3(9,8,Bn*NHn),blk>>>(pQc, pKv, pSc,
        Tn, Vn, HDn, Hn, 2*Hn, Vn,
        (long long)Tn*Hn, HDn, (long long)Vn*2*Hn, HDn,
        (long long)NHn*Tn*Vn, (long long)Tn*Vn, NHn, 0.125f);
    softmax_kernel<<<Bn*NHn*Tn,128>>>(pSc, Vn);
    gemm64<false><<<dim3(1,8,Bn*NHn),blk>>>(pSc, pKv+Hn, pAttn,
        Tn, HDn, Vn, Vn, 2*Hn, Hn,
        (long long)NHn*Tn*Vn, (long long)Tn*Vn, (long long)Vn*2*Hn, HDn,
        (long long)Tn*Hn, HDn, NHn, 1.f);
    mma_gemm<true,true,false,false><<<dim3(8,16,1),256>>>(pAttn, ca_w_out, ca_b_out, pQ1, pQ2,
        BT, Hn, Hn, Hn, Hn, 0,0,0,0,0,0, 0, 1, nullptr,0,0);

    // 3) gating
    mean_rows<<<Bn,256>>>(image, pCtxI, Vn);
    mean_rows<<<Bn,256>>>(textctx, pCtxT, Ln);
    ctxpart_kernel<<<Bn*En,256>>>(pCtxT, gate_img_w, gate_img_b, pCpI);
    ctxpart_kernel<<<Bn*En,256>>>(pCtxI, gate_txt_w, gate_txt_b, pCpT);
    gate_kernel<<<BV,256>>>(image, gate_img_w, pCpI, pPi, Vn);
    gate_kernel<<<BT,256>>>(pQ2, gate_txt_w, pCpT, pPt, Tn);
    topk_kernel<<<Bn*En,256>>>(pPt, Tn, KTXT, KTXT, pSelT, pPosT);
    topk_kernel<<<Bn*En,256>>>(pPi, Vn, KIMG, KIMG, pSelI, pPosI);

    // 4) text MoE
    ln_kernel<<<BT,256>>>(pQ2, lnf_g, lnf_b, pLn);
    mma_gemm<true,false,true,true><<<dim3(32,1,Bn*En),256>>>(pLn, e_w1, e_b1, nullptr, pH,
        KTXT, Hn, Hn, Hn, In,
        0,0, 0,(long long)In*Hn,
        (long long)En*KTXT*In, (long long)KTXT*In, (long long)In, En, pSelT, KTXT, Tn);
    mma_gemm<true,false,false,false><<<dim3(8,1,Bn*En),256>>>(pH, e_w2, e_b2, nullptr, pDown,
        KTXT, In, In, In, Hn,
        (long long)En*KTXT*In, (long long)KTXT*In, 0,(long long)Hn*In,
        (long long)En*KTXT*Hn, (long long)KTXT*Hn, (long long)Hn, En, nullptr,0,0);
    combine_kernel<<<BT,256>>>(pDown, pPosT, pQ2, outQ, Tn, KTXT);

    // 5) image MoE
    mma_gemm<true,false,true,true><<<dim3(32,1,Bn*En),256>>>(image, e_w1, e_b1, nullptr, pH,
        KIMG, Hn, Hn, Hn, In,
        0,0, 0,(long long)In*Hn,
        (long long)En*KIMG*In, (long long)KIMG*In, (long long)In, En, pSelI, KIMG, Vn);
    mma_gemm<true,false,false,false><<<dim3(8,1,Bn*En),256>>>(pH, e_w2, e_b2, nullptr, pDown,
        KIMG, In, In, In, Hn,
        (long long)En*KIMG*In, (long long)KIMG*In, 0,(long long)Hn*In,
        (long long)En*KIMG*Hn, (long long)KIMG*Hn, (long long)Hn, En, nullptr,0,0);
    combine_kernel<<<BV,256>>>(pDown, pPosI, image, outI, Vn, KIMG);
}

// round 6
// speedup vs baseline: 2.9809x; 1.0126x over previous
#include <cuda_runtime.h>
#include <cuda_bf16.h>
#include <cstdint>
#include <math.h>

// ---------------- problem constants ----------------
#define Bn 4
#define Tn 512
#define Vn 576
#define Ln 256
#define Hn 1024
#define NHn 16
#define HDn 64
#define In 4096
#define En 8
#define KTXT 80
#define KIMG 90

// ---------------- device scratch ----------------
__device__ float g_ln_buf[Bn*Tn*Hn];
__device__ float g_qkv  [Bn*Tn*3*Hn];
__device__ float g_attn [Bn*Tn*Hn];
__device__ float g_q1   [Bn*Tn*Hn];
__device__ float g_q2   [Bn*Tn*Hn];
__device__ float g_qc   [Bn*Tn*Hn];
__device__ float g_kv   [Bn*Vn*2*Hn];
__device__ float g_scores[Bn*NHn*Tn*Vn];
__device__ float g_probs_txt[Bn*Tn*En];
__device__ float g_probs_img[Bn*Vn*En];
__device__ float g_ctx_img[Bn*Hn];
__device__ float g_ctx_txt[Bn*Hn];
__device__ float g_cp_img[Bn*En];
__device__ float g_cp_txt[Bn*En];
__device__ int   g_sel_txt[Bn*En*KTXT];
__device__ int   g_sel_img[Bn*En*KIMG];
__device__ int   g_pos_txt[Bn*En*Tn];
__device__ int   g_pos_img[Bn*En*Vn];
__device__ float g_hbuf [Bn*En*KIMG*In];
__device__ float g_down [Bn*En*KIMG*Hn];

// ---------------- helpers ----------------
__device__ __forceinline__ uint32_t smem_u32(const void* p){
    uint32_t a;
    asm("{ .reg .u64 t; cvta.to.shared.u64 t, %1; cvt.u32.u64 %0, t; }" : "=r"(a) : "l"(p));
    return a;
}
__device__ __forceinline__ float gelu_tanh(float x){
    float x3 = x*x*x;
    return 0.5f*x*(1.0f+tanhf(0.7978845608028654f*(x+0.044715f*x3)));
}
__device__ __forceinline__ void ldm_x4(uint32_t& r0,uint32_t& r1,uint32_t& r2,uint32_t& r3, uint32_t addr){
    asm volatile("ldmatrix.sync.aligned.m8n8.x4.shared.b16 {%0,%1,%2,%3}, [%4];"
      : "=r"(r0),"=r"(r1),"=r"(r2),"=r"(r3) : "r"(addr));
}
__device__ __forceinline__ void ldm_x2(uint32_t& r0,uint32_t& r1, uint32_t addr){
    asm volatile("ldmatrix.sync.aligned.m8n8.x2.shared.b16 {%0,%1}, [%2];"
      : "=r"(r0),"=r"(r1) : "r"(addr));
}
__device__ __forceinline__ void mma_bf16(float* c, const uint32_t* a, const uint32_t* b){
    asm volatile("mma.sync.aligned.m16n8k16.row.col.f32.bf16.bf16.f32 "
      "{%0,%1,%2,%3}, {%4,%5,%6,%7}, {%8,%9}, {%0,%1,%2,%3};"
      : "+f"(c[0]),"+f"(c[1]),"+f"(c[2]),"+f"(c[3])
      : "r"(a[0]),"r"(a[1]),"r"(a[2]),"r"(a[3]), "r"(b[0]),"r"(b[1]));
}

// =========================================================================
// HMMA bf16x3 GEMM: C[M,N] = alpha*A[M,K] @ B^T (+bias)(gelu)(+res)
// TRB=true : B stored [N,K] row-major (weights).
// TRB=false: B stored [K,N] row-major (attention V / plain matmul).
// Tile 128x128x32, 256 threads (8 warps, 2x4), padded smem (stride 40 bf16).
// 3-pass split accumulation: Ahi*Bhi + Ahi*Blo + Alo*Bhi (fp32 acc).
// =========================================================================
#define LDS 40   // smem row stride in bf16 (80 bytes: 16B-aligned, conflict-free)

template<bool TRB, bool BIAS, bool RES, bool GELU, bool GATHER>
__global__ void __launch_bounds__(256, 2)
mma_gemm(const float* __restrict__ A, const float* __restrict__ Bm,
         const float* __restrict__ bias, const float* __restrict__ res,
         float* __restrict__ C,
         int M, int N, int K, int lda, int ldb, int ldc,
         long long aOffB, long long aOffH, long long bOffB, long long bOffH,
         long long cOffB, long long cOffH, long long biasOffH,
         int nh, float alpha,
         const int* __restrict__ gidx, int gStride, int rowsPerB)
{
    __shared__ __align__(16) __nv_bfloat16 sAhi[128*LDS];
    __shared__ __align__(16) __nv_bfloat16 sAlo[128*LDS];
    __shared__ __align__(16) __nv_bfloat16 sBhi[128*LDS];
    __shared__ __align__(16) __nv_bfloat16 sBlo[128*LDS];

    int tid = threadIdx.x;
    int wid = tid >> 5, lane = tid & 31;
    int wm = wid & 1, wn = wid >> 1;
    int z = blockIdx.z;
    int b = z / nh, h = z - b*nh;
    const float* Ab = GATHER ? A : (A + (long long)b*aOffB + (long long)h*aOffH);
    const float* Bb = Bm + (long long)b*bOffB + (long long)h*bOffH;
    float* Cb = C + (long long)b*cOffB + (long long)h*cOffH;
    const float* biasb = BIAS ? (bias + (long long)h*biasOffH) : nullptr;
    const float* resb  = RES  ? (res  + (long long)b*cOffB + (long long)h*cOffH) : nullptr;
    int row0 = blockIdx.y * 128, col0 = blockIdx.x * 128;

    uint32_t aHiB = smem_u32(sAhi), aLoB = smem_u32(sAlo);
    uint32_t bHiB = smem_u32(sBhi), bLoB = smem_u32(sBlo);

    float acc[4][4][4] = {};

    for (int k0 = 0; k0 < K; k0 += 32) {
        // ---- load + split A tile (128 x 32) ----
        #pragma unroll
        for (int i = 0; i < 4; i++) {
            int idx = tid + i*256;
            int r = idx >> 3, kb = (idx & 7) << 2;
            float4 v = make_float4(0.f,0.f,0.f,0.f);
            int grow = row0 + r;
            if (grow < M) {
                if (GATHER) {
                    long long arow = (long long)b*rowsPerB + gidx[(long long)z*gStride + grow];
                    v = *(const float4*)(A + arow*lda + k0 + kb);
                } else {
                    v = *(const float4*)(Ab + (long long)grow*lda + k0 + kb);
                }
            }
            __nv_bfloat162 h01 = __floats2bfloat162_rn(v.x, v.y);
            __nv_bfloat162 h23 = __floats2bfloat162_rn(v.z, v.w);
            __nv_bfloat162 l01 = __floats2bfloat162_rn(v.x - __bfloat162float(h01.x), v.y - __bfloat162float(h01.y));
            __nv_bfloat162 l23 = __floats2bfloat162_rn(v.z - __bfloat162float(h23.x), v.w - __bfloat162float(h23.y));
            uint2 hv, lv;
            hv.x = *(uint32_t*)&h01; hv.y = *(uint32_t*)&h23;
            lv.x = *(uint32_t*)&l01; lv.y = *(uint32_t*)&l23;
            *(uint2*)&sAhi[r*LDS + kb] = hv;
            *(uint2*)&sAlo[r*LDS + kb] = lv;
        }
        // ---- load + split B tile into smem [n][k] ----
        if (TRB) {
            #pragma unroll
            for (int i = 0; i < 4; i++) {
                int idx = tid + i*256;
                int r = idx >> 3, kb = (idx & 7) << 2;
                float4 v = make_float4(0.f,0.f,0.f,0.f);
                int gcol = col0 + r;
                if (gcol < N) v = *(const float4*)(Bb + (long long)gcol*ldb + k0 + kb);
                __nv_bfloat162 h01 = __floats2bfloat162_rn(v.x, v.y);
                __nv_bfloat162 h23 = __floats2bfloat162_rn(v.z, v.w);
                __nv_bfloat162 l01 = __floats2bfloat162_rn(v.x - __bfloat162float(h01.x), v.y - __bfloat162float(h01.y));
                __nv_bfloat162 l23 = __floats2bfloat162_rn(v.z - __bfloat162float(h23.x), v.w - __bfloat162float(h23.y));
                uint2 hv, lv;
                hv.x = *(uint32_t*)&h01; hv.y = *(uint32_t*)&h23;
                lv.x = *(uint32_t*)&l01; lv.y = *(uint32_t*)&l23;
                *(uint2*)&sBhi[r*LDS + kb] = hv;
                *(uint2*)&sBlo[r*LDS + kb] = lv;
            }
        } else {
            // B stored [K,N]: transpose on load (coalesced across n)
            #pragma unroll
            for (int i = 0; i < 16; i++) {
                int idx = tid + i*256;
                int n = idx & 127, kk = idx >> 7;
                float v = 0.f;
                int gcol = col0 + n;
                if (gcol < N) v = Bb[(long long)(k0 + kk)*ldb + gcol];
                __nv_bfloat16 hv = __float2bfloat16(v);
                __nv_bfloat16 lv = __float2bfloat16(v - __bfloat162float(hv));
                sBhi[n*LDS + kk] = hv;
                sBlo[n*LDS + kk] = lv;
            }
        }
        __syncthreads();
        // ---- mma over 2 k16 halves ----
        #pragma unroll
        for (int kh = 0; kh < 2; kh++) {
            uint32_t bh[4][2], bl[4][2];
            #pragma unroll
            for (int ni = 0; ni < 4; ni++) {
                uint32_t off = ((uint32_t)((wn*32 + ni*8 + (lane & 7))*LDS + kh*16 + ((lane >> 3) & 1)*8)) * 2u;
                ldm_x2(bh[ni][0], bh[ni][1], bHiB + off);
                ldm_x2(bl[ni][0], bl[ni][1], bLoB + off);
            }
            #pragma unroll
            for (int mi = 0; mi < 4; mi++) {
                uint32_t off = ((uint32_t)((wm*64 + mi*16 + (lane & 15))*LDS + kh*16 + (lane >> 4)*8)) * 2u;
                uint32_t ah[4], al[4];
                ldm_x4(ah[0], ah[1], ah[2], ah[3], aHiB + off);
                ldm_x4(al[0], al[1], al[2], al[3], aLoB + off);
                #pragma unroll
                for (int ni = 0; ni < 4; ni++) {
                    mma_bf16(acc[mi][ni], ah, bh[ni]);
                    mma_bf16(acc[mi][ni], ah, bl[ni]);
                    mma_bf16(acc[mi][ni], al, bh[ni]);
                }
            }
        }
        __syncthreads();
    }

    // ---- epilogue ----
    #pragma unroll
    for (int mi = 0; mi < 4; mi++) {
        #pragma unroll
        for (int ni = 0; ni < 4; ni++) {
            int rg = row0 + wm*64 + mi*16 + (lane >> 2);
            int cg = col0 + wn*32 + ni*8 + (lane & 3)*2;
            if (cg >= N) continue;
            #pragma unroll
            for (int half = 0; half < 2; half++) {
                int row = rg + half*8;
                if (row < M) {
                    float v0 = acc[mi][ni][half*2+0]*alpha;
                    float v1 = acc[mi][ni][half*2+1]*alpha;
                    if (BIAS) { v0 += biasb[cg]; v1 += biasb[cg+1]; }
                    if (GELU) { v0 = gelu_tanh(v0); v1 = gelu_tanh(v1); }
                    if (RES)  { v0 += resb[(long long)row*ldc + cg]; v1 += resb[(long long)row*ldc + cg + 1]; }
                    float2 o = make_float2(v0, v1);
                    *(float2*)&Cb[(long long)row*ldc + cg] = o;
                }
            }
        }
    }
}

// ---------------- LayerNorm ----------------
__global__ void ln_kernel(const float* __restrict__ x, const float* __restrict__ g,
                          const float* __restrict__ bta, float* __restrict__ y)
{
    long long row = blockIdx.x;
    int tid = threadIdx.x;
    const float4* xr = (const float4*)(x + row*Hn);
    float4 xv = xr[tid];
    float s = xv.x+xv.y+xv.z+xv.w;
    float q = xv.x*xv.x+xv.y*xv.y+xv.z*xv.z+xv.w*xv.w;
    for (int o=16;o;o>>=1){ s += __shfl_down_sync(0xffffffffu,s,o); q += __shfl_down_sync(0xffffffffu,q,o); }
    __shared__ float ss[8], qq[8];
    __shared__ float mv[2];
    int lane = tid&31, wd = tid>>5;
    if (lane==0){ ss[wd]=s; qq[wd]=q; }
    __syncthreads();
    if (tid==0){
        float a=0,c=0;
        #pragma unroll
        for(int i=0;i<8;i++){a+=ss[i]; c+=qq[i];}
        float mean = a*(1.f/Hn);
        float var  = c*(1.f/Hn) - mean*mean;
        mv[0]=mean; mv[1]=rsqrtf(var+1e-5f);
    }
    __syncthreads();
    float mean=mv[0], inv=mv[1];
    float4 gv = ((const float4*)g)[tid];
    float4 bv = ((const float4*)bta)[tid];
    float4 o;
    o.x=(xv.x-mean)*inv*gv.x+bv.x;
    o.y=(xv.y-mean)*inv*gv.y+bv.y;
    o.z=(xv.z-mean)*inv*gv.z+bv.z;
    o.w=(xv.w-mean)*inv*gv.w+bv.w;
    ((float4*)(y + row*Hn))[tid] = o;
}

// ---------------- row softmax ----------------
__global__ void softmax_kernel(float* __restrict__ p, int cols)
{
    long long row = blockIdx.x;
    float* r = p + row*cols;
    int tid = threadIdx.x;
    float mx = -1e30f;
    for (int i=tid;i<cols;i+=128) mx = fmaxf(mx, r[i]);
    for (int o=16;o;o>>=1) mx = fmaxf(mx, __shfl_xor_sync(0xffffffffu,mx,o));
    __shared__ float sm[4], sq[4];
    if ((tid&31)==0) sm[tid>>5]=mx;
    __syncthreads();
    mx = fmaxf(fmaxf(sm[0],sm[1]),fmaxf(sm[2],sm[3]));
    float sum = 0.f;
    for (int i=tid;i<cols;i+=128){ float e=__expf(r[i]-mx); r[i]=e; sum+=e; }
    for (int o=16;o;o>>=1) sum += __shfl_xor_sync(0xffffffffu,sum,o);
    if ((tid&31)==0) sq[tid>>5]=sum;
    __syncthreads();
    sum = sq[0]+sq[1]+sq[2]+sq[3];
    float inv = 1.f/sum;
    for (int i=tid;i<cols;i+=128) r[i]*=inv;
}

// ---------------- mean over rows ----------------
__global__ void mean_rows(const float* __restrict__ x, float* __restrict__ out, int rows)
{
    int b = blockIdx.x, tid = threadIdx.x;
    const float4* xb = (const float4*)(x + (long long)b*rows*Hn);
    float4 acc = {0,0,0,0};
    for (int v=0; v<rows; v++){
        float4 t = xb[v*(Hn/4) + tid];
        acc.x+=t.x; acc.y+=t.y; acc.z+=t.z; acc.w+=t.w;
    }
    float inv = 1.f/rows;
    float4 o = {acc.x*inv, acc.y*inv, acc.z*inv, acc.w*inv};
    ((float4*)(out + (long long)b*Hn))[tid] = o;
}

// ---------------- ctxpart ----------------
__global__ void ctxpart_kernel(const float* __restrict__ ctx, const float* __restrict__ W,
                               const float* __restrict__ bias, float* __restrict__ out)
{
    int z = blockIdx.x; int b = z >> 3, e = z & 7;
    int tid = threadIdx.x;
    const float4* c4 = (const float4*)(ctx + (long long)b*Hn);
    const float4* w4 = (const float4*)(W + (long long)e*2*Hn + Hn);
    float4 c = c4[tid], w = w4[tid];
    float s = c.x*w.x + c.y*w.y + c.z*w.z + c.w*w.w;
    for (int o=16;o;o>>=1) s += __shfl_down_sync(0xffffffffu,s,o);
    __shared__ float sh[8];
    if ((tid&31)==0) sh[tid>>5]=s;
    __syncthreads();
    if (tid==0){ float t=0; for(int i=0;i<8;i++) t+=sh[i]; out[z] = t + bias[e]; }
}

// ---------------- gating ----------------
__global__ void gate_kernel(const float* __restrict__ x, const float* __restrict__ W,
                            const float* __restrict__ cp, float* __restrict__ probs, int S)
{
    int token = blockIdx.x; int b = token / S;
    int tid = threadIdx.x;
    __shared__ float xs[Hn];
    ((float4*)xs)[tid] = ((const float4*)(x + (long long)token*Hn))[tid];
    __syncthreads();
    int w = tid >> 5, lane = tid & 31;
    const float* We = W + (long long)w*2*Hn;
    float s = 0.f;
    for (int hh = lane; hh < Hn; hh += 32) s += xs[hh]*We[hh];
    for (int o=16;o;o>>=1) s += __shfl_down_sync(0xffffffffu,s,o);
    __shared__ float lg[En];
    if (lane==0) lg[w] = s + cp[b*En + w];
    __syncthreads();
    if (tid==0){
        float mx = lg[0];
        #pragma unroll
        for (int e=1;e<En;e++) mx = fmaxf(mx, lg[e]);
        float ev[En]; float sum = 0.f;
        #pragma unroll
        for (int e=0;e<En;e++){ ev[e]=expf(lg[e]-mx); sum+=ev[e]; }
        float inv = 1.f/sum;
        #pragma unroll
        for (int e=0;e<En;e++) probs[(long long)token*En+e]=ev[e]*inv;
    }
}

// ---------------- top-k (bitonic; value desc, index asc) ----------------
__global__ void topk_kernel(const float* __restrict__ probs, int S, int k, int kmax,
                            int* __restrict__ sel, int* __restrict__ pos)
{
    int z = blockIdx.x; int b = z / En, e = z - b*En;
    int tid = threadIdx.x;
    __shared__ float sv[1024];
    __shared__ int   si[1024];
    for (int i=tid;i<1024;i+=256){
        sv[i] = (i < S) ? probs[((long long)b*S + i)*En + e] : -1e30f;
        si[i] = i;
    }
    __syncthreads();
    for (int ksz=2; ksz<=1024; ksz<<=1){
        for (int j=ksz>>1; j>0; j>>=1){
            for (int i=tid; i<1024; i+=256){
                int ixj = i ^ j;
                if (ixj > i){
                    float v1=sv[i], v2=sv[ixj];
                    int i1=si[i], i2=si[ixj];
                    bool before = (v1 > v2) || (v1 == v2 && i1 < i2);
                    bool asc = ((i & ksz) == 0);
                    if (asc ? !before : before){
                        sv[i]=v2; sv[ixj]=v1; si[i]=i2; si[ixj]=i1;
                    }
                }
            }
            __syncthreads();
        }
    }
    for (int i=tid;i<S;i+=256) pos[(long long)z*S + i] = 0;
    __syncthreads();
    for (int j=tid;j<k;j+=256){
        int s = si[j];
        sel[(long long)z*kmax + j] = s;
        pos[(long long)z*S + s] = j + 1;
    }
}

// ---------------- combine ----------------
__global__ void combine_kernel(const float* __restrict__ down, const int* __restrict__ pos,
                               const float* __restrict__ resid, float* __restrict__ out,
                               int S, int kmax)
{
    int bs = blockIdx.x; int b = bs / S; int s = bs - b*S;
    int tid = threadIdx.x;
    int p[En]; int cnt = 0;
    #pragma unroll
    for (int e=0;e<En;e++){ p[e] = pos[((long long)(b*En+e))*S + s]; cnt += (p[e]>0); }
    float inv = 1.f / (cnt > 0 ? cnt : 1);
    float4 acc = {0,0,0,0};
    #pragma unroll
    for (int e=0;e<En;e++){
        if (p[e] > 0){
            const float4* dr = (const float4*)(down + ((long long)(b*En+e)*kmax + (p[e]-1))*Hn);
            float4 d = dr[tid];
            acc.x+=d.x; acc.y+=d.y; acc.z+=d.z; acc.w+=d.w;
        }
    }
    float4 r = ((const float4*)(resid + (long long)bs*Hn))[tid];
    float4 o = {r.x+acc.x*inv, r.y+acc.y*inv, r.z+acc.z*inv, r.w+acc.w*inv};
    ((float4*)(out + (long long)bs*Hn))[tid] = o;
}

// ---------------- host ----------------
extern "C" void kernel_launch(void* const* d_in, const int* in_sizes, int n_in,
                              void* d_out, int out_size)
{
    const float* query    = (const float*)d_in[0];
    const float* image    = (const float*)d_in[1];
    const float* textctx  = (const float*)d_in[2];
    const float* sa_w_in  = (const float*)d_in[3];
    const float* sa_b_in  = (const float*)d_in[4];
    const float* sa_w_out = (const float*)d_in[5];
    const float* sa_b_out = (const float*)d_in[6];
    const float* ca_w_in  = (const float*)d_in[7];
    const float* ca_b_in  = (const float*)d_in[8];
    const float* ca_w_out = (const float*)d_in[9];
    const float* ca_b_out = (const float*)d_in[10];
    const float* gate_img_w = (const float*)d_in[11];
    const float* gate_img_b = (const float*)d_in[12];
    const float* gate_txt_w = (const float*)d_in[13];
    const float* gate_txt_b = (const float*)d_in[14];
    const float* e_w1 = (const float*)d_in[15];
    const float* e_b1 = (const float*)d_in[16];
    const float* e_w2 = (const float*)d_in[17];
    const float* e_b2 = (const float*)d_in[18];
    const float* lnq_g = (const float*)d_in[19];
    const float* lnq_b = (const float*)d_in[20];
    const float* lnc_g = (const float*)d_in[21];
    const float* lnc_b = (const float*)d_in[22];
    const float* lnf_g = (const float*)d_in[23];
    const float* lnf_b = (const float*)d_in[24];

    float *pLn,*pQkv,*pAttn,*pQ1,*pQ2,*pQc,*pKv,*pSc,*pPt,*pPi,*pCtxI,*pCtxT,*pCpI,*pCpT,*pH,*pDown;
    int *pSelT,*pSelI,*pPosT,*pPosI;
    cudaGetSymbolAddress((void**)&pLn,  g_ln_buf);
    cudaGetSymbolAddress((void**)&pQkv, g_qkv);
    cudaGetSymbolAddress((void**)&pAttn,g_attn);
    cudaGetSymbolAddress((void**)&pQ1,  g_q1);
    cudaGetSymbolAddress((void**)&pQ2,  g_q2);
    cudaGetSymbolAddress((void**)&pQc,  g_qc);
    cudaGetSymbolAddress((void**)&pKv,  g_kv);
    cudaGetSymbolAddress((void**)&pSc,  g_scores);
    cudaGetSymbolAddress((void**)&pPt,  g_probs_txt);
    cudaGetSymbolAddress((void**)&pPi,  g_probs_img);
    cudaGetSymbolAddress((void**)&pCtxI,g_ctx_img);
    cudaGetSymbolAddress((void**)&pCtxT,g_ctx_txt);
    cudaGetSymbolAddress((void**)&pCpI, g_cp_img);
    cudaGetSymbolAddress((void**)&pCpT, g_cp_txt);
    cudaGetSymbolAddress((void**)&pH,   g_hbuf);
    cudaGetSymbolAddress((void**)&pDown,g_down);
    cudaGetSymbolAddress((void**)&pSelT,g_sel_txt);
    cudaGetSymbolAddress((void**)&pSelI,g_sel_img);
    cudaGetSymbolAddress((void**)&pPosT,g_pos_txt);
    cudaGetSymbolAddress((void**)&pPosI,g_pos_img);

    const int BT = Bn*Tn, BV = Bn*Vn;
    float* outQ = (float*)d_out;
    float* outI = outQ + (long long)BT*Hn;

    // 1) self-attention
    ln_kernel<<<BT,256>>>(query, lnq_g, lnq_b, pLn);
    mma_gemm<true,true,false,false,false><<<dim3(24,16,1),256>>>(pLn, sa_w_in, sa_b_in, nullptr, pQkv,
        BT, 3*Hn, Hn, Hn, Hn, 3*Hn, 0,0,0,0,0,0, 0, 1, 1.f, nullptr,0,0);
    // scores = Q @ K^T * 0.125   (A rows tokens, B rows tokens -> TRB)
    mma_gemm<true,false,false,false,false><<<dim3(4,4,Bn*NHn),256>>>(pQkv, pQkv+Hn, nullptr, nullptr, pSc,
        Tn, Tn, HDn, 3*Hn, 3*Hn, Tn,
        (long long)Tn*3*Hn, HDn, (long long)Tn*3*Hn, HDn,
        (long long)NHn*Tn*Tn, (long long)Tn*Tn, 0, NHn, 0.125f, nullptr,0,0);
    softmax_kernel<<<Bn*NHn*Tn,128>>>(pSc, Tn);
    // attn = P @ V   (B stored [K=T, N=HD] -> NTB)
    mma_gemm<false,false,false,false,false><<<dim3(1,4,Bn*NHn),256>>>(pSc, pQkv+2*Hn, nullptr, nullptr, pAttn,
        Tn, HDn, Tn, Tn, 3*Hn, Hn,
        (long long)NHn*Tn*Tn, (long long)Tn*Tn, (long long)Tn*3*Hn, HDn,
        (long long)Tn*Hn, HDn, 0, NHn, 1.f, nullptr,0,0);
    mma_gemm<true,true,true,false,false><<<dim3(8,16,1),256>>>(pAttn, sa_w_out, sa_b_out, query, pQ1,
        BT, Hn, Hn, Hn, Hn, Hn, 0,0,0,0,0,0, 0, 1, 1.f, nullptr,0,0);

    // 2) cross-attention
    ln_kernel<<<BT,256>>>(pQ1, lnc_g, lnc_b, pLn);
    mma_gemm<true,true,false,false,false><<<dim3(8,16,1),256>>>(pLn, ca_w_in, ca_b_in, nullptr, pQc,
        BT, Hn, Hn, Hn, Hn, Hn, 0,0,0,0,0,0, 0, 1, 1.f, nullptr,0,0);
    mma_gemm<true,true,false,false,false><<<dim3(16,18,1),256>>>(image, ca_w_in + (long long)Hn*Hn, ca_b_in + Hn, nullptr, pKv,
        BV, 2*Hn, Hn, Hn, Hn, 2*Hn, 0,0,0,0,0,0, 0, 1, 1.f, nullptr,0,0);
    mma_gemm<true,false,false,false,false><<<dim3(5,4,Bn*NHn),256>>>(pQc, pKv, nullptr, nullptr, pSc,
        Tn, Vn, HDn, Hn, 2*Hn, Vn,
        (long long)Tn*Hn, HDn, (long long)Vn*2*Hn, HDn,
        (long long)NHn*Tn*Vn, (long long)Tn*Vn, 0, NHn, 0.125f, nullptr,0,0);
    softmax_kernel<<<Bn*NHn*Tn,128>>>(pSc, Vn);
    mma_gemm<false,false,false,false,false><<<dim3(1,4,Bn*NHn),256>>>(pSc, pKv+Hn, nullptr, nullptr, pAttn,
        Tn, HDn, Vn, Vn, 2*Hn, Hn,
        (long long)NHn*Tn*Vn, (long long)Tn*Vn, (long long)Vn*2*Hn, HDn,
        (long long)Tn*Hn, HDn, 0, NHn, 1.f, nullptr,0,0);
    mma_gemm<true,true,true,false,false><<<dim3(8,16,1),256>>>(pAttn, ca_w_out, ca_b_out, pQ1, pQ2,
        BT, Hn, Hn, Hn, Hn, Hn, 0,0,0,0,0,0, 0, 1, 1.f, nullptr,0,0);

    // 3) gating
    mean_rows<<<Bn,256>>>(image, pCtxI, Vn);
    mean_rows<<<Bn,256>>>(textctx, pCtxT, Ln);
    ctxpart_kernel<<<Bn*En,256>>>(pCtxT, gate_img_w, gate_img_b, pCpI);
    ctxpart_kernel<<<Bn*En,256>>>(pCtxI, gate_txt_w, gate_txt_b, pCpT);
    gate_kernel<<<BV,256>>>(image, gate_img_w, pCpI, pPi, Vn);
    gate_kernel<<<BT,256>>>(pQ2, gate_txt_w, pCpT, pPt, Tn);
    topk_kernel<<<Bn*En,256>>>(pPt, Tn, KTXT, KTXT, pSelT, pPosT);
    topk_kernel<<<Bn*En,256>>>(pPi, Vn, KIMG, KIMG, pSelI, pPosI);

    // 4) text MoE
    ln_kernel<<<BT,256>>>(pQ2, lnf_g, lnf_b, pLn);
    mma_gemm<true,true,false,true,true><<<dim3(32,1,Bn*En),256>>>(pLn, e_w1, e_b1, nullptr, pH,
        KTXT, In, Hn, Hn, Hn, In,
        0,0, 0,(long long)In*Hn,
        (long long)En*KTXT*In, (long long)KTXT*In, (long long)In, En, 1.f, pSelT, KTXT, Tn);
    mma_gemm<true,true,false,false,false><<<dim3(8,1,Bn*En),256>>>(pH, e_w2, e_b2, nullptr, pDown,
        KTXT, Hn, In, In, In, Hn,
        (long long)En*KTXT*In, (long long)KTXT*In, 0,(long long)Hn*In,
        (long long)En*KTXT*Hn, (long long)KTXT*Hn, (long long)Hn, En, 1.f, nullptr,0,0);
    combine_kernel<<<BT,256>>>(pDown, pPosT, pQ2, outQ, Tn, KTXT);

    // 5) image MoE
    mma_gemm<true,true,false,true,true><<<dim3(32,1,Bn*En),256>>>(image, e_w1, e_b1, nullptr, pH,
        KIMG, In, Hn, Hn, Hn, In,
        0,0, 0,(long long)In*Hn,
        (long long)En*KIMG*In, (long long)KIMG*In, (long long)In, En, 1.f, pSelI, KIMG, Vn);
    mma_gemm<true,true,false,false,false><<<dim3(8,1,Bn*En),256>>>(pH, e_w2, e_b2, nullptr, pDown,
        KIMG, Hn, In, In, In, Hn,
        (long long)En*KIMG*In, (long long)KIMG*In, 0,(long long)Hn*In,
        (long long)En*KIMG*Hn, (long long)KIMG*Hn, (long long)Hn, En, 1.f, nullptr,0,0);
    combine_kernel<<<BV,256>>>(pDown, pPosI, image, outI, Vn, KIMG);
}

// round 8
// speedup vs baseline: 3.4165x; 1.1461x over previous
#include <cuda_runtime.h>
#include <cuda_bf16.h>
#include <cstdint>
#include <math.h>

// ---------------- problem constants ----------------
#define Bn 4
#define Tn 512
#define Vn 576
#define Ln 256
#define Hn 1024
#define NHn 16
#define HDn 64
#define In 4096
#define En 8
#define KTXT 80
#define KIMG 90

// weight offsets inside the big split-weight buffers (elements)
static const long long W_SAIN  = 0;
static const long long W_SAOUT = 3145728;
static const long long W_CAIN  = 4194304;
static const long long W_CAOUT = 7340032;
static const long long W_EW1   = 8388608;
static const long long W_EW2   = 41943040;
#define W_TOTAL 75497472

// ---------------- device scratch ----------------
__device__ __nv_bfloat16 g_w_hi[W_TOTAL];
__device__ __nv_bfloat16 g_w_lo[W_TOTAL];
__device__ __nv_bfloat16 g_img_hi[Bn*Vn*Hn];
__device__ __nv_bfloat16 g_img_lo[Bn*Vn*Hn];
__device__ __nv_bfloat16 g_ln_hi[Bn*Tn*Hn];
__device__ __nv_bfloat16 g_ln_lo[Bn*Tn*Hn];
__device__ __nv_bfloat16 g_qkv_hi[Bn*Tn*3*Hn];
__device__ __nv_bfloat16 g_qkv_lo[Bn*Tn*3*Hn];
__device__ __nv_bfloat16 g_attn_hi[Bn*Tn*Hn];
__device__ __nv_bfloat16 g_attn_lo[Bn*Tn*Hn];
__device__ __nv_bfloat16 g_qc_hi[Bn*Tn*Hn];
__device__ __nv_bfloat16 g_qc_lo[Bn*Tn*Hn];
__device__ __nv_bfloat16 g_kv_hi[Bn*Vn*2*Hn];
__device__ __nv_bfloat16 g_kv_lo[Bn*Vn*2*Hn];
__device__ __nv_bfloat16 g_p_hi[Bn*NHn*Tn*Vn];
__device__ __nv_bfloat16 g_p_lo[Bn*NHn*Tn*Vn];
__device__ __nv_bfloat16 g_h_hi[Bn*En*KIMG*In];
__device__ __nv_bfloat16 g_h_lo[Bn*En*KIMG*In];

__device__ float g_scores[Bn*NHn*Tn*Vn];
__device__ float g_q1   [Bn*Tn*Hn];
__device__ float g_q2   [Bn*Tn*Hn];
__device__ float g_probs_txt[Bn*Tn*En];
__device__ float g_probs_img[Bn*Vn*En];
__device__ float g_ctx_img[Bn*Hn];
__device__ float g_ctx_txt[Bn*Hn];
__device__ float g_cp_img[Bn*En];
__device__ float g_cp_txt[Bn*En];
__device__ int   g_sel_txt[Bn*En*KTXT];
__device__ int   g_sel_img[Bn*En*KIMG];
__device__ int   g_pos_txt[Bn*En*Tn];
__device__ int   g_pos_img[Bn*En*Vn];
__device__ float g_down [Bn*En*KIMG*Hn];

// ---------------- helpers ----------------
__device__ __forceinline__ uint32_t smem_u32(const void* p){
    uint32_t a;
    asm("{ .reg .u64 t; cvta.to.shared.u64 t, %1; cvt.u32.u64 %0, t; }" : "=r"(a) : "l"(p));
    return a;
}
__device__ __forceinline__ float gelu_tanh(float x){
    float x3 = x*x*x;
    return 0.5f*x*(1.0f+tanhf(0.7978845608028654f*(x+0.044715f*x3)));
}
__device__ __forceinline__ void ldm_x4(uint32_t& r0,uint32_t& r1,uint32_t& r2,uint32_t& r3, uint32_t addr){
    asm volatile("ldmatrix.sync.aligned.m8n8.x4.shared.b16 {%0,%1,%2,%3}, [%4];"
      : "=r"(r0),"=r"(r1),"=r"(r2),"=r"(r3) : "r"(addr));
}
__device__ __forceinline__ void ldm_x2(uint32_t& r0,uint32_t& r1, uint32_t addr){
    asm volatile("ldmatrix.sync.aligned.m8n8.x2.shared.b16 {%0,%1}, [%2];"
      : "=r"(r0),"=r"(r1) : "r"(addr));
}
__device__ __forceinline__ void mma_bf16(float* c, const uint32_t* a, const uint32_t* b){
    asm volatile("mma.sync.aligned.m16n8k16.row.col.f32.bf16.bf16.f32 "
      "{%0,%1,%2,%3}, {%4,%5,%6,%7}, {%8,%9}, {%0,%1,%2,%3};"
      : "+f"(c[0]),"+f"(c[1]),"+f"(c[2]),"+f"(c[3])
      : "r"(a[0]),"r"(a[1]),"r"(a[2]),"r"(a[3]), "r"(b[0]),"r"(b[1]));
}
__device__ __forceinline__ void cp16(uint32_t d, const void* s, bool ok){
    asm volatile("cp.async.cg.shared.global [%0], [%1], 16, %2;"
      :: "r"(d), "l"(s), "r"(ok ? 16 : 0) : "memory");
}
#define CP_COMMIT() asm volatile("cp.async.commit_group;" ::: "memory")
#define CP_WAIT1() asm volatile("cp.async.wait_group 1;" ::: "memory")
#define CP_WAIT0() asm volatile("cp.async.wait_group 0;" ::: "memory")

__device__ __forceinline__ void split2(float x, float y, uint32_t& hv, uint32_t& lv){
    __nv_bfloat162 h = __floats2bfloat162_rn(x, y);
    __nv_bfloat162 l = __floats2bfloat162_rn(x - __bfloat162float(h.x), y - __bfloat162float(h.y));
    hv = *(uint32_t*)&h; lv = *(uint32_t*)&l;
}

// =========================================================================
// HMMA bf16x3 GEMM from pre-split hi/lo bf16 inputs.
// C[M,N] = alpha * A @ B^T (+bias)(gelu)(+res); outputs fp32 and/or hi/lo bf16.
// Tile 128x128x32, 256 threads (8 warps 2x4). cp.async double-buffered (TRB).
// =========================================================================
#define LDS 40           // smem row stride in bf16
#define BUFB 10240       // one 128xLDS bf16 buffer in bytes
#define STAGEB 40960     // 4 buffers per stage
#define SMEMB 81920      // 2 stages

template<bool TRB, bool BIAS, bool RES, bool GELU, bool GATHER, bool OUTF32, bool OUTSPLIT>
__global__ void __launch_bounds__(256, 2)
mma_gemm(const __nv_bfloat16* __restrict__ Ahi, const __nv_bfloat16* __restrict__ Alo,
         const __nv_bfloat16* __restrict__ Bhi, const __nv_bfloat16* __restrict__ Blo,
         const float* __restrict__ bias, const float* __restrict__ res,
         float* __restrict__ C, __nv_bfloat16* __restrict__ Chi, __nv_bfloat16* __restrict__ Clo,
         int M, int N, int K, int lda, int ldb, int ldc,
         long long aOffB, long long aOffH, long long bOffB, long long bOffH,
         long long cOffB, long long cOffH, long long biasOffH,
         int nh, float alpha,
         const int* __restrict__ gidx, int gStride, int rowsPerB)
{
    extern __shared__ char dynsmem[];
    uint32_t sbase = smem_u32(dynsmem);

    int tid = threadIdx.x;
    int wid = tid >> 5, lane = tid & 31;
    int wm = wid & 1, wn = wid >> 1;
    int z = blockIdx.z;
    int b = z / nh, h = z - b*nh;
    const __nv_bfloat16* AhB = GATHER ? Ahi : (Ahi + (long long)b*aOffB + (long long)h*aOffH);
    const __nv_bfloat16* AlB = GATHER ? Alo : (Alo + (long long)b*aOffB + (long long)h*aOffH);
    const __nv_bfloat16* BhB = Bhi + (long long)b*bOffB + (long long)h*bOffH;
    const __nv_bfloat16* BlB = Blo + (long long)b*bOffB + (long long)h*bOffH;
    const float* biasb = BIAS ? (bias + (long long)h*biasOffH) : nullptr;
    const float* resb  = RES  ? (res  + (long long)b*cOffB + (long long)h*cOffH) : nullptr;
    int row0 = blockIdx.y * 128, col0 = blockIdx.x * 128;
    int NC = K >> 5;

    float acc[4][4][4] = {};

    if (TRB) {
        // ---- async double-buffered producer ----
        auto load_chunk = [&](int c, int s){
            int k0 = c << 5;
            uint32_t st = sbase + s*STAGEB;
            #pragma unroll
            for (int i = 0; i < 2; i++) {
                int seg = tid + i*256;
                int r = seg >> 2, ks = (seg & 3) << 3;
                // A
                {
                    int grow = row0 + r;
                    bool ok = grow < M;
                    long long arow;
                    if (GATHER) arow = ok ? ((long long)b*rowsPerB + gidx[(long long)z*gStride + grow]) : 0;
                    else        arow = ok ? grow : 0;
                    uint32_t doff = (uint32_t)(r*LDS + ks)*2u;
                    cp16(st + doff,        AhB + arow*lda + k0 + ks, ok);
                    cp16(st + BUFB + doff, AlB + arow*lda + k0 + ks, ok);
                }
                // B
                {
                    int gcol = col0 + r;
                    bool ok = gcol < N;
                    long long brow = ok ? gcol : 0;
                    uint32_t doff = (uint32_t)(r*LDS + ks)*2u;
                    cp16(st + 2*BUFB + doff, BhB + brow*ldb + k0 + ks, ok);
                    cp16(st + 3*BUFB + doff, BlB + brow*ldb + k0 + ks, ok);
                }
            }
        };
        load_chunk(0, 0); CP_COMMIT();
        for (int c = 0; c < NC; c++) {
            int s = c & 1;
            if (c + 1 < NC) { load_chunk(c+1, 1-s); CP_COMMIT(); CP_WAIT1(); }
            else            { CP_WAIT0(); }
            __syncthreads();
            uint32_t aHiS = sbase + s*STAGEB;
            uint32_t aLoS = aHiS + BUFB;
            uint32_t bHiS = aHiS + 2*BUFB;
            uint32_t bLoS = aHiS + 3*BUFB;
            #pragma unroll
            for (int kh = 0; kh < 2; kh++) {
                uint32_t bh[4][2], bl[4][2];
                #pragma unroll
                for (int ni = 0; ni < 4; ni++) {
                    uint32_t off = ((uint32_t)((wn*32 + ni*8 + (lane & 7))*LDS + kh*16 + ((lane >> 3) & 1)*8)) * 2u;
                    ldm_x2(bh[ni][0], bh[ni][1], bHiS + off);
                    ldm_x2(bl[ni][0], bl[ni][1], bLoS + off);
                }
                #pragma unroll
                for (int mi = 0; mi < 4; mi++) {
                    uint32_t off = ((uint32_t)((wm*64 + mi*16 + (lane & 15))*LDS + kh*16 + (lane >> 4)*8)) * 2u;
                    uint32_t ah[4], al[4];
                    ldm_x4(ah[0], ah[1], ah[2], ah[3], aHiS + off);
                    ldm_x4(al[0], al[1], al[2], al[3], aLoS + off);
                    #pragma unroll
                    for (int ni = 0; ni < 4; ni++) {
                        mma_bf16(acc[mi][ni], ah, bh[ni]);
                        mma_bf16(acc[mi][ni], ah, bl[ni]);
                        mma_bf16(acc[mi][ni], al, bh[ni]);
                    }
                }
            }
            __syncthreads();
        }
    } else {
        // ---- NTB (B stored [K,N]) : single-stage synchronous ----
        uint32_t aHiS = sbase, aLoS = sbase + BUFB, bHiS = sbase + 2*BUFB, bLoS = sbase + 3*BUFB;
        __nv_bfloat16* sBh = (__nv_bfloat16*)(dynsmem + 2*BUFB);
        __nv_bfloat16* sBl = (__nv_bfloat16*)(dynsmem + 3*BUFB);
        for (int c = 0; c < NC; c++) {
            int k0 = c << 5;
            #pragma unroll
            for (int i = 0; i < 2; i++) {
                int seg = tid + i*256;
                int r = seg >> 2, ks = (seg & 3) << 3;
                int grow = row0 + r;
                uint4 hv = make_uint4(0,0,0,0), lv = make_uint4(0,0,0,0);
                if (grow < M) {
                    hv = *(const uint4*)(AhB + (long long)grow*lda + k0 + ks);
                    lv = *(const uint4*)(AlB + (long long)grow*lda + k0 + ks);
                }
                *(uint4*)(dynsmem + (r*LDS + ks)*2) = hv;
                *(uint4*)(dynsmem + BUFB + (r*LDS + ks)*2) = lv;
            }
            #pragma unroll
            for (int i = 0; i < 16; i++) {
                int idx = tid + i*256;
                int n = idx & 127, kk = idx >> 7;
                __nv_bfloat16 hv = __float2bfloat16(0.f), lv = __float2bfloat16(0.f);
                int gcol = col0 + n;
                if (gcol < N) {
                    hv = BhB[(long long)(k0 + kk)*ldb + gcol];
                    lv = BlB[(long long)(k0 + kk)*ldb + gcol];
                }
                sBh[n*LDS + kk] = hv;
                sBl[n*LDS + kk] = lv;
            }
            __syncthreads();
            #pragma unroll
            for (int kh = 0; kh < 2; kh++) {
                uint32_t bh[4][2], bl[4][2];
                #pragma unroll
                for (int ni = 0; ni < 4; ni++) {
                    uint32_t off = ((uint32_t)((wn*32 + ni*8 + (lane & 7))*LDS + kh*16 + ((lane >> 3) & 1)*8)) * 2u;
                    ldm_x2(bh[ni][0], bh[ni][1], bHiS + off);
                    ldm_x2(bl[ni][0], bl[ni][1], bLoS + off);
                }
                #pragma unroll
                for (int mi = 0; mi < 4; mi++) {
                    uint32_t off = ((uint32_t)((wm*64 + mi*16 + (lane & 15))*LDS + kh*16 + (lane >> 4)*8)) * 2u;
                    uint32_t ah[4], al[4];
                    ldm_x4(ah[0], ah[1], ah[2], ah[3], aHiS + off);
                    ldm_x4(al[0], al[1], al[2], al[3], aLoS + off);
                    #pragma unroll
                    for (int ni = 0; ni < 4; ni++) {
                        mma_bf16(acc[mi][ni], ah, bh[ni]);
                        mma_bf16(acc[mi][ni], ah, bl[ni]);
                        mma_bf16(acc[mi][ni], al, bh[ni]);
                    }
                }
            }
            __syncthreads();
        }
    }

    // ---- epilogue ----
    float* Cb = OUTF32 ? (C + (long long)b*cOffB + (long long)h*cOffH) : nullptr;
    __nv_bfloat16* ChB = OUTSPLIT ? (Chi + (long long)b*cOffB + (long long)h*cOffH) : nullptr;
    __nv_bfloat16* ClB = OUTSPLIT ? (Clo + (long long)b*cOffB + (long long)h*cOffH) : nullptr;
    #pragma unroll
    for (int mi = 0; mi < 4; mi++) {
        #pragma unroll
        for (int ni = 0; ni < 4; ni++) {
            int rg = row0 + wm*64 + mi*16 + (lane >> 2);
            int cg = col0 + wn*32 + ni*8 + (lane & 3)*2;
            if (cg >= N) continue;
            #pragma unroll
            for (int half = 0; half < 2; half++) {
                int row = rg + half*8;
                if (row < M) {
                    float v0 = acc[mi][ni][half*2+0]*alpha;
                    float v1 = acc[mi][ni][half*2+1]*alpha;
                    if (BIAS) { v0 += biasb[cg]; v1 += biasb[cg+1]; }
                    if (GELU) { v0 = gelu_tanh(v0); v1 = gelu_tanh(v1); }
                    if (RES)  { v0 += resb[(long long)row*ldc + cg]; v1 += resb[(long long)row*ldc + cg + 1]; }
                    if (OUTF32) *(float2*)&Cb[(long long)row*ldc + cg] = make_float2(v0, v1);
                    if (OUTSPLIT) {
                        uint32_t hv, lv;
                        split2(v0, v1, hv, lv);
                        *(uint32_t*)&ChB[(long long)row*ldc + cg] = hv;
                        *(uint32_t*)&ClB[(long long)row*ldc + cg] = lv;
                    }
                }
            }
        }
    }
}

// ---------------- fp32 -> bf16 hi/lo splitter ----------------
__global__ void split_kernel(const float* __restrict__ x, __nv_bfloat16* __restrict__ hi,
                             __nv_bfloat16* __restrict__ lo, int n4)
{
    int i = blockIdx.x*blockDim.x + threadIdx.x;
    if (i >= n4) return;
    float4 v = ((const float4*)x)[i];
    uint32_t h0, l0, h1, l1;
    split2(v.x, v.y, h0, l0);
    split2(v.z, v.w, h1, l1);
    ((uint2*)hi)[i] = make_uint2(h0, h1);
    ((uint2*)lo)[i] = make_uint2(l0, l1);
}

// ---------------- LayerNorm -> hi/lo bf16 ----------------
__global__ void ln_split(const float* __restrict__ x, const float* __restrict__ g,
                         const float* __restrict__ bta,
                         __nv_bfloat16* __restrict__ yhi, __nv_bfloat16* __restrict__ ylo)
{
    long long row = blockIdx.x;
    int tid = threadIdx.x;
    const float4* xr = (const float4*)(x + row*Hn);
    float4 xv = xr[tid];
    float s = xv.x+xv.y+xv.z+xv.w;
    float q = xv.x*xv.x+xv.y*xv.y+xv.z*xv.z+xv.w*xv.w;
    for (int o=16;o;o>>=1){ s += __shfl_down_sync(0xffffffffu,s,o); q += __shfl_down_sync(0xffffffffu,q,o); }
    __shared__ float ss[8], qq[8];
    __shared__ float mv[2];
    int lane = tid&31, wd = tid>>5;
    if (lane==0){ ss[wd]=s; qq[wd]=q; }
    __syncthreads();
    if (tid==0){
        float a=0,c=0;
        #pragma unroll
        for(int i=0;i<8;i++){a+=ss[i]; c+=qq[i];}
        float mean = a*(1.f/Hn);
        float var  = c*(1.f/Hn) - mean*mean;
        mv[0]=mean; mv[1]=rsqrtf(var+1e-5f);
    }
    __syncthreads();
    float mean=mv[0], inv=mv[1];
    float4 gv = ((const float4*)g)[tid];
    float4 bv = ((const float4*)bta)[tid];
    float o0=(xv.x-mean)*inv*gv.x+bv.x;
    float o1=(xv.y-mean)*inv*gv.y+bv.y;
    float o2=(xv.z-mean)*inv*gv.z+bv.z;
    float o3=(xv.w-mean)*inv*gv.w+bv.w;
    uint32_t h0,l0,h1,l1;
    split2(o0,o1,h0,l0);
    split2(o2,o3,h1,l1);
    ((uint2*)(yhi + row*Hn))[tid] = make_uint2(h0,h1);
    ((uint2*)(ylo + row*Hn))[tid] = make_uint2(l0,l1);
}

// ---------------- row softmax fp32 -> hi/lo bf16 ----------------
__global__ void softmax_split(const float* __restrict__ p,
                              __nv_bfloat16* __restrict__ phi, __nv_bfloat16* __restrict__ plo,
                              int cols)
{
    long long row = blockIdx.x;
    const float* r = p + row*cols;
    int tid = threadIdx.x;
    float tmp[5];
    float mx = -1e30f;
    int cnt = 0;
    for (int i=tid;i<cols;i+=128){ float v = r[i]; tmp[cnt++] = v; mx = fmaxf(mx, v); }
    for (int o=16;o;o>>=1) mx = fmaxf(mx, __shfl_xor_sync(0xffffffffu,mx,o));
    __shared__ float sm[4], sq[4];
    if ((tid&31)==0) sm[tid>>5]=mx;
    __syncthreads();
    mx = fmaxf(fmaxf(sm[0],sm[1]),fmaxf(sm[2],sm[3]));
    float sum = 0.f;
    for (int j=0;j<cnt;j++){ float e=__expf(tmp[j]-mx); tmp[j]=e; sum+=e; }
    for (int o=16;o;o>>=1) sum += __shfl_xor_sync(0xffffffffu,sum,o);
    if ((tid&31)==0) sq[tid>>5]=sum;
    __syncthreads();
    sum = sq[0]+sq[1]+sq[2]+sq[3];
    float inv = 1.f/sum;
    cnt = 0;
    for (int i=tid;i<cols;i+=128){
        float v = tmp[cnt++]*inv;
        __nv_bfloat16 hv = __float2bfloat16(v);
        __nv_bfloat16 lv = __float2bfloat16(v - __bfloat162float(hv));
        phi[row*cols + i] = hv;
        plo[row*cols + i] = lv;
    }
}

// ---------------- mean over rows ----------------
__global__ void mean_rows(const float* __restrict__ x, float* __restrict__ out, int rows)
{
    int b = blockIdx.x, tid = threadIdx.x;
    const float4* xb = (const float4*)(x + (long long)b*rows*Hn);
    float4 acc = {0,0,0,0};
    for (int v=0; v<rows; v++){
        float4 t = xb[v*(Hn/4) + tid];
        acc.x+=t.x; acc.y+=t.y; acc.z+=t.z; acc.w+=t.w;
    }
    float inv = 1.f/rows;
    float4 o = {acc.x*inv, acc.y*inv, acc.z*inv, acc.w*inv};
    ((float4*)(out + (long long)b*Hn))[tid] = o;
}

// ---------------- ctxpart ----------------
__global__ void ctxpart_kernel(const float* __restrict__ ctx, const float* __restrict__ W,
                               const float* __restrict__ bias, float* __restrict__ out)
{
    int z = blockIdx.x; int b = z >> 3, e = z & 7;
    int tid = threadIdx.x;
    const float4* c4 = (const float4*)(ctx + (long long)b*Hn);
    const float4* w4 = (const float4*)(W + (long long)e*2*Hn + Hn);
    float4 c = c4[tid], w = w4[tid];
    float s = c.x*w.x + c.y*w.y + c.z*w.z + c.w*w.w;
    for (int o=16;o;o>>=1) s += __shfl_down_sync(0xffffffffu,s,o);
    __shared__ float sh[8];
    if ((tid&31)==0) sh[tid>>5]=s;
    __syncthreads();
    if (tid==0){ float t=0; for(int i=0;i<8;i++) t+=sh[i]; out[z] = t + bias[e]; }
}

// ---------------- gating ----------------
__global__ void gate_kernel(const float* __restrict__ x, const float* __restrict__ W,
                            const float* __restrict__ cp, float* __restrict__ probs, int S)
{
    int token = blockIdx.x; int b = token / S;
    int tid = threadIdx.x;
    __shared__ float xs[Hn];
    ((float4*)xs)[tid] = ((const float4*)(x + (long long)token*Hn))[tid];
    __syncthreads();
    int w = tid >> 5, lane = tid & 31;
    const float* We = W + (long long)w*2*Hn;
    float s = 0.f;
    for (int hh = lane; hh < Hn; hh += 32) s += xs[hh]*We[hh];
    for (int o=16;o;o>>=1) s += __shfl_down_sync(0xffffffffu,s,o);
    __shared__ float lg[En];
    if (lane==0) lg[w] = s + cp[b*En + w];
    __syncthreads();
    if (tid==0){
        float mx = lg[0];
        #pragma unroll
        for (int e=1;e<En;e++) mx = fmaxf(mx, lg[e]);
        float ev[En]; float sum = 0.f;
        #pragma unroll
        for (int e=0;e<En;e++){ ev[e]=expf(lg[e]-mx); sum+=ev[e]; }
        float inv = 1.f/sum;
        #pragma unroll
        for (int e=0;e<En;e++) probs[(long long)token*En+e]=ev[e]*inv;
    }
}

// ---------------- top-k (bitonic; value desc, index asc) ----------------
__global__ void topk_kernel(const float* __restrict__ probs, int S, int k, int kmax,
                            int* __restrict__ sel, int* __restrict__ pos)
{
    int z = blockIdx.x; int b = z / En, e = z - b*En;
    int tid = threadIdx.x;
    __shared__ float sv[1024];
    __shared__ int   si[1024];
    for (int i=tid;i<1024;i+=256){
        sv[i] = (i < S) ? probs[((long long)b*S + i)*En + e] : -1e30f;
        si[i] = i;
    }
    __syncthreads();
    for (int ksz=2; ksz<=1024; ksz<<=1){
        for (int j=ksz>>1; j>0; j>>=1){
            for (int i=tid; i<1024; i+=256){
                int ixj = i ^ j;
                if (ixj > i){
                    float v1=sv[i], v2=sv[ixj];
                    int i1=si[i], i2=si[ixj];
                    bool before = (v1 > v2) || (v1 == v2 && i1 < i2);
                    bool asc = ((i & ksz) == 0);
                    if (asc ? !before : before){
                        sv[i]=v2; sv[ixj]=v1; si[i]=i2; si[ixj]=i1;
                    }
                }
            }
            __syncthreads();
        }
    }
    for (int i=tid;i<S;i+=256) pos[(long long)z*S + i] = 0;
    __syncthreads();
    for (int j=tid;j<k;j+=256){
        int s = si[j];
        sel[(long long)z*kmax + j] = s;
        pos[(long long)z*S + s] = j + 1;
    }
}

// ---------------- combine ----------------
__global__ void combine_kernel(const float* __restrict__ down, const int* __restrict__ pos,
                               const float* __restrict__ resid, float* __restrict__ out,
                               int S, int kmax)
{
    int bs = blockIdx.x; int b = bs / S; int s = bs - b*S;
    int tid = threadIdx.x;
    int p[En]; int cnt = 0;
    #pragma unroll
    for (int e=0;e<En;e++){ p[e] = pos[((long long)(b*En+e))*S + s]; cnt += (p[e]>0); }
    float inv = 1.f / (cnt > 0 ? cnt : 1);
    float4 acc = {0,0,0,0};
    #pragma unroll
    for (int e=0;e<En;e++){
        if (p[e] > 0){
            const float4* dr = (const float4*)(down + ((long long)(b*En+e)*kmax + (p[e]-1))*Hn);
            float4 d = dr[tid];
            acc.x+=d.x; acc.y+=d.y; acc.z+=d.z; acc.w+=d.w;
        }
    }
    float4 r = ((const float4*)(resid + (long long)bs*Hn))[tid];
    float4 o = {r.x+acc.x*inv, r.y+acc.y*inv, r.z+acc.z*inv, r.w+acc.w*inv};
    ((float4*)(out + (long long)bs*Hn))[tid] = o;
}

// ---------------- host ----------------
extern "C" void kernel_launch(void* const* d_in, const int* in_sizes, int n_in,
                              void* d_out, int out_size)
{
    const float* query    = (const float*)d_in[0];
    const float* image    = (const float*)d_in[1];
    const float* textctx  = (const float*)d_in[2];
    const float* sa_w_in  = (const float*)d_in[3];
    const float* sa_b_in  = (const float*)d_in[4];
    const float* sa_w_out = (const float*)d_in[5];
    const float* sa_b_out = (const float*)d_in[6];
    const float* ca_w_in  = (const float*)d_in[7];
    const float* ca_b_in  = (const float*)d_in[8];
    const float* ca_w_out = (const float*)d_in[9];
    const float* ca_b_out = (const float*)d_in[10];
    const float* gate_img_w = (const float*)d_in[11];
    const float* gate_img_b = (const float*)d_in[12];
    const float* gate_txt_w = (const float*)d_in[13];
    const float* gate_txt_b = (const float*)d_in[14];
    const float* e_w1 = (const float*)d_in[15];
    const float* e_b1 = (const float*)d_in[16];
    const float* e_w2 = (const float*)d_in[17];
    const float* e_b2 = (const float*)d_in[18];
    const float* lnq_g = (const float*)d_in[19];
    const float* lnq_b = (const float*)d_in[20];
    const float* lnc_g = (const float*)d_in[21];
    const float* lnc_b = (const float*)d_in[22];
    const float* lnf_g = (const float*)d_in[23];
    const float* lnf_b = (const float*)d_in[24];

    __nv_bfloat16 *pWh,*pWl,*pImgH,*pImgL,*pLnH,*pLnL,*pQkvH,*pQkvL,*pAttnH,*pAttnL;
    __nv_bfloat16 *pQcH,*pQcL,*pKvH,*pKvL,*pPh,*pPl,*pHh,*pHl;
    float *pSc,*pQ1,*pQ2,*pPt,*pPi,*pCtxI,*pCtxT,*pCpI,*pCpT,*pDown;
    int *pSelT,*pSelI,*pPosT,*pPosI;
    cudaGetSymbolAddress((void**)&pWh,  g_w_hi);
    cudaGetSymbolAddress((void**)&pWl,  g_w_lo);
    cudaGetSymbolAddress((void**)&pImgH,g_img_hi);
    cudaGetSymbolAddress((void**)&pImgL,g_img_lo);
    cudaGetSymbolAddress((void**)&pLnH, g_ln_hi);
    cudaGetSymbolAddress((void**)&pLnL, g_ln_lo);
    cudaGetSymbolAddress((void**)&pQkvH,g_qkv_hi);
    cudaGetSymbolAddress((void**)&pQkvL,g_qkv_lo);
    cudaGetSymbolAddress((void**)&pAttnH,g_attn_hi);
    cudaGetSymbolAddress((void**)&pAttnL,g_attn_lo);
    cudaGetSymbolAddress((void**)&pQcH, g_qc_hi);
    cudaGetSymbolAddress((void**)&pQcL, g_qc_lo);
    cudaGetSymbolAddress((void**)&pKvH, g_kv_hi);
    cudaGetSymbolAddress((void**)&pKvL, g_kv_lo);
    cudaGetSymbolAddress((void**)&pPh,  g_p_hi);
    cudaGetSymbolAddress((void**)&pPl,  g_p_lo);
    cudaGetSymbolAddress((void**)&pHh,  g_h_hi);
    cudaGetSymbolAddress((void**)&pHl,  g_h_lo);
    cudaGetSymbolAddress((void**)&pSc,  g_scores);
    cudaGetSymbolAddress((void**)&pQ1,  g_q1);
    cudaGetSymbolAddress((void**)&pQ2,  g_q2);
    cudaGetSymbolAddress((void**)&pPt,  g_probs_txt);
    cudaGetSymbolAddress((void**)&pPi,  g_probs_img);
    cudaGetSymbolAddress((void**)&pCtxI,g_ctx_img);
    cudaGetSymbolAddress((void**)&pCtxT,g_ctx_txt);
    cudaGetSymbolAddress((void**)&pCpI, g_cp_img);
    cudaGetSymbolAddress((void**)&pCpT, g_cp_txt);
    cudaGetSymbolAddress((void**)&pDown,g_down);
    cudaGetSymbolAddress((void**)&pSelT,g_sel_txt);
    cudaGetSymbolAddress((void**)&pSelI,g_sel_img);
    cudaGetSymbolAddress((void**)&pPosT,g_pos_txt);
    cudaGetSymbolAddress((void**)&pPosI,g_pos_img);

    // opt-in smem for all mma_gemm instantiations
    cudaFuncSetAttribute(mma_gemm<true ,true ,false,false,false,false,true >, cudaFuncAttributeMaxDynamicSharedMemorySize, SMEMB);
    cudaFuncSetAttribute(mma_gemm<true ,false,false,false,false,true ,false>, cudaFuncAttributeMaxDynamicSharedMemorySize, SMEMB);
    cudaFuncSetAttribute(mma_gemm<false,false,false,false,false,false,true >, cudaFuncAttributeMaxDynamicSharedMemorySize, SMEMB);
    cudaFuncSetAttribute(mma_gemm<true ,true ,true ,false,false,true ,false>, cudaFuncAttributeMaxDynamicSharedMemorySize, SMEMB);
    cudaFuncSetAttribute(mma_gemm<true ,true ,false,true ,true ,false,true >, cudaFuncAttributeMaxDynamicSharedMemorySize, SMEMB);
    cudaFuncSetAttribute(mma_gemm<true ,true ,false,false,false,true ,false>, cudaFuncAttributeMaxDynamicSharedMemorySize, SMEMB);

    const int BT = Bn*Tn, BV = Bn*Vn;
    float* outQ = (float*)d_out;
    float* outI = outQ + (long long)BT*Hn;

    // 0) pre-split weights + image tokens
    split_kernel<<<(3145728/4+255)/256,256>>>(sa_w_in,  pWh+W_SAIN,  pWl+W_SAIN,  3145728/4);
    split_kernel<<<(1048576/4+255)/256,256>>>(sa_w_out, pWh+W_SAOUT, pWl+W_SAOUT, 1048576/4);
    split_kernel<<<(3145728/4+255)/256,256>>>(ca_w_in,  pWh+W_CAIN,  pWl+W_CAIN,  3145728/4);
    split_kernel<<<(1048576/4+255)/256,256>>>(ca_w_out, pWh+W_CAOUT, pWl+W_CAOUT, 1048576/4);
    split_kernel<<<(33554432/4+255)/256,256>>>(e_w1,    pWh+W_EW1,   pWl+W_EW1,   33554432/4);
    split_kernel<<<(33554432/4+255)/256,256>>>(e_w2,    pWh+W_EW2,   pWl+W_EW2,   33554432/4);
    split_kernel<<<(BV*Hn/4+255)/256,256>>>(image, pImgH, pImgL, BV*Hn/4);

    // 1) self-attention
    ln_split<<<BT,256>>>(query, lnq_g, lnq_b, pLnH, pLnL);
    mma_gemm<true,true,false,false,false,false,true><<<dim3(24,16,1),256,SMEMB>>>(
        pLnH,pLnL, pWh+W_SAIN,pWl+W_SAIN, sa_b_in, nullptr, nullptr, pQkvH,pQkvL,
        BT, 3*Hn, Hn, Hn, Hn, 3*Hn, 0,0,0,0,0,0,0, 1, 1.f, nullptr,0,0);
    mma_gemm<true,false,false,false,false,true,false><<<dim3(4,4,Bn*NHn),256,SMEMB>>>(
        pQkvH,pQkvL, pQkvH+Hn,pQkvL+Hn, nullptr,nullptr, pSc, nullptr,nullptr,
        Tn, Tn, HDn, 3*Hn, 3*Hn, Tn,
        (long long)Tn*3*Hn, HDn, (long long)Tn*3*Hn, HDn,
        (long long)NHn*Tn*Tn, (long long)Tn*Tn, 0, NHn, 0.125f, nullptr,0,0);
    softmax_split<<<Bn*NHn*Tn,128>>>(pSc, pPh, pPl, Tn);
    mma_gemm<false,false,false,false,false,false,true><<<dim3(1,4,Bn*NHn),256,SMEMB>>>(
        pPh,pPl, pQkvH+2*Hn,pQkvL+2*Hn, nullptr,nullptr, nullptr, pAttnH,pAttnL,
        Tn, HDn, Tn, Tn, 3*Hn, Hn,
        (long long)NHn*Tn*Tn, (long long)Tn*Tn, (long long)Tn*3*Hn, HDn,
        (long long)Tn*Hn, HDn, 0, NHn, 1.f, nullptr,0,0);
    mma_gemm<true,true,true,false,false,true,false><<<dim3(8,16,1),256,SMEMB>>>(
        pAttnH,pAttnL, pWh+W_SAOUT,pWl+W_SAOUT, sa_b_out, query, pQ1, nullptr,nullptr,
        BT, Hn, Hn, Hn, Hn, Hn, 0,0,0,0,0,0,0, 1, 1.f, nullptr,0,0);

    // 2) cross-attention
    ln_split<<<BT,256>>>(pQ1, lnc_g, lnc_b, pLnH, pLnL);
    mma_gemm<true,true,false,false,false,false,true><<<dim3(8,16,1),256,SMEMB>>>(
        pLnH,pLnL, pWh+W_CAIN,pWl+W_CAIN, ca_b_in, nullptr, nullptr, pQcH,pQcL,
        BT, Hn, Hn, Hn, Hn, Hn, 0,0,0,0,0,0,0, 1, 1.f, nullptr,0,0);
    mma_gemm<true,true,false,false,false,false,true><<<dim3(16,18,1),256,SMEMB>>>(
        pImgH,pImgL, pWh+W_CAIN+(long long)Hn*Hn,pWl+W_CAIN+(long long)Hn*Hn, ca_b_in+Hn, nullptr, nullptr, pKvH,pKvL,
        BV, 2*Hn, Hn, Hn, Hn, 2*Hn, 0,0,0,0,0,0,0, 1, 1.f, nullptr,0,0);
    mma_gemm<true,false,false,false,false,true,false><<<dim3(5,4,Bn*NHn),256,SMEMB>>>(
        pQcH,pQcL, pKvH,pKvL, nullptr,nullptr, pSc, nullptr,nullptr,
        Tn, Vn, HDn, Hn, 2*Hn, Vn,
        (long long)Tn*Hn, HDn, (long long)Vn*2*Hn, HDn,
        (long long)NHn*Tn*Vn, (long long)Tn*Vn, 0, NHn, 0.125f, nullptr,0,0);
    softmax_split<<<Bn*NHn*Tn,128>>>(pSc, pPh, pPl, Vn);
    mma_gemm<false,false,false,false,false,false,true><<<dim3(1,4,Bn*NHn),256,SMEMB>>>(
        pPh,pPl, pKvH+Hn,pKvL+Hn, nullptr,nullptr, nullptr, pAttnH,pAttnL,
        Tn, HDn, Vn, Vn, 2*Hn, Hn,
        (long long)NHn*Tn*Vn, (long long)Tn*Vn, (long long)Vn*2*Hn, HDn,
        (long long)Tn*Hn, HDn, 0, NHn, 1.f, nullptr,0,0);
    mma_gemm<true,true,true,false,false,true,false><<<dim3(8,16,1),256,SMEMB>>>(
        pAttnH,pAttnL, pWh+W_CAOUT,pWl+W_CAOUT, ca_b_out, pQ1, pQ2, nullptr,nullptr,
        BT, Hn, Hn, Hn, Hn, Hn, 0,0,0,0,0,0,0, 1, 1.f, nullptr,0,0);

    // 3) gating
    mean_rows<<<Bn,256>>>(image, pCtxI, Vn);
    mean_rows<<<Bn,256>>>(textctx, pCtxT, Ln);
    ctxpart_kernel<<<Bn*En,256>>>(pCtxT, gate_img_w, gate_img_b, pCpI);
    ctxpart_kernel<<<Bn*En,256>>>(pCtxI, gate_txt_w, gate_txt_b, pCpT);
    gate_kernel<<<BV,256>>>(image, gate_img_w, pCpI, pPi, Vn);
    gate_kernel<<<BT,256>>>(pQ2, gate_txt_w, pCpT, pPt, Tn);
    topk_kernel<<<Bn*En,256>>>(pPt, Tn, KTXT, KTXT, pSelT, pPosT);
    topk_kernel<<<Bn*En,256>>>(pPi, Vn, KIMG, KIMG, pSelI, pPosI);

    // 4) text MoE
    ln_split<<<BT,256>>>(pQ2, lnf_g, lnf_b, pLnH, pLnL);
    mma_gemm<true,true,false,true,true,false,true><<<dim3(32,1,Bn*En),256,SMEMB>>>(
        pLnH,pLnL, pWh+W_EW1,pWl+W_EW1, e_b1, nullptr, nullptr, pHh,pHl,
        KTXT, In, Hn, Hn, Hn, In,
        0,0, 0,(long long)In*Hn,
        (long long)En*KTXT*In, (long long)KTXT*In, (long long)In, En, 1.f, pSelT, KTXT, Tn);
    mma_gemm<true,true,false,false,false,true,false><<<dim3(8,1,Bn*En),256,SMEMB>>>(
        pHh,pHl, pWh+W_EW2,pWl+W_EW2, e_b2, nullptr, pDown, nullptr,nullptr,
        KTXT, Hn, In, In, In, Hn,
        (long long)En*KTXT*In, (long long)KTXT*In, 0,(long long)Hn*In,
        (long long)En*KTXT*Hn, (long long)KTXT*Hn, (long long)Hn, En, 1.f, nullptr,0,0);
    combine_kernel<<<BT,256>>>(pDown, pPosT, pQ2, outQ, Tn, KTXT);

    // 5) image MoE
    mma_gemm<true,true,false,true,true,false,true><<<dim3(32,1,Bn*En),256,SMEMB>>>(
        pImgH,pImgL, pWh+W_EW1,pWl+W_EW1, e_b1, nullptr, nullptr, pHh,pHl,
        KIMG, In, Hn, Hn, Hn, In,
        0,0, 0,(long long)In*Hn,
        (long long)En*KIMG*In, (long long)KIMG*In, (long long)In, En, 1.f, pSelI, KIMG, Vn);
    mma_gemm<true,true,false,false,false,true,false><<<dim3(8,1,Bn*En),256,SMEMB>>>(
        pHh,pHl, pWh+W_EW2,pWl+W_EW2, e_b2, nullptr, pDown, nullptr,nullptr,
        KIMG, Hn, In, In, In, Hn,
        (long long)En*KIMG*In, (long long)KIMG*In, 0,(long long)Hn*In,
        (long long)En*KIMG*Hn, (long long)KIMG*Hn, (long long)Hn, En, 1.f, nullptr,0,0);
    combine_kernel<<<BV,256>>>(pDown, pPosI, image, outI, Vn, KIMG);
}

// round 10
// speedup vs baseline: 3.4742x; 1.0169x over previous
#include <cuda_runtime.h>
#include <cuda_bf16.h>
#include <cstdint>
#include <math.h>

// ---------------- problem constants ----------------
#define Bn 4
#define Tn 512
#define Vn 576
#define Ln 256
#define Hn 1024
#define NHn 16
#define HDn 64
#define In 4096
#define En 8
#define KTXT 80
#define KIMG 90
#define BKT (Bn*KTXT)   // 320 rows per expert (text)
#define BKI (Bn*KIMG)   // 360 rows per expert (image)

// weight offsets inside the big split-weight buffers (elements)
static const long long W_SAIN  = 0;
static const long long W_SAOUT = 3145728;
static const long long W_CAIN  = 4194304;
static const long long W_CAOUT = 7340032;
static const long long W_EW1   = 8388608;
static const long long W_EW2   = 41943040;
#define W_TOTAL 75497472

// ---------------- device scratch ----------------
__device__ __nv_bfloat16 g_w_hi[W_TOTAL];
__device__ __nv_bfloat16 g_w_lo[W_TOTAL];
__device__ __nv_bfloat16 g_img_hi[Bn*Vn*Hn];
__device__ __nv_bfloat16 g_img_lo[Bn*Vn*Hn];
__device__ __nv_bfloat16 g_ln_hi[Bn*Tn*Hn];
__device__ __nv_bfloat16 g_ln_lo[Bn*Tn*Hn];
__device__ __nv_bfloat16 g_qkv_hi[Bn*Tn*3*Hn];
__device__ __nv_bfloat16 g_qkv_lo[Bn*Tn*3*Hn];
__device__ __nv_bfloat16 g_attn_hi[Bn*Tn*Hn];
__device__ __nv_bfloat16 g_attn_lo[Bn*Tn*Hn];
__device__ __nv_bfloat16 g_qc_hi[Bn*Tn*Hn];
__device__ __nv_bfloat16 g_qc_lo[Bn*Tn*Hn];
__device__ __nv_bfloat16 g_kv_hi[Bn*Vn*2*Hn];
__device__ __nv_bfloat16 g_kv_lo[Bn*Vn*2*Hn];
__device__ __nv_bfloat16 g_p_hi[Bn*NHn*Tn*Vn];
__device__ __nv_bfloat16 g_p_lo[Bn*NHn*Tn*Vn];
__device__ __nv_bfloat16 g_h_hi[En*BKI*In];
__device__ __nv_bfloat16 g_h_lo[En*BKI*In];

__device__ float g_scores[Bn*NHn*Tn*Vn];
__device__ float g_q1   [Bn*Tn*Hn];
__device__ float g_q2   [Bn*Tn*Hn];
__device__ float g_probs_txt[Bn*Tn*En];
__device__ float g_probs_img[Bn*Vn*En];
__device__ float g_ctx_img[Bn*Hn];
__device__ float g_ctx_txt[Bn*Hn];
__device__ float g_cp_img[Bn*En];
__device__ float g_cp_txt[Bn*En];
__device__ int   g_sel_txt[En*BKT];
__device__ int   g_sel_img[En*BKI];
__device__ int   g_pos_txt[Bn*En*Tn];
__device__ int   g_pos_img[Bn*En*Vn];
__device__ float g_down [En*BKI*Hn];

// ---------------- helpers ----------------
__device__ __forceinline__ uint32_t smem_u32(const void* p){
    uint32_t a;
    asm("{ .reg .u64 t; cvta.to.shared.u64 t, %1; cvt.u32.u64 %0, t; }" : "=r"(a) : "l"(p));
    return a;
}
__device__ __forceinline__ float gelu_tanh(float x){
    float x3 = x*x*x;
    return 0.5f*x*(1.0f+tanhf(0.7978845608028654f*(x+0.044715f*x3)));
}
__device__ __forceinline__ void ldm_x4(uint32_t& r0,uint32_t& r1,uint32_t& r2,uint32_t& r3, uint32_t addr){
    asm volatile("ldmatrix.sync.aligned.m8n8.x4.shared.b16 {%0,%1,%2,%3}, [%4];"
      : "=r"(r0),"=r"(r1),"=r"(r2),"=r"(r3) : "r"(addr));
}
__device__ __forceinline__ void ldm_x2(uint32_t& r0,uint32_t& r1, uint32_t addr){
    asm volatile("ldmatrix.sync.aligned.m8n8.x2.shared.b16 {%0,%1}, [%2];"
      : "=r"(r0),"=r"(r1) : "r"(addr));
}
__device__ __forceinline__ void mma_bf16(float* c, const uint32_t* a, const uint32_t* b){
    asm volatile("mma.sync.aligned.m16n8k16.row.col.f32.bf16.bf16.f32 "
      "{%0,%1,%2,%3}, {%4,%5,%6,%7}, {%8,%9}, {%0,%1,%2,%3};"
      : "+f"(c[0]),"+f"(c[1]),"+f"(c[2]),"+f"(c[3])
      : "r"(a[0]),"r"(a[1]),"r"(a[2]),"r"(a[3]), "r"(b[0]),"r"(b[1]));
}
__device__ __forceinline__ void cp16(uint32_t d, const void* s, bool ok){
    asm volatile("cp.async.cg.shared.global [%0], [%1], 16, %2;"
      :: "r"(d), "l"(s), "r"(ok ? 16 : 0) : "memory");
}
#define CP_COMMIT() asm volatile("cp.async.commit_group;" ::: "memory")
#define CP_WAIT1() asm volatile("cp.async.wait_group 1;" ::: "memory")
#define CP_WAIT0() asm volatile("cp.async.wait_group 0;" ::: "memory")

__device__ __forceinline__ void split2(float x, float y, uint32_t& hv, uint32_t& lv){
    __nv_bfloat162 h = __floats2bfloat162_rn(x, y);
    __nv_bfloat162 l = __floats2bfloat162_rn(x - __bfloat162float(h.x), y - __bfloat162float(h.y));
    hv = *(uint32_t*)&h; lv = *(uint32_t*)&l;
}

// =========================================================================
// HMMA bf16x3 GEMM from pre-split hi/lo bf16 inputs.
// C[M,N] = alpha * A @ B^T (+bias)(gelu)(+res); outputs fp32 and/or hi/lo bf16.
// Tile 128x128x32, 256 threads (8 warps 2x4). cp.async double-buffered (TRB).
// GATHER mode: A rows come from gidx (absolute row indices).
// =========================================================================
#define LDS 40           // smem row stride in bf16
#define BUFB 10240       // one 128xLDS bf16 buffer in bytes
#define STAGEB 40960     // 4 buffers per stage
#define SMEMB 81920      // 2 stages

template<bool TRB, bool BIAS, bool RES, bool GELU, bool GATHER, bool OUTF32, bool OUTSPLIT>
__global__ void __launch_bounds__(256, 2)
mma_gemm(const __nv_bfloat16* __restrict__ Ahi, const __nv_bfloat16* __restrict__ Alo,
         const __nv_bfloat16* __restrict__ Bhi, const __nv_bfloat16* __restrict__ Blo,
         const float* __restrict__ bias, const float* __restrict__ res,
         float* __restrict__ C, __nv_bfloat16* __restrict__ Chi, __nv_bfloat16* __restrict__ Clo,
         int M, int N, int K, int lda, int ldb, int ldc,
         long long aOffB, long long aOffH, long long bOffB, long long bOffH,
         long long cOffB, long long cOffH, long long biasOffH,
         int nh, float alpha,
         const int* __restrict__ gidx, int gStride)
{
    extern __shared__ char dynsmem[];
    uint32_t sbase = smem_u32(dynsmem);

    int tid = threadIdx.x;
    int wid = tid >> 5, lane = tid & 31;
    int wm = wid & 1, wn = wid >> 1;
    int z = blockIdx.z;
    int b = z / nh, h = z - b*nh;
    const __nv_bfloat16* AhB = GATHER ? Ahi : (Ahi + (long long)b*aOffB + (long long)h*aOffH);
    const __nv_bfloat16* AlB = GATHER ? Alo : (Alo + (long long)b*aOffB + (long long)h*aOffH);
    const __nv_bfloat16* BhB = Bhi + (long long)b*bOffB + (long long)h*bOffH;
    const __nv_bfloat16* BlB = Blo + (long long)b*bOffB + (long long)h*bOffH;
    const float* biasb = BIAS ? (bias + (long long)h*biasOffH) : nullptr;
    const float* resb  = RES  ? (res  + (long long)b*cOffB + (long long)h*cOffH) : nullptr;
    int row0 = blockIdx.y * 128, col0 = blockIdx.x * 128;
    int NC = K >> 5;

    float acc[4][4][4] = {};

    if (TRB) {
        // ---- async double-buffered producer ----
        auto load_chunk = [&](int c, int s){
            int k0 = c << 5;
            uint32_t st = sbase + s*STAGEB;
            #pragma unroll
            for (int i = 0; i < 2; i++) {
                int seg = tid + i*256;
                int r = seg >> 2, ks = (seg & 3) << 3;
                // A
                {
                    int grow = row0 + r;
                    bool ok = grow < M;
                    long long arow;
                    if (GATHER) arow = ok ? (long long)gidx[(long long)z*gStride + grow] : 0;
                    else        arow = ok ? grow : 0;
                    uint32_t doff = (uint32_t)(r*LDS + ks)*2u;
                    cp16(st + doff,        AhB + arow*lda + k0 + ks, ok);
                    cp16(st + BUFB + doff, AlB + arow*lda + k0 + ks, ok);
                }
                // B
                {
                    int gcol = col0 + r;
                    bool ok = gcol < N;
                    long long brow = ok ? gcol : 0;
                    uint32_t doff = (uint32_t)(r*LDS + ks)*2u;
                    cp16(st + 2*BUFB + doff, BhB + brow*ldb + k0 + ks, ok);
                    cp16(st + 3*BUFB + doff, BlB + brow*ldb + k0 + ks, ok);
                }
            }
        };
        load_chunk(0, 0); CP_COMMIT();
        for (int c = 0; c < NC; c++) {
            int s = c & 1;
            if (c + 1 < NC) { load_chunk(c+1, 1-s); CP_COMMIT(); CP_WAIT1(); }
            else            { CP_WAIT0(); }
            __syncthreads();
            uint32_t aHiS = sbase + s*STAGEB;
            uint32_t aLoS = aHiS + BUFB;
            uint32_t bHiS = aHiS + 2*BUFB;
            uint32_t bLoS = aHiS + 3*BUFB;
            #pragma unroll
            for (int kh = 0; kh < 2; kh++) {
                uint32_t bh[4][2], bl[4][2];
                #pragma unroll
                for (int ni = 0; ni < 4; ni++) {
                    uint32_t off = ((uint32_t)((wn*32 + ni*8 + (lane & 7))*LDS + kh*16 + ((lane >> 3) & 1)*8)) * 2u;
                    ldm_x2(bh[ni][0], bh[ni][1], bHiS + off);
                    ldm_x2(bl[ni][0], bl[ni][1], bLoS + off);
                }
                #pragma unroll
                for (int mi = 0; mi < 4; mi++) {
                    uint32_t off = ((uint32_t)((wm*64 + mi*16 + (lane & 15))*LDS + kh*16 + (lane >> 4)*8)) * 2u;
                    uint32_t ah[4], al[4];
                    ldm_x4(ah[0], ah[1], ah[2], ah[3], aHiS + off);
                    ldm_x4(al[0], al[1], al[2], al[3], aLoS + off);
                    #pragma unroll
                    for (int ni = 0; ni < 4; ni++) {
                        mma_bf16(acc[mi][ni], ah, bh[ni]);
                        mma_bf16(acc[mi][ni], ah, bl[ni]);
                        mma_bf16(acc[mi][ni], al, bh[ni]);
                    }
                }
            }
            __syncthreads();
        }
    } else {
        // ---- NTB (B stored [K,N]) : single-stage synchronous ----
        uint32_t aHiS = sbase, aLoS = sbase + BUFB, bHiS = sbase + 2*BUFB, bLoS = sbase + 3*BUFB;
        __nv_bfloat16* sBh = (__nv_bfloat16*)(dynsmem + 2*BUFB);
        __nv_bfloat16* sBl = (__nv_bfloat16*)(dynsmem + 3*BUFB);
        for (int c = 0; c < NC; c++) {
            int k0 = c << 5;
            #pragma unroll
            for (int i = 0; i < 2; i++) {
                int seg = tid + i*256;
                int r = seg >> 2, ks = (seg & 3) << 3;
                int grow = row0 + r;
                uint4 hv = make_uint4(0,0,0,0), lv = make_uint4(0,0,0,0);
                if (grow < M) {
                    hv = *(const uint4*)(AhB + (long long)grow*lda + k0 + ks);
                    lv = *(const uint4*)(AlB + (long long)grow*lda + k0 + ks);
                }
                *(uint4*)(dynsmem + (r*LDS + ks)*2) = hv;
                *(uint4*)(dynsmem + BUFB + (r*LDS + ks)*2) = lv;
            }
            #pragma unroll
            for (int i = 0; i < 16; i++) {
                int idx = tid + i*256;
                int n = idx & 127, kk = idx >> 7;
                __nv_bfloat16 hv = __float2bfloat16(0.f), lv = __float2bfloat16(0.f);
                int gcol = col0 + n;
                if (gcol < N) {
                    hv = BhB[(long long)(k0 + kk)*ldb + gcol];
                    lv = BlB[(long long)(k0 + kk)*ldb + gcol];
                }
                sBh[n*LDS + kk] = hv;
                sBl[n*LDS + kk] = lv;
            }
            __syncthreads();
            #pragma unroll
            for (int kh = 0; kh < 2; kh++) {
                uint32_t bh[4][2], bl[4][2];
                #pragma unroll
                for (int ni = 0; ni < 4; ni++) {
                    uint32_t off = ((uint32_t)((wn*32 + ni*8 + (lane & 7))*LDS + kh*16 + ((lane >> 3) & 1)*8)) * 2u;
                    ldm_x2(bh[ni][0], bh[ni][1], bHiS + off);
                    ldm_x2(bl[ni][0], bl[ni][1], bLoS + off);
                }
                #pragma unroll
                for (int mi = 0; mi < 4; mi++) {
                    uint32_t off = ((uint32_t)((wm*64 + mi*16 + (lane & 15))*LDS + kh*16 + (lane >> 4)*8)) * 2u;
                    uint32_t ah[4], al[4];
                    ldm_x4(ah[0], ah[1], ah[2], ah[3], aHiS + off);
                    ldm_x4(al[0], al[1], al[2], al[3], aLoS + off);
                    #pragma unroll
                    for (int ni = 0; ni < 4; ni++) {
                        mma_bf16(acc[mi][ni], ah, bh[ni]);
                        mma_bf16(acc[mi][ni], ah, bl[ni]);
                        mma_bf16(acc[mi][ni], al, bh[ni]);
                    }
                }
            }
            __syncthreads();
        }
    }

    // ---- epilogue ----
    float* Cb = OUTF32 ? (C + (long long)b*cOffB + (long long)h*cOffH) : nullptr;
    __nv_bfloat16* ChB = OUTSPLIT ? (Chi + (long long)b*cOffB + (long long)h*cOffH) : nullptr;
    __nv_bfloat16* ClB = OUTSPLIT ? (Clo + (long long)b*cOffB + (long long)h*cOffH) : nullptr;
    #pragma unroll
    for (int mi = 0; mi < 4; mi++) {
        #pragma unroll
        for (int ni = 0; ni < 4; ni++) {
            int rg = row0 + wm*64 + mi*16 + (lane >> 2);
            int cg = col0 + wn*32 + ni*8 + (lane & 3)*2;
            if (cg >= N) continue;
            #pragma unroll
            for (int half = 0; half < 2; half++) {
                int row = rg + half*8;
                if (row < M) {
                    float v0 = acc[mi][ni][half*2+0]*alpha;
                    float v1 = acc[mi][ni][half*2+1]*alpha;
                    if (BIAS) { v0 += biasb[cg]; v1 += biasb[cg+1]; }
                    if (GELU) { v0 = gelu_tanh(v0); v1 = gelu_tanh(v1); }
                    if (RES)  { v0 += resb[(long long)row*ldc + cg]; v1 += resb[(long long)row*ldc + cg + 1]; }
                    if (OUTF32) *(float2*)&Cb[(long long)row*ldc + cg] = make_float2(v0, v1);
                    if (OUTSPLIT) {
                        uint32_t hv, lv;
                        split2(v0, v1, hv, lv);
                        *(uint32_t*)&ChB[(long long)row*ldc + cg] = hv;
                        *(uint32_t*)&ClB[(long long)row*ldc + cg] = lv;
                    }
                }
            }
        }
    }
}

// ---------------- fp32 -> bf16 hi/lo splitter ----------------
__global__ void split_kernel(const float* __restrict__ x, __nv_bfloat16* __restrict__ hi,
                             __nv_bfloat16* __restrict__ lo, int n4)
{
    int i = blockIdx.x*blockDim.x + threadIdx.x;
    if (i >= n4) return;
    float4 v = ((const float4*)x)[i];
    uint32_t h0, l0, h1, l1;
    split2(v.x, v.y, h0, l0);
    split2(v.z, v.w, h1, l1);
    ((uint2*)hi)[i] = make_uint2(h0, h1);
    ((uint2*)lo)[i] = make_uint2(l0, l1);
}

// ---------------- LayerNorm -> hi/lo bf16 ----------------
__global__ void ln_split(const float* __restrict__ x, const float* __restrict__ g,
                         const float* __restrict__ bta,
                         __nv_bfloat16* __restrict__ yhi, __nv_bfloat16* __restrict__ ylo)
{
    long long row = blockIdx.x;
    int tid = threadIdx.x;
    const float4* xr = (const float4*)(x + row*Hn);
    float4 xv = xr[tid];
    float s = xv.x+xv.y+xv.z+xv.w;
    float q = xv.x*xv.x+xv.y*xv.y+xv.z*xv.z+xv.w*xv.w;
    for (int o=16;o;o>>=1){ s += __shfl_down_sync(0xffffffffu,s,o); q += __shfl_down_sync(0xffffffffu,q,o); }
    __shared__ float ss[8], qq[8];
    __shared__ float mv[2];
    int lane = tid&31, wd = tid>>5;
    if (lane==0){ ss[wd]=s; qq[wd]=q; }
    __syncthreads();
    if (tid==0){
        float a=0,c=0;
        #pragma unroll
        for(int i=0;i<8;i++){a+=ss[i]; c+=qq[i];}
        float mean = a*(1.f/Hn);
        float var  = c*(1.f/Hn) - mean*mean;
        mv[0]=mean; mv[1]=rsqrtf(var+1e-5f);
    }
    __syncthreads();
    float mean=mv[0], inv=mv[1];
    float4 gv = ((const float4*)g)[tid];
    float4 bv = ((const float4*)bta)[tid];
    float o0=(xv.x-mean)*inv*gv.x+bv.x;
    float o1=(xv.y-mean)*inv*gv.y+bv.y;
    float o2=(xv.z-mean)*inv*gv.z+bv.z;
    float o3=(xv.w-mean)*inv*gv.w+bv.w;
    uint32_t h0,l0,h1,l1;
    split2(o0,o1,h0,l0);
    split2(o2,o3,h1,l1);
    ((uint2*)(yhi + row*Hn))[tid] = make_uint2(h0,h1);
    ((uint2*)(ylo + row*Hn))[tid] = make_uint2(l0,l1);
}

// ---------------- row softmax fp32 -> hi/lo bf16 ----------------
__global__ void softmax_split(const float* __restrict__ p,
                              __nv_bfloat16* __restrict__ phi, __nv_bfloat16* __restrict__ plo,
                              int cols)
{
    long long row = blockIdx.x;
    const float* r = p + row*cols;
    int tid = threadIdx.x;
    float tmp[5];
    float mx = -1e30f;
    int cnt = 0;
    for (int i=tid;i<cols;i+=128){ float v = r[i]; tmp[cnt++] = v; mx = fmaxf(mx, v); }
    for (int o=16;o;o>>=1) mx = fmaxf(mx, __shfl_xor_sync(0xffffffffu,mx,o));
    __shared__ float sm[4], sq[4];
    if ((tid&31)==0) sm[tid>>5]=mx;
    __syncthreads();
    mx = fmaxf(fmaxf(sm[0],sm[1]),fmaxf(sm[2],sm[3]));
    float sum = 0.f;
    for (int j=0;j<cnt;j++){ float e=__expf(tmp[j]-mx); tmp[j]=e; sum+=e; }
    for (int o=16;o;o>>=1) sum += __shfl_xor_sync(0xffffffffu,sum,o);
    if ((tid&31)==0) sq[tid>>5]=sum;
    __syncthreads();
    sum = sq[0]+sq[1]+sq[2]+sq[3];
    float inv = 1.f/sum;
    cnt = 0;
    for (int i=tid;i<cols;i+=128){
        float v = tmp[cnt++]*inv;
        __nv_bfloat16 hv = __float2bfloat16(v);
        __nv_bfloat16 lv = __float2bfloat16(v - __bfloat162float(hv));
        phi[row*cols + i] = hv;
        plo[row*cols + i] = lv;
    }
}

// ---------------- mean over rows ----------------
__global__ void mean_rows(const float* __restrict__ x, float* __restrict__ out, int rows)
{
    int b = blockIdx.x, tid = threadIdx.x;
    const float4* xb = (const float4*)(x + (long long)b*rows*Hn);
    float4 acc = {0,0,0,0};
    for (int v=0; v<rows; v++){
        float4 t = xb[v*(Hn/4) + tid];
        acc.x+=t.x; acc.y+=t.y; acc.z+=t.z; acc.w+=t.w;
    }
    float inv = 1.f/rows;
    float4 o = {acc.x*inv, acc.y*inv, acc.z*inv, acc.w*inv};
    ((float4*)(out + (long long)b*Hn))[tid] = o;
}

// ---------------- ctxpart ----------------
__global__ void ctxpart_kernel(const float* __restrict__ ctx, const float* __restrict__ W,
                               const float* __restrict__ bias, float* __restrict__ out)
{
    int z = blockIdx.x; int b = z >> 3, e = z & 7;
    int tid = threadIdx.x;
    const float4* c4 = (const float4*)(ctx + (long long)b*Hn);
    const float4* w4 = (const float4*)(W + (long long)e*2*Hn + Hn);
    float4 c = c4[tid], w = w4[tid];
    float s = c.x*w.x + c.y*w.y + c.z*w.z + c.w*w.w;
    for (int o=16;o;o>>=1) s += __shfl_down_sync(0xffffffffu,s,o);
    __shared__ float sh[8];
    if ((tid&31)==0) sh[tid>>5]=s;
    __syncthreads();
    if (tid==0){ float t=0; for(int i=0;i<8;i++) t+=sh[i]; out[z] = t + bias[e]; }
}

// ---------------- gating ----------------
__global__ void gate_kernel(const float* __restrict__ x, const float* __restrict__ W,
                            const float* __restrict__ cp, float* __restrict__ probs, int S)
{
    int token = blockIdx.x; int b = token / S;
    int tid = threadIdx.x;
    __shared__ float xs[Hn];
    ((float4*)xs)[tid] = ((const float4*)(x + (long long)token*Hn))[tid];
    __syncthreads();
    int w = tid >> 5, lane = tid & 31;
    const float* We = W + (long long)w*2*Hn;
    float s = 0.f;
    for (int hh = lane; hh < Hn; hh += 32) s += xs[hh]*We[hh];
    for (int o=16;o;o>>=1) s += __shfl_down_sync(0xffffffffu,s,o);
    __shared__ float lg[En];
    if (lane==0) lg[w] = s + cp[b*En + w];
    __syncthreads();
    if (tid==0){
        float mx = lg[0];
        #pragma unroll
        for (int e=1;e<En;e++) mx = fmaxf(mx, lg[e]);
        float ev[En]; float sum = 0.f;
        #pragma unroll
        for (int e=0;e<En;e++){ ev[e]=expf(lg[e]-mx); sum+=ev[e]; }
        float inv = 1.f/sum;
        #pragma unroll
        for (int e=0;e<En;e++) probs[(long long)token*En+e]=ev[e]*inv;
    }
}

// ---------------- top-k (bitonic; value desc, index asc) ----------------
// sel[e][b*k + j] = absolute row (b*S + s); pos[(b*En+e)*S + s] = b*k + j + 1
__global__ void topk_kernel(const float* __restrict__ probs, int S, int k,
                            int* __restrict__ sel, int* __restrict__ pos)
{
    int z = blockIdx.x; int b = z / En, e = z - b*En;
    int tid = threadIdx.x;
    __shared__ float sv[1024];
    __shared__ int   si[1024];
    for (int i=tid;i<1024;i+=256){
        sv[i] = (i < S) ? probs[((long long)b*S + i)*En + e] : -1e30f;
        si[i] = i;
    }
    __syncthreads();
    for (int ksz=2; ksz<=1024; ksz<<=1){
        for (int j=ksz>>1; j>0; j>>=1){
            for (int i=tid; i<1024; i+=256){
                int ixj = i ^ j;
                if (ixj > i){
                    float v1=sv[i], v2=sv[ixj];
                    int i1=si[i], i2=si[ixj];
                    bool before = (v1 > v2) || (v1 == v2 && i1 < i2);
                    bool asc = ((i & ksz) == 0);
                    if (asc ? !before : before){
                        sv[i]=v2; sv[ixj]=v1; si[i]=i2; si[ixj]=i1;
                    }
                }
            }
            __syncthreads();
        }
    }
    for (int i=tid;i<S;i+=256) pos[(long long)z*S + i] = 0;
    __syncthreads();
    for (int j=tid;j<k;j+=256){
        int s = si[j];
        sel[(long long)e*(Bn*k) + b*k + j] = b*S + s;
        pos[(long long)z*S + s] = b*k + j + 1;
    }
}

// ---------------- combine: down laid out [En][BK][Hn] ----------------
__global__ void combine_kernel(const float* __restrict__ down, const int* __restrict__ pos,
                               const float* __restrict__ resid, float* __restrict__ out,
                               int S, int BK)
{
    int bs = blockIdx.x; int b = bs / S; int s = bs - b*S;
    int tid = threadIdx.x;
    int p[En]; int cnt = 0;
    #pragma unroll
    for (int e=0;e<En;e++){ p[e] = pos[((long long)(b*En+e))*S + s]; cnt += (p[e]>0); }
    float inv = 1.f / (cnt > 0 ? cnt : 1);
    float4 acc = {0,0,0,0};
    #pragma unroll
    for (int e=0;e<En;e++){
        if (p[e] > 0){
            const float4* dr = (const float4*)(down + ((long long)e*BK + (p[e]-1))*Hn);
            float4 d = dr[tid];
            acc.x+=d.x; acc.y+=d.y; acc.z+=d.z; acc.w+=d.w;
        }
    }
    float4 r = ((const float4*)(resid + (long long)bs*Hn))[tid];
    float4 o = {r.x+acc.x*inv, r.y+acc.y*inv, r.z+acc.z*inv, r.w+acc.w*inv};
    ((float4*)(out + (long long)bs*Hn))[tid] = o;
}

// ---------------- host ----------------
extern "C" void kernel_launch(void* const* d_in, const int* in_sizes, int n_in,
                              void* d_out, int out_size)
{
    const float* query    = (const float*)d_in[0];
    const float* image    = (const float*)d_in[1];
    const float* textctx  = (const float*)d_in[2];
    const float* sa_w_in  = (const float*)d_in[3];
    const float* sa_b_in  = (const float*)d_in[4];
    const float* sa_w_out = (const float*)d_in[5];
    const float* sa_b_out = (const float*)d_in[6];
    const float* ca_w_in  = (const float*)d_in[7];
    const float* ca_b_in  = (const float*)d_in[8];
    const float* ca_w_out = (const float*)d_in[9];
    const float* ca_b_out = (const float*)d_in[10];
    const float* gate_img_w = (const float*)d_in[11];
    const float* gate_img_b = (const float*)d_in[12];
    const float* gate_txt_w = (const float*)d_in[13];
    const float* gate_txt_b = (const float*)d_in[14];
    const float* e_w1 = (const float*)d_in[15];
    const float* e_b1 = (const float*)d_in[16];
    const float* e_w2 = (const float*)d_in[17];
    const float* e_b2 = (const float*)d_in[18];
    const float* lnq_g = (const float*)d_in[19];
    const float* lnq_b = (const float*)d_in[20];
    const float* lnc_g = (const float*)d_in[21];
    const float* lnc_b = (const float*)d_in[22];
    const float* lnf_g = (const float*)d_in[23];
    const float* lnf_b = (const float*)d_in[24];

    __nv_bfloat16 *pWh,*pWl,*pImgH,*pImgL,*pLnH,*pLnL,*pQkvH,*pQkvL,*pAttnH,*pAttnL;
    __nv_bfloat16 *pQcH,*pQcL,*pKvH,*pKvL,*pPh,*pPl,*pHh,*pHl;
    float *pSc,*pQ1,*pQ2,*pPt,*pPi,*pCtxI,*pCtxT,*pCpI,*pCpT,*pDown;
    int *pSelT,*pSelI,*pPosT,*pPosI;
    cudaGetSymbolAddress((void**)&pWh,  g_w_hi);
    cudaGetSymbolAddress((void**)&pWl,  g_w_lo);
    cudaGetSymbolAddress((void**)&pImgH,g_img_hi);
    cudaGetSymbolAddress((void**)&pImgL,g_img_lo);
    cudaGetSymbolAddress((void**)&pLnH, g_ln_hi);
    cudaGetSymbolAddress((void**)&pLnL, g_ln_lo);
    cudaGetSymbolAddress((void**)&pQkvH,g_qkv_hi);
    cudaGetSymbolAddress((void**)&pQkvL,g_qkv_lo);
    cudaGetSymbolAddress((void**)&pAttnH,g_attn_hi);
    cudaGetSymbolAddress((void**)&pAttnL,g_attn_lo);
    cudaGetSymbolAddress((void**)&pQcH, g_qc_hi);
    cudaGetSymbolAddress((void**)&pQcL, g_qc_lo);
    cudaGetSymbolAddress((void**)&pKvH, g_kv_hi);
    cudaGetSymbolAddress((void**)&pKvL, g_kv_lo);
    cudaGetSymbolAddress((void**)&pPh,  g_p_hi);
    cudaGetSymbolAddress((void**)&pPl,  g_p_lo);
    cudaGetSymbolAddress((void**)&pHh,  g_h_hi);
    cudaGetSymbolAddress((void**)&pHl,  g_h_lo);
    cudaGetSymbolAddress((void**)&pSc,  g_scores);
    cudaGetSymbolAddress((void**)&pQ1,  g_q1);
    cudaGetSymbolAddress((void**)&pQ2,  g_q2);
    cudaGetSymbolAddress((void**)&pPt,  g_probs_txt);
    cudaGetSymbolAddress((void**)&pPi,  g_probs_img);
    cudaGetSymbolAddress((void**)&pCtxI,g_ctx_img);
    cudaGetSymbolAddress((void**)&pCtxT,g_ctx_txt);
    cudaGetSymbolAddress((void**)&pCpI, g_cp_img);
    cudaGetSymbolAddress((void**)&pCpT, g_cp_txt);
    cudaGetSymbolAddress((void**)&pDown,g_down);
    cudaGetSymbolAddress((void**)&pSelT,g_sel_txt);
    cudaGetSymbolAddress((void**)&pSelI,g_sel_img);
    cudaGetSymbolAddress((void**)&pPosT,g_pos_txt);
    cudaGetSymbolAddress((void**)&pPosI,g_pos_img);

    // opt-in smem for all mma_gemm instantiations
    cudaFuncSetAttribute(mma_gemm<true ,true ,false,false,false,false,true >, cudaFuncAttributeMaxDynamicSharedMemorySize, SMEMB);
    cudaFuncSetAttribute(mma_gemm<true ,false,false,false,false,true ,false>, cudaFuncAttributeMaxDynamicSharedMemorySize, SMEMB);
    cudaFuncSetAttribute(mma_gemm<false,false,false,false,false,false,true >, cudaFuncAttributeMaxDynamicSharedMemorySize, SMEMB);
    cudaFuncSetAttribute(mma_gemm<true ,true ,true ,false,false,true ,false>, cudaFuncAttributeMaxDynamicSharedMemorySize, SMEMB);
    cudaFuncSetAttribute(mma_gemm<true ,true ,false,true ,true ,false,true >, cudaFuncAttributeMaxDynamicSharedMemorySize, SMEMB);
    cudaFuncSetAttribute(mma_gemm<true ,true ,false,false,false,true ,false>, cudaFuncAttributeMaxDynamicSharedMemorySize, SMEMB);

    const int BT = Bn*Tn, BV = Bn*Vn;
    float* outQ = (float*)d_out;
    float* outI = outQ + (long long)BT*Hn;

    // 0) pre-split weights + image tokens
    split_kernel<<<(3145728/4+255)/256,256>>>(sa_w_in,  pWh+W_SAIN,  pWl+W_SAIN,  3145728/4);
    split_kernel<<<(1048576/4+255)/256,256>>>(sa_w_out, pWh+W_SAOUT, pWl+W_SAOUT, 1048576/4);
    split_kernel<<<(3145728/4+255)/256,256>>>(ca_w_in,  pWh+W_CAIN,  pWl+W_CAIN,  3145728/4);
    split_kernel<<<(1048576/4+255)/256,256>>>(ca_w_out, pWh+W_CAOUT, pWl+W_CAOUT, 1048576/4);
    split_kernel<<<(33554432/4+255)/256,256>>>(e_w1,    pWh+W_EW1,   pWl+W_EW1,   33554432/4);
    split_kernel<<<(33554432/4+255)/256,256>>>(e_w2,    pWh+W_EW2,   pWl+W_EW2,   33554432/4);
    split_kernel<<<(BV*Hn/4+255)/256,256>>>(image, pImgH, pImgL, BV*Hn/4);

    // 1) self-attention
    ln_split<<<BT,256>>>(query, lnq_g, lnq_b, pLnH, pLnL);
    mma_gemm<true,true,false,false,false,false,true><<<dim3(24,16,1),256,SMEMB>>>(
        pLnH,pLnL, pWh+W_SAIN,pWl+W_SAIN, sa_b_in, nullptr, nullptr, pQkvH,pQkvL,
        BT, 3*Hn, Hn, Hn, Hn, 3*Hn, 0,0,0,0,0,0,0, 1, 1.f, nullptr,0);
    mma_gemm<true,false,false,false,false,true,false><<<dim3(4,4,Bn*NHn),256,SMEMB>>>(
        pQkvH,pQkvL, pQkvH+Hn,pQkvL+Hn, nullptr,nullptr, pSc, nullptr,nullptr,
        Tn, Tn, HDn, 3*Hn, 3*Hn, Tn,
        (long long)Tn*3*Hn, HDn, (long long)Tn*3*Hn, HDn,
        (long long)NHn*Tn*Tn, (long long)Tn*Tn, 0, NHn, 0.125f, nullptr,0);
    softmax_split<<<Bn*NHn*Tn,128>>>(pSc, pPh, pPl, Tn);
    mma_gemm<false,false,false,false,false,false,true><<<dim3(1,4,Bn*NHn),256,SMEMB>>>(
        pPh,pPl, pQkvH+2*Hn,pQkvL+2*Hn, nullptr,nullptr, nullptr, pAttnH,pAttnL,
        Tn, HDn, Tn, Tn, 3*Hn, Hn,
        (long long)NHn*Tn*Tn, (long long)Tn*Tn, (long long)Tn*3*Hn, HDn,
        (long long)Tn*Hn, HDn, 0, NHn, 1.f, nullptr,0);
    mma_gemm<true,true,true,false,false,true,false><<<dim3(8,16,1),256,SMEMB>>>(
        pAttnH,pAttnL, pWh+W_SAOUT,pWl+W_SAOUT, sa_b_out, query, pQ1, nullptr,nullptr,
        BT, Hn, Hn, Hn, Hn, Hn, 0,0,0,0,0,0,0, 1, 1.f, nullptr,0);

    // 2) cross-attention
    ln_split<<<BT,256>>>(pQ1, lnc_g, lnc_b, pLnH, pLnL);
    mma_gemm<true,true,false,false,false,false,true><<<dim3(8,16,1),256,SMEMB>>>(
        pLnH,pLnL, pWh+W_CAIN,pWl+W_CAIN, ca_b_in, nullptr, nullptr, pQcH,pQcL,
        BT, Hn, Hn, Hn, Hn, Hn, 0,0,0,0,0,0,0, 1, 1.f, nullptr,0);
    mma_gemm<true,true,false,false,false,false,true><<<dim3(16,18,1),256,SMEMB>>>(
        pImgH,pImgL, pWh+W_CAIN+(long long)Hn*Hn,pWl+W_CAIN+(long long)Hn*Hn, ca_b_in+Hn, nullptr, nullptr, pKvH,pKvL,
        BV, 2*Hn, Hn, Hn, Hn, 2*Hn, 0,0,0,0,0,0,0, 1, 1.f, nullptr,0);
    mma_gemm<true,false,false,false,false,true,false><<<dim3(5,4,Bn*NHn),256,SMEMB>>>(
        pQcH,pQcL, pKvH,pKvL, nullptr,nullptr, pSc, nullptr,nullptr,
        Tn, Vn, HDn, Hn, 2*Hn, Vn,
        (long long)Tn*Hn, HDn, (long long)Vn*2*Hn, HDn,
        (long long)NHn*Tn*Vn, (long long)Tn*Vn, 0, NHn, 0.125f, nullptr,0);
    softmax_split<<<Bn*NHn*Tn,128>>>(pSc, pPh, pPl, Vn);
    mma_gemm<false,false,false,false,false,false,true><<<dim3(1,4,Bn*NHn),256,SMEMB>>>(
        pPh,pPl, pKvH+Hn,pKvL+Hn, nullptr,nullptr, nullptr, pAttnH,pAttnL,
        Tn, HDn, Vn, Vn, 2*Hn, Hn,
        (long long)NHn*Tn*Vn, (long long)Tn*Vn, (long long)Vn*2*Hn, HDn,
        (long long)Tn*Hn, HDn, 0, NHn, 1.f, nullptr,0);
    mma_gemm<true,true,true,false,false,true,false><<<dim3(8,16,1),256,SMEMB>>>(
        pAttnH,pAttnL, pWh+W_CAOUT,pWl+W_CAOUT, ca_b_out, pQ1, pQ2, nullptr,nullptr,
        BT, Hn, Hn, Hn, Hn, Hn, 0,0,0,0,0,0,0, 1, 1.f, nullptr,0);

    // 3) gating
    mean_rows<<<Bn,256>>>(image, pCtxI, Vn);
    mean_rows<<<Bn,256>>>(textctx, pCtxT, Ln);
    ctxpart_kernel<<<Bn*En,256>>>(pCtxT, gate_img_w, gate_img_b, pCpI);
    ctxpart_kernel<<<Bn*En,256>>>(pCtxI, gate_txt_w, gate_txt_b, pCpT);
    gate_kernel<<<BV,256>>>(image, gate_img_w, pCpI, pPi, Vn);
    gate_kernel<<<BT,256>>>(pQ2, gate_txt_w, pCpT, pPt, Tn);
    topk_kernel<<<Bn*En,256>>>(pPt, Tn, KTXT, pSelT, pPosT);
    topk_kernel<<<Bn*En,256>>>(pPi, Vn, KIMG, pSelI, pPosI);

    // 4) text MoE: per-expert batched M = Bn*KTXT = 320
    ln_split<<<BT,256>>>(pQ2, lnf_g, lnf_b, pLnH, pLnL);
    mma_gemm<true,true,false,true,true,false,true><<<dim3(32,3,En),256,SMEMB>>>(
        pLnH,pLnL, pWh+W_EW1,pWl+W_EW1, e_b1, nullptr, nullptr, pHh,pHl,
        BKT, In, Hn, Hn, Hn, In,
        0, 0, 0, (long long)In*Hn,
        0, (long long)BKT*In, (long long)In, En, 1.f, pSelT, BKT);
    mma_gemm<true,true,false,false,false,true,false><<<dim3(8,3,En),256,SMEMB>>>(
        pHh,pHl, pWh+W_EW2,pWl+W_EW2, e_b2, nullptr, pDown, nullptr,nullptr,
        BKT, Hn, In, In, In, Hn,
        0, (long long)BKT*In, 0, (long long)Hn*In,
        0, (long long)BKT*Hn, (long long)Hn, En, 1.f, nullptr,0);
    combine_kernel<<<BT,256>>>(pDown, pPosT, pQ2, outQ, Tn, BKT);

    // 5) image MoE: per-expert batched M = Bn*KIMG = 360
    mma_gemm<true,true,false,true,true,false,true><<<dim3(32,3,En),256,SMEMB>>>(
        pImgH,pImgL, pWh+W_EW1,pWl+W_EW1, e_b1, nullptr, nullptr, pHh,pHl,
        BKI, In, Hn, Hn, Hn, In,
        0, 0, 0, (long long)In*Hn,
        0, (long long)BKI*In, (long long)In, En, 1.f, pSelI, BKI);
    mma_gemm<true,true,false,false,false,true,false><<<dim3(8,3,En),256,SMEMB>>>(
        pHh,pHl, pWh+W_EW2,pWl+W_EW2, e_b2, nullptr, pDown, nullptr,nullptr,
        BKI, Hn, In, In, In, Hn,
        0, (long long)BKI*In, 0, (long long)Hn*In,
        0, (long long)BKI*Hn, (long long)Hn, En, 1.f, nullptr,0);
    combine_kernel<<<BV,256>>>(pDown, pPosI, image, outI, Vn, BKI);
}

// round 11
// speedup vs baseline: 3.5556x; 1.0234x over previous
#include <cuda_runtime.h>
#include <cuda_bf16.h>
#include <cstdint>
#include <math.h>

// ---------------- problem constants ----------------
#define Bn 4
#define Tn 512
#define Vn 576
#define Ln 256
#define Hn 1024
#define NHn 16
#define HDn 64
#define In 4096
#define En 8
#define KTXT 80
#define KIMG 90
#define BKT (Bn*KTXT)   // 320 rows per expert (text)
#define BKI (Bn*KIMG)   // 360 rows per expert (image)

// weight offsets inside the big split-weight buffers (elements)
static const long long W_SAIN  = 0;
static const long long W_SAOUT = 3145728;
static const long long W_CAIN  = 4194304;
static const long long W_CAOUT = 7340032;
static const long long W_EW1   = 8388608;
static const long long W_EW2   = 41943040;
#define W_TOTAL 75497472

// ---------------- device scratch ----------------
__device__ __nv_bfloat16 g_w_hi[W_TOTAL];
__device__ __nv_bfloat16 g_w_lo[W_TOTAL];
__device__ __nv_bfloat16 g_img_hi[Bn*Vn*Hn];
__device__ __nv_bfloat16 g_img_lo[Bn*Vn*Hn];
__device__ __nv_bfloat16 g_ln_hi[Bn*Tn*Hn];
__device__ __nv_bfloat16 g_ln_lo[Bn*Tn*Hn];
__device__ __nv_bfloat16 g_qkv_hi[Bn*Tn*3*Hn];
__device__ __nv_bfloat16 g_qkv_lo[Bn*Tn*3*Hn];
__device__ __nv_bfloat16 g_attn_hi[Bn*Tn*Hn];
__device__ __nv_bfloat16 g_attn_lo[Bn*Tn*Hn];
__device__ __nv_bfloat16 g_qc_hi[Bn*Tn*Hn];
__device__ __nv_bfloat16 g_qc_lo[Bn*Tn*Hn];
__device__ __nv_bfloat16 g_kv_hi[Bn*Vn*2*Hn];
__device__ __nv_bfloat16 g_kv_lo[Bn*Vn*2*Hn];
__device__ __nv_bfloat16 g_p_hi[Bn*NHn*Tn*Vn];
__device__ __nv_bfloat16 g_p_lo[Bn*NHn*Tn*Vn];
__device__ __nv_bfloat16 g_h_hi[En*BKI*In];
__device__ __nv_bfloat16 g_h_lo[En*BKI*In];

__device__ float g_scores[Bn*NHn*Tn*Vn];
__device__ float g_q1   [Bn*Tn*Hn];
__device__ float g_q2   [Bn*Tn*Hn];
__device__ float g_probs_txt[Bn*Tn*En];
__device__ float g_probs_img[Bn*Vn*En];
__device__ float g_ctx_img[Bn*Hn];
__device__ float g_ctx_txt[Bn*Hn];
__device__ float g_cp_img[Bn*En];
__device__ float g_cp_txt[Bn*En];
__device__ int   g_sel_txt[En*BKT];
__device__ int   g_sel_img[En*BKI];
__device__ int   g_pos_txt[Bn*En*Tn];
__device__ int   g_pos_img[Bn*En*Vn];
__device__ float g_down [En*BKI*Hn];

// ---------------- helpers ----------------
__device__ __forceinline__ uint32_t smem_u32(const void* p){
    uint32_t a;
    asm("{ .reg .u64 t; cvta.to.shared.u64 t, %1; cvt.u32.u64 %0, t; }" : "=r"(a) : "l"(p));
    return a;
}
__device__ __forceinline__ float gelu_tanh(float x){
    float x3 = x*x*x;
    return 0.5f*x*(1.0f+tanhf(0.7978845608028654f*(x+0.044715f*x3)));
}
__device__ __forceinline__ void ldm_x4(uint32_t& r0,uint32_t& r1,uint32_t& r2,uint32_t& r3, uint32_t addr){
    asm volatile("ldmatrix.sync.aligned.m8n8.x4.shared.b16 {%0,%1,%2,%3}, [%4];"
      : "=r"(r0),"=r"(r1),"=r"(r2),"=r"(r3) : "r"(addr));
}
__device__ __forceinline__ void ldm_x2(uint32_t& r0,uint32_t& r1, uint32_t addr){
    asm volatile("ldmatrix.sync.aligned.m8n8.x2.shared.b16 {%0,%1}, [%2];"
      : "=r"(r0),"=r"(r1) : "r"(addr));
}
__device__ __forceinline__ void mma_bf16(float* c, const uint32_t* a, const uint32_t* b){
    asm volatile("mma.sync.aligned.m16n8k16.row.col.f32.bf16.bf16.f32 "
      "{%0,%1,%2,%3}, {%4,%5,%6,%7}, {%8,%9}, {%0,%1,%2,%3};"
      : "+f"(c[0]),"+f"(c[1]),"+f"(c[2]),"+f"(c[3])
      : "r"(a[0]),"r"(a[1]),"r"(a[2]),"r"(a[3]), "r"(b[0]),"r"(b[1]));
}
__device__ __forceinline__ void cp16(uint32_t d, const void* s, bool ok){
    asm volatile("cp.async.cg.shared.global [%0], [%1], 16, %2;"
      :: "r"(d), "l"(s), "r"(ok ? 16 : 0) : "memory");
}
#define CP_COMMIT() asm volatile("cp.async.commit_group;" ::: "memory")
#define CP_WAIT1() asm volatile("cp.async.wait_group 1;" ::: "memory")
#define CP_WAIT0() asm volatile("cp.async.wait_group 0;" ::: "memory")

__device__ __forceinline__ void split2(float x, float y, uint32_t& hv, uint32_t& lv){
    __nv_bfloat162 h = __floats2bfloat162_rn(x, y);
    __nv_bfloat162 l = __floats2bfloat162_rn(x - __bfloat162float(h.x), y - __bfloat162float(h.y));
    hv = *(uint32_t*)&h; lv = *(uint32_t*)&l;
}

// =========================================================================
// HMMA bf16x3 GEMM from pre-split hi/lo bf16 inputs.
// C[M,N] = alpha * A @ B^T (+bias)(gelu)(+res); outputs fp32 and/or hi/lo bf16.
// WARPM=2: 128x128 tile (2x4 warps). WARPM=4: 256x64 tile (4x2 warps).
// TRB: B[N,K] row-major, cp.async double-buffered.
// NTB: B[K,N] row-major, vectorized LDG + STS transpose, synchronous.
// =========================================================================
#define LDS 40           // smem row stride in bf16

template<int WARPM, bool TRB, bool BIAS, bool RES, bool GELU, bool GATHER, bool OUTF32, bool OUTSPLIT>
__global__ void __launch_bounds__(256, 2)
mma_gemm(const __nv_bfloat16* __restrict__ Ahi, const __nv_bfloat16* __restrict__ Alo,
         const __nv_bfloat16* __restrict__ Bhi, const __nv_bfloat16* __restrict__ Blo,
         const float* __restrict__ bias, const float* __restrict__ res,
         float* __restrict__ C, __nv_bfloat16* __restrict__ Chi, __nv_bfloat16* __restrict__ Clo,
         int M, int N, int K, int lda, int ldb, int ldc,
         long long aOffB, long long aOffH, long long bOffB, long long bOffH,
         long long cOffB, long long cOffH, long long biasOffH,
         int nh, float alpha,
         const int* __restrict__ gidx, int gStride)
{
    constexpr int TM = WARPM*64;          // tile rows
    constexpr int TN = (8/WARPM)*32;      // tile cols
    constexpr int ABUF = TM*LDS*2;        // bytes of one A buffer
    constexpr int BBUF = TN*LDS*2;        // bytes of one B buffer
    constexpr int STG = 2*ABUF + 2*BBUF;  // one stage

    extern __shared__ char dynsmem[];
    uint32_t sbase = smem_u32(dynsmem);

    int tid = threadIdx.x;
    int wid = tid >> 5, lane = tid & 31;
    int wm = wid % WARPM, wn = wid / WARPM;
    int z = blockIdx.z;
    int b = z / nh, h = z - b*nh;
    const __nv_bfloat16* AhB = GATHER ? Ahi : (Ahi + (long long)b*aOffB + (long long)h*aOffH);
    const __nv_bfloat16* AlB = GATHER ? Alo : (Alo + (long long)b*aOffB + (long long)h*aOffH);
    const __nv_bfloat16* BhB = Bhi + (long long)b*bOffB + (long long)h*bOffH;
    const __nv_bfloat16* BlB = Blo + (long long)b*bOffB + (long long)h*bOffH;
    const float* biasb = BIAS ? (bias + (long long)h*biasOffH) : nullptr;
    const float* resb  = RES  ? (res  + (long long)b*cOffB + (long long)h*cOffH) : nullptr;
    int row0 = blockIdx.y * TM, col0 = blockIdx.x * TN;
    int NC = K >> 5;

    float acc[4][4][4] = {};

    if (TRB) {
        // ---- async double-buffered producer ----
        auto load_chunk = [&](int c, int s){
            int k0 = c << 5;
            uint32_t st = sbase + s*STG;
            #pragma unroll
            for (int i = 0; i < TM/64; i++) {
                int seg = tid + i*256;
                int r = seg >> 2, ks = (seg & 3) << 3;
                int grow = row0 + r;
                bool ok = grow < M;
                long long arow;
                if (GATHER) arow = ok ? (long long)gidx[(long long)z*gStride + grow] : 0;
                else        arow = ok ? grow : 0;
                uint32_t doff = (uint32_t)(r*LDS + ks)*2u;
                cp16(st + doff,        AhB + arow*lda + k0 + ks, ok);
                cp16(st + ABUF + doff, AlB + arow*lda + k0 + ks, ok);
            }
            #pragma unroll
            for (int i = 0; i < TN/64; i++) {
                int seg = tid + i*256;
                int r = seg >> 2, ks = (seg & 3) << 3;
                int gcol = col0 + r;
                bool ok = gcol < N;
                long long brow = ok ? gcol : 0;
                uint32_t doff = (uint32_t)(r*LDS + ks)*2u;
                cp16(st + 2*ABUF + doff,        BhB + brow*ldb + k0 + ks, ok);
                cp16(st + 2*ABUF + BBUF + doff, BlB + brow*ldb + k0 + ks, ok);
            }
        };
        load_chunk(0, 0); CP_COMMIT();
        for (int c = 0; c < NC; c++) {
            int s = c & 1;
            if (c + 1 < NC) { load_chunk(c+1, 1-s); CP_COMMIT(); CP_WAIT1(); }
            else            { CP_WAIT0(); }
            __syncthreads();
            uint32_t st = sbase + s*STG;
            uint32_t aHiS = st, aLoS = st + ABUF;
            uint32_t bHiS = st + 2*ABUF, bLoS = st + 2*ABUF + BBUF;
            #pragma unroll
            for (int kh = 0; kh < 2; kh++) {
                uint32_t bh[4][2], bl[4][2];
                #pragma unroll
                for (int ni = 0; ni < 4; ni++) {
                    uint32_t off = ((uint32_t)((wn*32 + ni*8 + (lane & 7))*LDS + kh*16 + ((lane >> 3) & 1)*8)) * 2u;
                    ldm_x2(bh[ni][0], bh[ni][1], bHiS + off);
                    ldm_x2(bl[ni][0], bl[ni][1], bLoS + off);
                }
                #pragma unroll
                for (int mi = 0; mi < 4; mi++) {
                    uint32_t off = ((uint32_t)((wm*64 + mi*16 + (lane & 15))*LDS + kh*16 + (lane >> 4)*8)) * 2u;
                    uint32_t ah[4], al[4];
                    ldm_x4(ah[0], ah[1], ah[2], ah[3], aHiS + off);
                    ldm_x4(al[0], al[1], al[2], al[3], aLoS + off);
                    #pragma unroll
                    for (int ni = 0; ni < 4; ni++) {
                        mma_bf16(acc[mi][ni], ah, bh[ni]);
                        mma_bf16(acc[mi][ni], ah, bl[ni]);
                        mma_bf16(acc[mi][ni], al, bh[ni]);
                    }
                }
            }
            __syncthreads();
        }
    } else {
        // ---- NTB (B stored [K,N]) : synchronous, vectorized loads ----
        uint32_t aHiS = sbase, aLoS = sbase + ABUF;
        uint32_t bHiS = sbase + 2*ABUF, bLoS = sbase + 2*ABUF + BBUF;
        __nv_bfloat16* sBh = (__nv_bfloat16*)(dynsmem + 2*ABUF);
        __nv_bfloat16* sBl = (__nv_bfloat16*)(dynsmem + 2*ABUF + BBUF);
        for (int c = 0; c < NC; c++) {
            int k0 = c << 5;
            // A tile: vector loads, row-major smem
            #pragma unroll
            for (int i = 0; i < TM/64; i++) {
                int seg = tid + i*256;
                int r = seg >> 2, ks = (seg & 3) << 3;
                int grow = row0 + r;
                uint4 hv = make_uint4(0,0,0,0), lv = make_uint4(0,0,0,0);
                if (grow < M) {
                    hv = *(const uint4*)(AhB + (long long)grow*lda + k0 + ks);
                    lv = *(const uint4*)(AlB + (long long)grow*lda + k0 + ks);
                }
                *(uint4*)(dynsmem + (r*LDS + ks)*2) = hv;
                *(uint4*)(dynsmem + ABUF + (r*LDS + ks)*2) = lv;
            }
            // B tile: vector LDG along n, scalar STS transpose into [n][k]
            #pragma unroll
            for (int i = 0; i < TN/64; i++) {
                int idx = tid + i*256;
                int kk = idx / (TN/8);
                int n0 = (idx % (TN/8)) * 8;
                int gc = col0 + n0;
                __nv_bfloat16 hv8[8], lv8[8];
                if (gc < N) {
                    *(uint4*)hv8 = *(const uint4*)(BhB + (long long)(k0 + kk)*ldb + gc);
                    *(uint4*)lv8 = *(const uint4*)(BlB + (long long)(k0 + kk)*ldb + gc);
                } else {
                    #pragma unroll
                    for (int j = 0; j < 8; j++){ hv8[j] = __float2bfloat16(0.f); lv8[j] = __float2bfloat16(0.f); }
                }
                #pragma unroll
                for (int j = 0; j < 8; j++) {
                    sBh[(n0 + j)*LDS + kk] = hv8[j];
                    sBl[(n0 + j)*LDS + kk] = lv8[j];
                }
            }
            __syncthreads();
            #pragma unroll
            for (int kh = 0; kh < 2; kh++) {
                uint32_t bh[4][2], bl[4][2];
                #pragma unroll
                for (int ni = 0; ni < 4; ni++) {
                    uint32_t off = ((uint32_t)((wn*32 + ni*8 + (lane & 7))*LDS + kh*16 + ((lane >> 3) & 1)*8)) * 2u;
                    ldm_x2(bh[ni][0], bh[ni][1], bHiS + off);
                    ldm_x2(bl[ni][0], bl[ni][1], bLoS + off);
                }
                #pragma unroll
                for (int mi = 0; mi < 4; mi++) {
                    uint32_t off = ((uint32_t)((wm*64 + mi*16 + (lane & 15))*LDS + kh*16 + (lane >> 4)*8)) * 2u;
                    uint32_t ah[4], al[4];
                    ldm_x4(ah[0], ah[1], ah[2], ah[3], aHiS + off);
                    ldm_x4(al[0], al[1], al[2], al[3], aLoS + off);
                    #pragma unroll
                    for (int ni = 0; ni < 4; ni++) {
                        mma_bf16(acc[mi][ni], ah, bh[ni]);
                        mma_bf16(acc[mi][ni], ah, bl[ni]);
                        mma_bf16(acc[mi][ni], al, bh[ni]);
                    }
                }
            }
            __syncthreads();
        }
    }

    // ---- epilogue ----
    float* Cb = OUTF32 ? (C + (long long)b*cOffB + (long long)h*cOffH) : nullptr;
    __nv_bfloat16* ChB = OUTSPLIT ? (Chi + (long long)b*cOffB + (long long)h*cOffH) : nullptr;
    __nv_bfloat16* ClB = OUTSPLIT ? (Clo + (long long)b*cOffB + (long long)h*cOffH) : nullptr;
    #pragma unroll
    for (int mi = 0; mi < 4; mi++) {
        #pragma unroll
        for (int ni = 0; ni < 4; ni++) {
            int rg = row0 + wm*64 + mi*16 + (lane >> 2);
            int cg = col0 + wn*32 + ni*8 + (lane & 3)*2;
            if (cg >= N) continue;
            #pragma unroll
            for (int half = 0; half < 2; half++) {
                int row = rg + half*8;
                if (row < M) {
                    float v0 = acc[mi][ni][half*2+0]*alpha;
                    float v1 = acc[mi][ni][half*2+1]*alpha;
                    if (BIAS) { v0 += biasb[cg]; v1 += biasb[cg+1]; }
                    if (GELU) { v0 = gelu_tanh(v0); v1 = gelu_tanh(v1); }
                    if (RES)  { v0 += resb[(long long)row*ldc + cg]; v1 += resb[(long long)row*ldc + cg + 1]; }
                    if (OUTF32) *(float2*)&Cb[(long long)row*ldc + cg] = make_float2(v0, v1);
                    if (OUTSPLIT) {
                        uint32_t hv, lv;
                        split2(v0, v1, hv, lv);
                        *(uint32_t*)&ChB[(long long)row*ldc + cg] = hv;
                        *(uint32_t*)&ClB[(long long)row*ldc + cg] = lv;
                    }
                }
            }
        }
    }
}

// ---------------- merged fp32 -> bf16 hi/lo splitter (all 7 regions) ----------------
struct SplitDesc { const float* src; __nv_bfloat16* hi; __nv_bfloat16* lo; int n4; };
struct SplitArgs { SplitDesc d[7]; };

__global__ void split_all(SplitArgs a)
{
    int i = blockIdx.x*256 + threadIdx.x;
    #pragma unroll
    for (int s = 0; s < 7; s++) {
        if (i < a.d[s].n4) {
            float4 v = ((const float4*)a.d[s].src)[i];
            uint32_t h0, l0, h1, l1;
            split2(v.x, v.y, h0, l0);
            split2(v.z, v.w, h1, l1);
            ((uint2*)a.d[s].hi)[i] = make_uint2(h0, h1);
            ((uint2*)a.d[s].lo)[i] = make_uint2(l0, l1);
            return;
        }
        i -= a.d[s].n4;
    }
}

// ---------------- LayerNorm -> hi/lo bf16 ----------------
__global__ void ln_split(const float* __restrict__ x, const float* __restrict__ g,
                         const float* __restrict__ bta,
                         __nv_bfloat16* __restrict__ yhi, __nv_bfloat16* __restrict__ ylo)
{
    long long row = blockIdx.x;
    int tid = threadIdx.x;
    const float4* xr = (const float4*)(x + row*Hn);
    float4 xv = xr[tid];
    float s = xv.x+xv.y+xv.z+xv.w;
    float q = xv.x*xv.x+xv.y*xv.y+xv.z*xv.z+xv.w*xv.w;
    for (int o=16;o;o>>=1){ s += __shfl_down_sync(0xffffffffu,s,o); q += __shfl_down_sync(0xffffffffu,q,o); }
    __shared__ float ss[8], qq[8];
    __shared__ float mv[2];
    int lane = tid&31, wd = tid>>5;
    if (lane==0){ ss[wd]=s; qq[wd]=q; }
    __syncthreads();
    if (tid==0){
        float a=0,c=0;
        #pragma unroll
        for(int i=0;i<8;i++){a+=ss[i]; c+=qq[i];}
        float mean = a*(1.f/Hn);
        float var  = c*(1.f/Hn) - mean*mean;
        mv[0]=mean; mv[1]=rsqrtf(var+1e-5f);
    }
    __syncthreads();
    float mean=mv[0], inv=mv[1];
    float4 gv = ((const float4*)g)[tid];
    float4 bv = ((const float4*)bta)[tid];
    float o0=(xv.x-mean)*inv*gv.x+bv.x;
    float o1=(xv.y-mean)*inv*gv.y+bv.y;
    float o2=(xv.z-mean)*inv*gv.z+bv.z;
    float o3=(xv.w-mean)*inv*gv.w+bv.w;
    uint32_t h0,l0,h1,l1;
    split2(o0,o1,h0,l0);
    split2(o2,o3,h1,l1);
    ((uint2*)(yhi + row*Hn))[tid] = make_uint2(h0,h1);
    ((uint2*)(ylo + row*Hn))[tid] = make_uint2(l0,l1);
}

// ---------------- row softmax fp32 -> hi/lo bf16 ----------------
__global__ void softmax_split(const float* __restrict__ p,
                              __nv_bfloat16* __restrict__ phi, __nv_bfloat16* __restrict__ plo,
                              int cols)
{
    long long row = blockIdx.x;
    const float* r = p + row*cols;
    int tid = threadIdx.x;
    float tmp[5];
    float mx = -1e30f;
    int cnt = 0;
    for (int i=tid;i<cols;i+=128){ float v = r[i]; tmp[cnt++] = v; mx = fmaxf(mx, v); }
    for (int o=16;o;o>>=1) mx = fmaxf(mx, __shfl_xor_sync(0xffffffffu,mx,o));
    __shared__ float sm[4], sq[4];
    if ((tid&31)==0) sm[tid>>5]=mx;
    __syncthreads();
    mx = fmaxf(fmaxf(sm[0],sm[1]),fmaxf(sm[2],sm[3]));
    float sum = 0.f;
    for (int j=0;j<cnt;j++){ float e=__expf(tmp[j]-mx); tmp[j]=e; sum+=e; }
    for (int o=16;o;o>>=1) sum += __shfl_xor_sync(0xffffffffu,sum,o);
    if ((tid&31)==0) sq[tid>>5]=sum;
    __syncthreads();
    sum = sq[0]+sq[1]+sq[2]+sq[3];
    float inv = 1.f/sum;
    cnt = 0;
    for (int i=tid;i<cols;i+=128){
        float v = tmp[cnt++]*inv;
        __nv_bfloat16 hv = __float2bfloat16(v);
        __nv_bfloat16 lv = __float2bfloat16(v - __bfloat162float(hv));
        phi[row*cols + i] = hv;
        plo[row*cols + i] = lv;
    }
}

// ---------------- mean over rows ----------------
__global__ void mean_rows(const float* __restrict__ x, float* __restrict__ out, int rows)
{
    int b = blockIdx.x, tid = threadIdx.x;
    const float4* xb = (const float4*)(x + (long long)b*rows*Hn);
    float4 acc = {0,0,0,0};
    for (int v=0; v<rows; v++){
        float4 t = xb[v*(Hn/4) + tid];
        acc.x+=t.x; acc.y+=t.y; acc.z+=t.z; acc.w+=t.w;
    }
    float inv = 1.f/rows;
    float4 o = {acc.x*inv, acc.y*inv, acc.z*inv, acc.w*inv};
    ((float4*)(out + (long long)b*Hn))[tid] = o;
}

// ---------------- ctxpart ----------------
__global__ void ctxpart_kernel(const float* __restrict__ ctx, const float* __restrict__ W,
                               const float* __restrict__ bias, float* __restrict__ out)
{
    int z = blockIdx.x; int b = z >> 3, e = z & 7;
    int tid = threadIdx.x;
    const float4* c4 = (const float4*)(ctx + (long long)b*Hn);
    const float4* w4 = (const float4*)(W + (long long)e*2*Hn + Hn);
    float4 c = c4[tid], w = w4[tid];
    float s = c.x*w.x + c.y*w.y + c.z*w.z + c.w*w.w;
    for (int o=16;o;o>>=1) s += __shfl_down_sync(0xffffffffu,s,o);
    __shared__ float sh[8];
    if ((tid&31)==0) sh[tid>>5]=s;
    __syncthreads();
    if (tid==0){ float t=0; for(int i=0;i<8;i++) t+=sh[i]; out[z] = t + bias[e]; }
}

// ---------------- gating ----------------
__global__ void gate_kernel(const float* __restrict__ x, const float* __restrict__ W,
                            const float* __restrict__ cp, float* __restrict__ probs, int S)
{
    int token = blockIdx.x; int b = token / S;
    int tid = threadIdx.x;
    __shared__ float xs[Hn];
    ((float4*)xs)[tid] = ((const float4*)(x + (long long)token*Hn))[tid];
    __syncthreads();
    int w = tid >> 5, lane = tid & 31;
    const float* We = W + (long long)w*2*Hn;
    float s = 0.f;
    for (int hh = lane; hh < Hn; hh += 32) s += xs[hh]*We[hh];
    for (int o=16;o;o>>=1) s += __shfl_down_sync(0xffffffffu,s,o);
    __shared__ float lg[En];
    if (lane==0) lg[w] = s + cp[b*En + w];
    __syncthreads();
    if (tid==0){
        float mx = lg[0];
        #pragma unroll
        for (int e=1;e<En;e++) mx = fmaxf(mx, lg[e]);
        float ev[En]; float sum = 0.f;
        #pragma unroll
        for (int e=0;e<En;e++){ ev[e]=expf(lg[e]-mx); sum+=ev[e]; }
        float inv = 1.f/sum;
        #pragma unroll
        for (int e=0;e<En;e++) probs[(long long)token*En+e]=ev[e]*inv;
    }
}

// ---------------- top-k (bitonic; value desc, index asc) ----------------
// sel[e][b*k + j] = absolute row (b*S + s); pos[(b*En+e)*S + s] = b*k + j + 1
__global__ void topk_kernel(const float* __restrict__ probs, int S, int k,
                            int* __restrict__ sel, int* __restrict__ pos)
{
    int z = blockIdx.x; int b = z / En, e = z - b*En;
    int tid = threadIdx.x;
    __shared__ float sv[1024];
    __shared__ int   si[1024];
    for (int i=tid;i<1024;i+=256){
        sv[i] = (i < S) ? probs[((long long)b*S + i)*En + e] : -1e30f;
        si[i] = i;
    }
    __syncthreads();
    for (int ksz=2; ksz<=1024; ksz<<=1){
        for (int j=ksz>>1; j>0; j>>=1){
            for (int i=tid; i<1024; i+=256){
                int ixj = i ^ j;
                if (ixj > i){
                    float v1=sv[i], v2=sv[ixj];
                    int i1=si[i], i2=si[ixj];
                    bool before = (v1 > v2) || (v1 == v2 && i1 < i2);
                    bool asc = ((i & ksz) == 0);
                    if (asc ? !before : before){
                        sv[i]=v2; sv[ixj]=v1; si[i]=i2; si[ixj]=i1;
                    }
                }
            }
            __syncthreads();
        }
    }
    for (int i=tid;i<S;i+=256) pos[(long long)z*S + i] = 0;
    __syncthreads();
    for (int j=tid;j<k;j+=256){
        int s = si[j];
        sel[(long long)e*(Bn*k) + b*k + j] = b*S + s;
        pos[(long long)z*S + s] = b*k + j + 1;
    }
}

// ---------------- combine: down laid out [En][BK][Hn] ----------------
__global__ void combine_kernel(const float* __restrict__ down, const int* __restrict__ pos,
                               const float* __restrict__ resid, float* __restrict__ out,
                               int S, int BK)
{
    int bs = blockIdx.x; int b = bs / S; int s = bs - b*S;
    int tid = threadIdx.x;
    int p[En]; int cnt = 0;
    #pragma unroll
    for (int e=0;e<En;e++){ p[e] = pos[((long long)(b*En+e))*S + s]; cnt += (p[e]>0); }
    float inv = 1.f / (cnt > 0 ? cnt : 1);
    float4 acc = {0,0,0,0};
    #pragma unroll
    for (int e=0;e<En;e++){
        if (p[e] > 0){
            const float4* dr = (const float4*)(down + ((long long)e*BK + (p[e]-1))*Hn);
            float4 d = dr[tid];
            acc.x+=d.x; acc.y+=d.y; acc.z+=d.z; acc.w+=d.w;
        }
    }
    float4 r = ((const float4*)(resid + (long long)bs*Hn))[tid];
    float4 o = {r.x+acc.x*inv, r.y+acc.y*inv, r.z+acc.z*inv, r.w+acc.w*inv};
    ((float4*)(out + (long long)bs*Hn))[tid] = o;
}

// ---------------- host ----------------
extern "C" void kernel_launch(void* const* d_in, const int* in_sizes, int n_in,
                              void* d_out, int out_size)
{
    const float* query    = (const float*)d_in[0];
    const float* image    = (const float*)d_in[1];
    const float* textctx  = (const float*)d_in[2];
    const float* sa_w_in  = (const float*)d_in[3];
    const float* sa_b_in  = (const float*)d_in[4];
    const float* sa_w_out = (const float*)d_in[5];
    const float* sa_b_out = (const float*)d_in[6];
    const float* ca_w_in  = (const float*)d_in[7];
    const float* ca_b_in  = (const float*)d_in[8];
    const float* ca_w_out = (const float*)d_in[9];
    const float* ca_b_out = (const float*)d_in[10];
    const float* gate_img_w = (const float*)d_in[11];
    const float* gate_img_b = (const float*)d_in[12];
    const float* gate_txt_w = (const float*)d_in[13];
    const float* gate_txt_b = (const float*)d_in[14];
    const float* e_w1 = (const float*)d_in[15];
    const float* e_b1 = (const float*)d_in[16];
    const float* e_w2 = (const float*)d_in[17];
    const float* e_b2 = (const float*)d_in[18];
    const float* lnq_g = (const float*)d_in[19];
    const float* lnq_b = (const float*)d_in[20];
    const float* lnc_g = (const float*)d_in[21];
    const float* lnc_b = (const float*)d_in[22];
    const float* lnf_g = (const float*)d_in[23];
    const float* lnf_b = (const float*)d_in[24];

    __nv_bfloat16 *pWh,*pWl,*pImgH,*pImgL,*pLnH,*pLnL,*pQkvH,*pQkvL,*pAttnH,*pAttnL;
    __nv_bfloat16 *pQcH,*pQcL,*pKvH,*pKvL,*pPh,*pPl,*pHh,*pHl;
    float *pSc,*pQ1,*pQ2,*pPt,*pPi,*pCtxI,*pCtxT,*pCpI,*pCpT,*pDown;
    int *pSelT,*pSelI,*pPosT,*pPosI;
    cudaGetSymbolAddress((void**)&pWh,  g_w_hi);
    cudaGetSymbolAddress((void**)&pWl,  g_w_lo);
    cudaGetSymbolAddress((void**)&pImgH,g_img_hi);
    cudaGetSymbolAddress((void**)&pImgL,g_img_lo);
    cudaGetSymbolAddress((void**)&pLnH, g_ln_hi);
    cudaGetSymbolAddress((void**)&pLnL, g_ln_lo);
    cudaGetSymbolAddress((void**)&pQkvH,g_qkv_hi);
    cudaGetSymbolAddress((void**)&pQkvL,g_qkv_lo);
    cudaGetSymbolAddress((void**)&pAttnH,g_attn_hi);
    cudaGetSymbolAddress((void**)&pAttnL,g_attn_lo);
    cudaGetSymbolAddress((void**)&pQcH, g_qc_hi);
    cudaGetSymbolAddress((void**)&pQcL, g_qc_lo);
    cudaGetSymbolAddress((void**)&pKvH, g_kv_hi);
    cudaGetSymbolAddress((void**)&pKvL, g_kv_lo);
    cudaGetSymbolAddress((void**)&pPh,  g_p_hi);
    cudaGetSymbolAddress((void**)&pPl,  g_p_lo);
    cudaGetSymbolAddress((void**)&pHh,  g_h_hi);
    cudaGetSymbolAddress((void**)&pHl,  g_h_lo);
    cudaGetSymbolAddress((void**)&pSc,  g_scores);
    cudaGetSymbolAddress((void**)&pQ1,  g_q1);
    cudaGetSymbolAddress((void**)&pQ2,  g_q2);
    cudaGetSymbolAddress((void**)&pPt,  g_probs_txt);
    cudaGetSymbolAddress((void**)&pPi,  g_probs_img);
    cudaGetSymbolAddress((void**)&pCtxI,g_ctx_img);
    cudaGetSymbolAddress((void**)&pCtxT,g_ctx_txt);
    cudaGetSymbolAddress((void**)&pCpI, g_cp_img);
    cudaGetSymbolAddress((void**)&pCpT, g_cp_txt);
    cudaGetSymbolAddress((void**)&pDown,g_down);
    cudaGetSymbolAddress((void**)&pSelT,g_sel_txt);
    cudaGetSymbolAddress((void**)&pSelI,g_sel_img);
    cudaGetSymbolAddress((void**)&pPosT,g_pos_txt);
    cudaGetSymbolAddress((void**)&pPosI,g_pos_img);

    // smem sizes: WARPM=2 stage=40960 x2 = 81920; WARPM=4 NTB single-use = 51200x? (allocate 2 stages worth for safety of layout = 51200)
    const int SM2 = 81920;
    const int SM4 = 51200;
    cudaFuncSetAttribute(mma_gemm<2,true ,true ,false,false,false,false,true >, cudaFuncAttributeMaxDynamicSharedMemorySize, SM2);
    cudaFuncSetAttribute(mma_gemm<2,true ,false,false,false,false,true ,false>, cudaFuncAttributeMaxDynamicSharedMemorySize, SM2);
    cudaFuncSetAttribute(mma_gemm<4,false,false,false,false,false,false,true >, cudaFuncAttributeMaxDynamicSharedMemorySize, SM4);
    cudaFuncSetAttribute(mma_gemm<2,true ,true ,true ,false,false,true ,false>, cudaFuncAttributeMaxDynamicSharedMemorySize, SM2);
    cudaFuncSetAttribute(mma_gemm<2,true ,true ,false,true ,true ,false,true >, cudaFuncAttributeMaxDynamicSharedMemorySize, SM2);
    cudaFuncSetAttribute(mma_gemm<2,true ,true ,false,false,false,true ,false>, cudaFuncAttributeMaxDynamicSharedMemorySize, SM2);

    const int BT = Bn*Tn, BV = Bn*Vn;
    float* outQ = (float*)d_out;
    float* outI = outQ + (long long)BT*Hn;

    // 0) pre-split all weights + image tokens in ONE launch
    SplitArgs sa;
    sa.d[0] = { sa_w_in,  pWh+W_SAIN,  pWl+W_SAIN,  3145728/4 };
    sa.d[1] = { sa_w_out, pWh+W_SAOUT, pWl+W_SAOUT, 1048576/4 };
    sa.d[2] = { ca_w_in,  pWh+W_CAIN,  pWl+W_CAIN,  3145728/4 };
    sa.d[3] = { ca_w_out, pWh+W_CAOUT, pWl+W_CAOUT, 1048576/4 };
    sa.d[4] = { e_w1,     pWh+W_EW1,   pWl+W_EW1,   33554432/4 };
    sa.d[5] = { e_w2,     pWh+W_EW2,   pWl+W_EW2,   33554432/4 };
    sa.d[6] = { image,    pImgH,       pImgL,       (Bn*Vn*Hn)/4 };
    int totN4 = 3145728/4 + 1048576/4 + 3145728/4 + 1048576/4 + 33554432/4 + 33554432/4 + (Bn*Vn*Hn)/4;
    split_all<<<(totN4+255)/256,256>>>(sa);

    // 1) self-attention
    ln_split<<<BT,256>>>(query, lnq_g, lnq_b, pLnH, pLnL);
    mma_gemm<2,true,true,false,false,false,false,true><<<dim3(24,16,1),256,SM2>>>(
        pLnH,pLnL, pWh+W_SAIN,pWl+W_SAIN, sa_b_in, nullptr, nullptr, pQkvH,pQkvL,
        BT, 3*Hn, Hn, Hn, Hn, 3*Hn, 0,0,0,0,0,0,0, 1, 1.f, nullptr,0);
    mma_gemm<2,true,false,false,false,false,true,false><<<dim3(4,4,Bn*NHn),256,SM2>>>(
        pQkvH,pQkvL, pQkvH+Hn,pQkvL+Hn, nullptr,nullptr, pSc, nullptr,nullptr,
        Tn, Tn, HDn, 3*Hn, 3*Hn, Tn,
        (long long)Tn*3*Hn, HDn, (long long)Tn*3*Hn, HDn,
        (long long)NHn*Tn*Tn, (long long)Tn*Tn, 0, NHn, 0.125f, nullptr,0);
    softmax_split<<<Bn*NHn*Tn,128>>>(pSc, pPh, pPl, Tn);
    mma_gemm<4,false,false,false,false,false,false,true><<<dim3(1,2,Bn*NHn),256,SM4>>>(
        pPh,pPl, pQkvH+2*Hn,pQkvL+2*Hn, nullptr,nullptr, nullptr, pAttnH,pAttnL,
        Tn, HDn, Tn, Tn, 3*Hn, Hn,
        (long long)NHn*Tn*Tn, (long long)Tn*Tn, (long long)Tn*3*Hn, HDn,
        (long long)Tn*Hn, HDn, 0, NHn, 1.f, nullptr,0);
    mma_gemm<2,true,true,true,false,false,true,false><<<dim3(8,16,1),256,SM2>>>(
        pAttnH,pAttnL, pWh+W_SAOUT,pWl+W_SAOUT, sa_b_out, query, pQ1, nullptr,nullptr,
        BT, Hn, Hn, Hn, Hn, Hn, 0,0,0,0,0,0,0, 1, 1.f, nullptr,0);

    // 2) cross-attention
    ln_split<<<BT,256>>>(pQ1, lnc_g, lnc_b, pLnH, pLnL);
    mma_gemm<2,true,true,false,false,false,false,true><<<dim3(8,16,1),256,SM2>>>(
        pLnH,pLnL, pWh+W_CAIN,pWl+W_CAIN, ca_b_in, nullptr, nullptr, pQcH,pQcL,
        BT, Hn, Hn, Hn, Hn, Hn, 0,0,0,0,0,0,0, 1, 1.f, nullptr,0);
    mma_gemm<2,true,true,false,false,false,false,true><<<dim3(16,18,1),256,SM2>>>(
        pImgH,pImgL, pWh+W_CAIN+(long long)Hn*Hn,pWl+W_CAIN+(long long)Hn*Hn, ca_b_in+Hn, nullptr, nullptr, pKvH,pKvL,
        BV, 2*Hn, Hn, Hn, Hn, 2*Hn, 0,0,0,0,0,0,0, 1, 1.f, nullptr,0);
    mma_gemm<2,true,false,false,false,false,true,false><<<dim3(5,4,Bn*NHn),256,SM2>>>(
        pQcH,pQcL, pKvH,pKvL, nullptr,nullptr, pSc, nullptr,nullptr,
        Tn, Vn, HDn, Hn, 2*Hn, Vn,
        (long long)Tn*Hn, HDn, (long long)Vn*2*Hn, HDn,
        (long long)NHn*Tn*Vn, (long long)Tn*Vn, 0, NHn, 0.125f, nullptr,0);
    softmax_split<<<Bn*NHn*Tn,128>>>(pSc, pPh, pPl, Vn);
    mma_gemm<4,false,false,false,false,false,false,true><<<dim3(1,2,Bn*NHn),256,SM4>>>(
        pPh,pPl, pKvH+Hn,pKvL+Hn, nullptr,nullptr, nullptr, pAttnH,pAttnL,
        Tn, HDn, Vn, Vn, 2*Hn, Hn,
        (long long)NHn*Tn*Vn, (long long)Tn*Vn, (long long)Vn*2*Hn, HDn,
        (long long)Tn*Hn, HDn, 0, NHn, 1.f, nullptr,0);
    mma_gemm<2,true,true,true,false,false,true,false><<<dim3(8,16,1),256,SM2>>>(
        pAttnH,pAttnL, pWh+W_CAOUT,pWl+W_CAOUT, ca_b_out, pQ1, pQ2, nullptr,nullptr,
        BT, Hn, Hn, Hn, Hn, Hn, 0,0,0,0,0,0,0, 1, 1.f, nullptr,0);

    // 3) gating
    mean_rows<<<Bn,256>>>(image, pCtxI, Vn);
    mean_rows<<<Bn,256>>>(textctx, pCtxT, Ln);
    ctxpart_kernel<<<Bn*En,256>>>(pCtxT, gate_img_w, gate_img_b, pCpI);
    ctxpart_kernel<<<Bn*En,256>>>(pCtxI, gate_txt_w, gate_txt_b, pCpT);
    gate_kernel<<<BV,256>>>(image, gate_img_w, pCpI, pPi, Vn);
    gate_kernel<<<BT,256>>>(pQ2, gate_txt_w, pCpT, pPt, Tn);
    topk_kernel<<<Bn*En,256>>>(pPt, Tn, KTXT, pSelT, pPosT);
    topk_kernel<<<Bn*En,256>>>(pPi, Vn, KIMG, pSelI, pPosI);

    // 4) text MoE: per-expert batched M = Bn*KTXT = 320
    ln_split<<<BT,256>>>(pQ2, lnf_g, lnf_b, pLnH, pLnL);
    mma_gemm<2,true,true,false,true,true,false,true><<<dim3(32,3,En),256,SM2>>>(
        pLnH,pLnL, pWh+W_EW1,pWl+W_EW1, e_b1, nullptr, nullptr, pHh,pHl,
        BKT, In, Hn, Hn, Hn, In,
        0, 0, 0, (long long)In*Hn,
        0, (long long)BKT*In, (long long)In, En, 1.f, pSelT, BKT);
    mma_gemm<2,true,true,false,false,false,true,false><<<dim3(8,3,En),256,SM2>>>(
        pHh,pHl, pWh+W_EW2,pWl+W_EW2, e_b2, nullptr, pDown, nullptr,nullptr,
        BKT, Hn, In, In, In, Hn,
        0, (long long)BKT*In, 0, (long long)Hn*In,
        0, (long long)BKT*Hn, (long long)Hn, En, 1.f, nullptr,0);
    combine_kernel<<<BT,256>>>(pDown, pPosT, pQ2, outQ, Tn, BKT);

    // 5) image MoE: per-expert batched M = Bn*KIMG = 360
    mma_gemm<2,true,true,false,true,true,false,true><<<dim3(32,3,En),256,SM2>>>(
        pImgH,pImgL, pWh+W_EW1,pWl+W_EW1, e_b1, nullptr, nullptr, pHh,pHl,
        BKI, In, Hn, Hn, Hn, In,
        0, 0, 0, (long long)In*Hn,
        0, (long long)BKI*In, (long long)In, En, 1.f, pSelI, BKI);
    mma_gemm<2,true,true,false,false,false,true,false><<<dim3(8,3,En),256,SM2>>>(
        pHh,pHl, pWh+W_EW2,pWl+W_EW2, e_b2, nullptr, pDown, nullptr,nullptr,
        BKI, Hn, In, In, In, Hn,
        0, (long long)BKI*In, 0, (long long)Hn*In,
        0, (long long)BKI*Hn, (long long)Hn, En, 1.f, nullptr,0);
    combine_kernel<<<BV,256>>>(pDown, pPosI, image, outI, Vn, BKI);
}